// round 3
// baseline (speedup 1.0000x reference)
#include <cuda_runtime.h>
#include <math.h>

#define NB 4
#define NC 256
#define NPIX 16384
#define NHEADS 8
#define CH 32
#define KSPLIT 8

// ------------------------- scratch (__device__ globals, no allocs) ----------
__device__ float  g_S[NB * NC];                          // per-channel pixel sums
__device__ float  g_part[KSPLIT * NB * 2 * NC * NC];     // gram partials (16.8 MB)
__device__ float  g_C0[NB * NC * NC];                    // X X^T
__device__ float  g_Cf[NB * NC * NC];                    // X Xflip^T
__device__ float  g_P[3 * NB * NC * NC];                 // Cf@W2^T, C0@W1^T, C0@W2^T
__device__ float2 g_At[NB * NHEADS * CH * CH];           // ifft_c(attn), complex
__device__ float  g_vs[(size_t)NB * NC * NPIX];          // conv3 output (64 MB)
__device__ float2 g_Vt[(size_t)NB * NPIX * NC];          // transformed V, [b][t][d] (134 MB)
__device__ float  g_y [(size_t)NB * NC * NPIX];          // |Atil @ Vt| (64 MB)
__device__ float2 g_Dtab[128 * 256];                     // Dirichlet Toeplitz rows

// ------------------------- per-channel sums --------------------------------
__global__ __launch_bounds__(256) void k_sum(const float* __restrict__ x) {
    int bc = blockIdx.x;                      // 0 .. NB*NC-1
    const float* p = x + (size_t)bc * NPIX;
    float s = 0.f;
    for (int i = threadIdx.x; i < NPIX; i += 256) s += p[i];
    __shared__ float sm[256];
    sm[threadIdx.x] = s; __syncthreads();
    for (int w = 128; w > 0; w >>= 1) {
        if (threadIdx.x < w) sm[threadIdx.x] += sm[threadIdx.x + w];
        __syncthreads();
    }
    if (threadIdx.x == 0) g_S[bc] = sm[0];
}

// ------------------------- Gram matrices: C0 = X X^T, Cf = X Xflip^T -------
__global__ __launch_bounds__(256) void k_gram(const float* __restrict__ x) {
    int tile = blockIdx.x, b = blockIdx.y, ks = blockIdx.z;
    int i0 = (tile >> 2) * 64, j0 = (tile & 3) * 64;
    const float* X = x + (size_t)b * NC * NPIX;
    __shared__ float As[64][33], Bs[64][33], Bf[64][33];
    float a0[4][4] = {}, af[4][4] = {};
    int ty = threadIdx.x >> 4, tx = threadIdx.x & 15;
    int k0 = ks * (NPIX / KSPLIT);
    for (int kb = k0; kb < k0 + NPIX / KSPLIT; kb += 32) {
        for (int idx = threadIdx.x; idx < 64 * 32; idx += 256) {
            int r = idx >> 5, c = idx & 31;
            int k = kb + c;
            As[r][c] = X[(size_t)(i0 + r) * NPIX + k];
            Bs[r][c] = X[(size_t)(j0 + r) * NPIX + k];
            int yy = k >> 7, xx = k & 127;
            int fk = (((128 - yy) & 127) << 7) | ((128 - xx) & 127);
            Bf[r][c] = X[(size_t)(j0 + r) * NPIX + fk];
        }
        __syncthreads();
#pragma unroll
        for (int kk = 0; kk < 32; ++kk) {
            float a[4], b0[4], b1v[4];
#pragma unroll
            for (int ii = 0; ii < 4; ++ii) a[ii] = As[ty + 16 * ii][kk];
#pragma unroll
            for (int jj = 0; jj < 4; ++jj) { b0[jj] = Bs[tx + 16 * jj][kk]; b1v[jj] = Bf[tx + 16 * jj][kk]; }
#pragma unroll
            for (int ii = 0; ii < 4; ++ii)
#pragma unroll
                for (int jj = 0; jj < 4; ++jj) {
                    a0[ii][jj] += a[ii] * b0[jj];
                    af[ii][jj] += a[ii] * b1v[jj];
                }
        }
        __syncthreads();
    }
    float* P0 = g_part + ((size_t)(ks * NB + b) * 2 + 0) * (NC * NC);
    float* P1 = g_part + ((size_t)(ks * NB + b) * 2 + 1) * (NC * NC);
    for (int ii = 0; ii < 4; ++ii)
        for (int jj = 0; jj < 4; ++jj) {
            int r = i0 + ty + 16 * ii, c = j0 + tx + 16 * jj;
            P0[r * NC + c] = a0[ii][jj];
            P1[r * NC + c] = af[ii][jj];
        }
}

__global__ __launch_bounds__(256) void k_gred() {
    int gid = blockIdx.x * 256 + threadIdx.x;          // over NB*2*NC*NC
    if (gid >= NB * 2 * NC * NC) return;
    int e = gid % (NC * NC);
    int bm = gid / (NC * NC);
    int m = bm & 1, b = bm >> 1;
    float s = 0.f;
    for (int ks = 0; ks < KSPLIT; ++ks)
        s += g_part[((size_t)(ks * NB + b) * 2 + m) * (NC * NC) + e];
    (m == 0 ? g_C0 : g_Cf)[b * (NC * NC) + e] = s;
}

// ------------------------- P matrices: A @ W^T -----------------------------
// z=0: Cf@w2^T,  z=1: C0@w1^T,  z=2: C0@w2^T
__global__ __launch_bounds__(256) void k_mm256(const float* __restrict__ w1,
                                               const float* __restrict__ w2) {
    int tile = blockIdx.x, b = blockIdx.y, z = blockIdx.z;
    const float* A = (z == 0 ? g_Cf : g_C0) + (size_t)b * NC * NC;
    const float* W = (z == 1 ? w1 : w2);
    float* P = g_P + ((size_t)z * NB + b) * NC * NC;
    int i0 = (tile >> 2) * 64, j0 = (tile & 3) * 64;
    __shared__ float As[64][33], Bs[64][33];
    float acc[4][4] = {};
    int ty = threadIdx.x >> 4, tx = threadIdx.x & 15;
    for (int kb = 0; kb < NC; kb += 32) {
        for (int idx = threadIdx.x; idx < 64 * 32; idx += 256) {
            int r = idx >> 5, c = idx & 31;
            As[r][c] = A[(i0 + r) * NC + kb + c];
            Bs[r][c] = W[(j0 + r) * NC + kb + c];
        }
        __syncthreads();
#pragma unroll
        for (int kk = 0; kk < 32; ++kk) {
            float a[4], bv[4];
#pragma unroll
            for (int ii = 0; ii < 4; ++ii) a[ii] = As[ty + 16 * ii][kk];
#pragma unroll
            for (int jj = 0; jj < 4; ++jj) bv[jj] = Bs[tx + 16 * jj][kk];
#pragma unroll
            for (int ii = 0; ii < 4; ++ii)
#pragma unroll
                for (int jj = 0; jj < 4; ++jj) acc[ii][jj] += a[ii] * bv[jj];
        }
        __syncthreads();
    }
    for (int ii = 0; ii < 4; ++ii)
        for (int jj = 0; jj < 4; ++jj)
            P[(i0 + ty + 16 * ii) * NC + j0 + tx + 16 * jj] = acc[ii][jj];
}

// ------------------------- attn -> softmax -> ifft_c -----------------------
__global__ __launch_bounds__(256) void k_attn(const float* __restrict__ w1,
                                              const float* __restrict__ w2,
                                              const float* __restrict__ b1,
                                              const float* __restrict__ b2,
                                              const float* __restrict__ temp) {
    int b = blockIdx.x >> 3, h = blockIdx.x & 7;
    int tid = threadIdx.x;
    __shared__ float Ps[NC][33];
    __shared__ float numS[CH][33];
    __shared__ float redA[CH][8], redB[CH][8];
    __shared__ float qn[CH], kn[CH], w1s[CH], w2s[CH];
    const float* P1 = g_P + ((size_t)0 * NB + b) * NC * NC;
    const float* P2 = g_P + ((size_t)1 * NB + b) * NC * NC;
    const float* P3 = g_P + ((size_t)2 * NB + b) * NC * NC;
    const float* Sb = g_S + b * NC;

    // ---- num[c][d] = sum_j W1[ch+c,j] * (Cf W2^T)[j, dh+d]
    for (int idx = tid; idx < NC * CH; idx += 256)
        Ps[idx >> 5][idx & 31] = P1[(size_t)(idx >> 5) * NC + h * CH + (idx & 31)];
    __syncthreads();
    {
        int c = tid >> 3, dg = tid & 7;
        float acc[4] = {0.f, 0.f, 0.f, 0.f};
        const float* wrow = w1 + (size_t)(h * CH + c) * NC;
        for (int j = 0; j < NC; ++j) {
            float w = wrow[j];
#pragma unroll
            for (int q = 0; q < 4; ++q) acc[q] += w * Ps[j][dg + 8 * q];
        }
#pragma unroll
        for (int q = 0; q < 4; ++q) numS[c][dg + 8 * q] = acc[q];
    }
    __syncthreads();

    // ---- qn (norms of q rows) and w1s = W1_c . S
    for (int idx = tid; idx < NC * CH; idx += 256)
        Ps[idx >> 5][idx & 31] = P2[(size_t)(idx >> 5) * NC + h * CH + (idx & 31)];
    __syncthreads();
    {
        int c = tid >> 3, g = tid & 7;
        const float* wrow = w1 + (size_t)(h * CH + c) * NC;
        float pa = 0.f, pb = 0.f;
        for (int j = g * 32; j < g * 32 + 32; ++j) {
            float w = wrow[j];
            pa += w * Ps[j][c];
            pb += w * Sb[j];
        }
        redA[c][g] = pa; redB[c][g] = pb;
    }
    __syncthreads();
    if (tid < CH) {
        float a = 0.f, bb = 0.f;
        for (int g = 0; g < 8; ++g) { a += redA[tid][g]; bb += redB[tid][g]; }
        float b1c = b1[h * CH + tid];
        w1s[tid] = bb;
        qn[tid] = fmaxf(sqrtf(fmaxf(a + 2.f * b1c * bb + 16384.f * b1c * b1c, 0.f)), 1e-12f);
    }
    __syncthreads();

    // ---- kn and w2s
    for (int idx = tid; idx < NC * CH; idx += 256)
        Ps[idx >> 5][idx & 31] = P3[(size_t)(idx >> 5) * NC + h * CH + (idx & 31)];
    __syncthreads();
    {
        int c = tid >> 3, g = tid & 7;
        const float* wrow = w2 + (size_t)(h * CH + c) * NC;
        float pa = 0.f, pb = 0.f;
        for (int j = g * 32; j < g * 32 + 32; ++j) {
            float w = wrow[j];
            pa += w * Ps[j][c];
            pb += w * Sb[j];
        }
        redA[c][g] = pa; redB[c][g] = pb;
    }
    __syncthreads();
    if (tid < CH) {
        float a = 0.f, bb = 0.f;
        for (int g = 0; g < 8; ++g) { a += redA[tid][g]; bb += redB[tid][g]; }
        float b2d = b2[h * CH + tid];
        w2s[tid] = bb;
        kn[tid] = fmaxf(sqrtf(fmaxf(a + 2.f * b2d * bb + 16384.f * b2d * b2d, 0.f)), 1e-12f);
    }
    __syncthreads();

    // ---- attn.real with bias corrections + temperature
    {
        float tH = temp[h];
        for (int idx = tid; idx < CH * CH; idx += 256) {
            int c = idx >> 5, d = idx & 31;
            float b1c = b1[h * CH + c], b2d = b2[h * CH + d];
            float numF = numS[c][d] + b1c * w2s[d] + b2d * w1s[c] + 16384.f * b1c * b2d;
            numS[c][d] = tH * numF / (qn[c] * kn[d]);
        }
    }
    __syncthreads();

    // ---- row softmax
    if (tid < CH) {
        float mx = -1e30f;
        for (int d = 0; d < CH; ++d) mx = fmaxf(mx, numS[tid][d]);
        float s = 0.f;
        for (int d = 0; d < CH; ++d) { float e = expf(numS[tid][d] - mx); numS[tid][d] = e; s += e; }
        float inv = 1.f / s;
        for (int d = 0; d < CH; ++d) numS[tid][d] *= inv;
    }
    __syncthreads();

    // ---- Atil[c'][d] = (1/32) sum_c aR[c][d] e^{+2pi i c c'/32}  (+ i/32 at c'=0)
    for (int idx = tid; idx < CH * CH; idx += 256) {
        int cp = idx >> 5, d = idx & 31;
        float re = 0.f, im = 0.f;
        for (int c = 0; c < CH; ++c) {
            int ph = (c * cp) & 31;
            float sv, cv;
            sincosf(0.19634954084936207f * (float)ph, &sv, &cv);  // 2*pi/32 * ph
            float a = numS[c][d];
            re += a * cv; im += a * sv;
        }
        re *= 0.03125f; im *= 0.03125f;
        if (cp == 0) im += 0.03125f;
        g_At[((size_t)blockIdx.x * CH + cp) * CH + d] = make_float2(re, im);
    }
}

// ------------------------- 1x1 conv GEMM: O = W @ X + bias -----------------
// mode 0: X = Xin (input x), O = g_vs.   mode 1: X = g_y, O = Outp (d_out).
__global__ __launch_bounds__(256) void k_conv(const float* __restrict__ W,
                                              const float* __restrict__ bias,
                                              const float* __restrict__ Xin,
                                              float* __restrict__ Outp,
                                              int mode) {
    int t0 = blockIdx.x * 64, o0 = blockIdx.y * 64, b = blockIdx.z;
    const float* X = (mode == 0 ? Xin : g_y) + (size_t)b * NC * NPIX;
    float* O = (mode == 0 ? g_vs : Outp) + (size_t)b * NC * NPIX;
    __shared__ float Ws[64][33];
    __shared__ float Xs[32][65];
    float acc[4][4] = {};
    int ty = threadIdx.x >> 4, tx = threadIdx.x & 15;
    for (int kb = 0; kb < NC; kb += 32) {
        for (int idx = threadIdx.x; idx < 64 * 32; idx += 256) {
            int r = idx >> 5, c = idx & 31;
            Ws[r][c] = W[(o0 + r) * NC + kb + c];
        }
        for (int idx = threadIdx.x; idx < 32 * 64; idx += 256) {
            int r = idx >> 6, c = idx & 63;
            Xs[r][c] = X[(size_t)(kb + r) * NPIX + t0 + c];
        }
        __syncthreads();
#pragma unroll
        for (int kk = 0; kk < 32; ++kk) {
            float a[4], v[4];
#pragma unroll
            for (int ii = 0; ii < 4; ++ii) a[ii] = Ws[ty + 16 * ii][kk];
#pragma unroll
            for (int jj = 0; jj < 4; ++jj) v[jj] = Xs[kk][tx + 16 * jj];
#pragma unroll
            for (int ii = 0; ii < 4; ++ii)
#pragma unroll
                for (int jj = 0; jj < 4; ++jj) acc[ii][jj] += a[ii] * v[jj];
        }
        __syncthreads();
    }
    for (int ii = 0; ii < 4; ++ii) {
        int o = o0 + ty + 16 * ii;
        float bo = bias[o];
        for (int jj = 0; jj < 4; ++jj)
            O[(size_t)o * NPIX + t0 + tx + 16 * jj] = acc[ii][jj] + bo;
    }
}

// ------------------------- Dirichlet Toeplitz table ------------------------
// D_s(m) = (1/128) * e^{i pi a 127/128} * sin(pi a)/sin(pi a/128), a = m + s/128
__global__ __launch_bounds__(256) void k_dtab() {
    int i = blockIdx.x * 256 + threadIdx.x;
    if (i >= 128 * 255) return;
    int s = i / 255, mi = i % 255, m = mi - 127;
    float2 v;
    if (s == 0) {
        v = make_float2(m == 0 ? 1.f : 0.f, 0.f);
    } else {
        double f = (double)s / 128.0;
        double al = (double)m + f;
        double mag = sinpi(f) / (128.0 * sinpi(al / 128.0));
        if (m & 1) mag = -mag;
        double ph = al * (127.0 / 128.0);
        v = make_float2((float)(cospi(ph) * mag), (float)(sinpi(ph) * mag));
    }
    g_Dtab[s * 256 + mi] = v;
}

// ------------------------- Vt[b][128p+s][d] = sum_x vs[d][s][x] D_s(p-x) ---
__global__ __launch_bounds__(256) void k_fft() {
    int s = blockIdx.x;
    int b = blockIdx.y >> 2, d0 = (blockIdx.y & 3) * 64;
    __shared__ float2 Ds[256];
    __shared__ float Vs[64][129];
    int tid = threadIdx.x;
    if (tid < 255) Ds[tid] = g_Dtab[s * 256 + tid];
    for (int idx = tid; idx < 64 * 128; idx += 256) {
        int r = idx >> 7, xx = idx & 127;
        Vs[r][xx] = g_vs[((size_t)(b * NC + d0 + r)) * NPIX + s * 128 + xx];
    }
    __syncthreads();
    int ty = tid >> 3, tx = tid & 7;   // ty: 32 p-groups, tx: 8 r-groups
    for (int rp = 0; rp < 2; ++rp) {
        int rbase = rp * 32 + tx * 4;
        float2 acc[4][4];
#pragma unroll
        for (int pp = 0; pp < 4; ++pp)
#pragma unroll
            for (int rr = 0; rr < 4; ++rr) acc[pp][rr] = make_float2(0.f, 0.f);
        for (int xx = 0; xx < 128; ++xx) {
            float2 dv[4]; float vv[4];
#pragma unroll
            for (int pp = 0; pp < 4; ++pp) dv[pp] = Ds[ty + 32 * pp - xx + 127];
#pragma unroll
            for (int rr = 0; rr < 4; ++rr) vv[rr] = Vs[rbase + rr][xx];
#pragma unroll
            for (int pp = 0; pp < 4; ++pp)
#pragma unroll
                for (int rr = 0; rr < 4; ++rr) {
                    acc[pp][rr].x += dv[pp].x * vv[rr];
                    acc[pp][rr].y += dv[pp].y * vv[rr];
                }
        }
#pragma unroll
        for (int pp = 0; pp < 4; ++pp)
            for (int rr = 0; rr < 4; ++rr) {
                int p = ty + 32 * pp;
                g_Vt[((size_t)b * NPIX + (p << 7) + s) * NC + d0 + rbase + rr] = acc[pp][rr];
            }
    }
}

// ------------------------- y = | Atil @ Vt | -------------------------------
__global__ __launch_bounds__(256) void k_attnv() {
    int bh = blockIdx.y;               // 0..31
    int b = bh >> 3, h = bh & 7;
    int t0 = blockIdx.x * 1024;
    int tid = threadIdx.x;
    __shared__ float2 Amat[CH][33];
    __shared__ float2 Vsm[64][33];
    for (int idx = tid; idx < CH * CH; idx += 256)
        Amat[idx >> 5][idx & 31] = g_At[(size_t)bh * CH * CH + idx];
    int ty = tid >> 4, tx = tid & 15;  // ty: 16 c-groups(x2), tx: 16 t-groups(x4 strided)
    for (int ck = 0; ck < 16; ++ck) {
        int tc = t0 + ck * 64;
        __syncthreads();
        for (int idx = tid; idx < 64 * CH; idx += 256) {
            int tt = idx >> 5, d = idx & 31;
            Vsm[tt][d] = g_Vt[((size_t)b * NPIX + tc + tt) * NC + h * CH + d];
        }
        __syncthreads();
        float accr[2][4] = {}, acci[2][4] = {};
        for (int d = 0; d < CH; ++d) {
            float2 a0 = Amat[ty * 2][d], a1 = Amat[ty * 2 + 1][d];
            float2 v[4];
#pragma unroll
            for (int q = 0; q < 4; ++q) v[q] = Vsm[tx + 16 * q][d];
#pragma unroll
            for (int q = 0; q < 4; ++q) {
                accr[0][q] += a0.x * v[q].x - a0.y * v[q].y;
                acci[0][q] += a0.x * v[q].y + a0.y * v[q].x;
                accr[1][q] += a1.x * v[q].x - a1.y * v[q].y;
                acci[1][q] += a1.x * v[q].y + a1.y * v[q].x;
            }
        }
        for (int i = 0; i < 2; ++i) {
            int cg = h * CH + ty * 2 + i;
            for (int q = 0; q < 4; ++q) {
                float re = accr[i][q], im = acci[i][q];
                g_y[((size_t)b * NC + cg) * NPIX + tc + tx + 16 * q] = sqrtf(re * re + im * im);
            }
        }
    }
}

// ------------------------- launch ------------------------------------------
extern "C" void kernel_launch(void* const* d_in, const int* in_sizes, int n_in,
                              void* d_out, int out_size) {
    const float* x  = (const float*)d_in[0];
    const float* w1 = (const float*)d_in[1];
    const float* b1 = (const float*)d_in[2];
    const float* w2 = (const float*)d_in[3];
    const float* b2 = (const float*)d_in[4];
    const float* w3 = (const float*)d_in[5];
    const float* b3 = (const float*)d_in[6];
    const float* wo = (const float*)d_in[7];
    const float* bo = (const float*)d_in[8];
    const float* temp = (const float*)d_in[9];
    float* out = (float*)d_out;

    k_dtab<<<128, 256>>>();
    k_sum<<<NB * NC, 256>>>(x);
    k_gram<<<dim3(16, NB, KSPLIT), 256>>>(x);
    k_gred<<<(NB * 2 * NC * NC) / 256, 256>>>();
    k_mm256<<<dim3(16, NB, 3), 256>>>(w1, w2);
    k_attn<<<NB * NHEADS, 256>>>(w1, w2, b1, b2, temp);
    k_conv<<<dim3(NPIX / 64, NC / 64, NB), 256>>>(w3, b3, x, nullptr, 0);   // vs = w3@x+b3
    k_fft<<<dim3(128, 16), 256>>>();
    k_attnv<<<dim3(16, 32), 256>>>();
    k_conv<<<dim3(NPIX / 64, NC / 64, NB), 256>>>(wo, bo, nullptr, out, 1); // out = wo@y+bo
}

// round 7
// speedup vs baseline: 1.0032x; 1.0032x over previous
#include <cuda_runtime.h>
#include <math.h>

#define NB 4
#define NC 256
#define NPIX 16384
#define NHEADS 8
#define CH 32
#define KSPLIT 8

// ------------------------- scratch (__device__ globals, no allocs) ----------
__device__ float  g_S[NB * NC];                          // per-channel pixel sums
__device__ float  g_part[KSPLIT * NB * 2 * NC * NC];     // gram partials (16.8 MB)
__device__ float  g_C0[NB * NC * NC];                    // X X^T
__device__ float  g_Cf[NB * NC * NC];                    // X Xflip^T
__device__ float  g_P[3 * NB * NC * NC];                 // Cf@W2^T, C0@W1^T, C0@W2^T
__device__ float2 g_At[NB * NHEADS * CH * CH];           // ifft_c(attn), complex
__device__ float  g_vs[(size_t)NB * NC * NPIX];          // conv3 output (64 MB)
__device__ float2 g_Vt[(size_t)NB * NPIX * NC];          // transformed V, [b][t][d] (134 MB)
__device__ float  g_y [(size_t)NB * NC * NPIX];          // |Atil @ Vt| (64 MB)
__device__ float2 g_Dtab[128 * 256];                     // Dirichlet Toeplitz rows

// ------------------------- per-channel sums --------------------------------
__global__ __launch_bounds__(256) void k_sum(const float* __restrict__ x) {
    int bc = blockIdx.x;                      // 0 .. NB*NC-1
    const float* p = x + (size_t)bc * NPIX;
    float s = 0.f;
    for (int i = threadIdx.x; i < NPIX; i += 256) s += p[i];
    __shared__ float sm[256];
    sm[threadIdx.x] = s; __syncthreads();
    for (int w = 128; w > 0; w >>= 1) {
        if (threadIdx.x < w) sm[threadIdx.x] += sm[threadIdx.x + w];
        __syncthreads();
    }
    if (threadIdx.x == 0) g_S[bc] = sm[0];
}

// ------------------------- Gram matrices: C0 = X X^T, Cf = X Xflip^T -------
__global__ __launch_bounds__(256) void k_gram(const float* __restrict__ x) {
    int tile = blockIdx.x, b = blockIdx.y, ks = blockIdx.z;
    int i0 = (tile >> 2) * 64, j0 = (tile & 3) * 64;
    const float* X = x + (size_t)b * NC * NPIX;
    __shared__ float As[64][33], Bs[64][33], Bf[64][33];
    float a0[4][4] = {}, af[4][4] = {};
    int ty = threadIdx.x >> 4, tx = threadIdx.x & 15;
    int k0 = ks * (NPIX / KSPLIT);
    for (int kb = k0; kb < k0 + NPIX / KSPLIT; kb += 32) {
        for (int idx = threadIdx.x; idx < 64 * 32; idx += 256) {
            int r = idx >> 5, c = idx & 31;
            int k = kb + c;
            As[r][c] = X[(size_t)(i0 + r) * NPIX + k];
            Bs[r][c] = X[(size_t)(j0 + r) * NPIX + k];
            int yy = k >> 7, xx = k & 127;
            int fk = (((128 - yy) & 127) << 7) | ((128 - xx) & 127);
            Bf[r][c] = X[(size_t)(j0 + r) * NPIX + fk];
        }
        __syncthreads();
#pragma unroll
        for (int kk = 0; kk < 32; ++kk) {
            float a[4], b0[4], b1v[4];
#pragma unroll
            for (int ii = 0; ii < 4; ++ii) a[ii] = As[ty + 16 * ii][kk];
#pragma unroll
            for (int jj = 0; jj < 4; ++jj) { b0[jj] = Bs[tx + 16 * jj][kk]; b1v[jj] = Bf[tx + 16 * jj][kk]; }
#pragma unroll
            for (int ii = 0; ii < 4; ++ii)
#pragma unroll
                for (int jj = 0; jj < 4; ++jj) {
                    a0[ii][jj] += a[ii] * b0[jj];
                    af[ii][jj] += a[ii] * b1v[jj];
                }
        }
        __syncthreads();
    }
    float* P0 = g_part + ((size_t)(ks * NB + b) * 2 + 0) * (NC * NC);
    float* P1 = g_part + ((size_t)(ks * NB + b) * 2 + 1) * (NC * NC);
    for (int ii = 0; ii < 4; ++ii)
        for (int jj = 0; jj < 4; ++jj) {
            int r = i0 + ty + 16 * ii, c = j0 + tx + 16 * jj;
            P0[r * NC + c] = a0[ii][jj];
            P1[r * NC + c] = af[ii][jj];
        }
}

__global__ __launch_bounds__(256) void k_gred() {
    int gid = blockIdx.x * 256 + threadIdx.x;          // over NB*2*NC*NC
    if (gid >= NB * 2 * NC * NC) return;
    int e = gid % (NC * NC);
    int bm = gid / (NC * NC);
    int m = bm & 1, b = bm >> 1;
    float s = 0.f;
    for (int ks = 0; ks < KSPLIT; ++ks)
        s += g_part[((size_t)(ks * NB + b) * 2 + m) * (NC * NC) + e];
    (m == 0 ? g_C0 : g_Cf)[b * (NC * NC) + e] = s;
}

// ------------------------- P matrices: A @ W^T -----------------------------
// z=0: Cf@w2^T,  z=1: C0@w1^T,  z=2: C0@w2^T
__global__ __launch_bounds__(256) void k_mm256(const float* __restrict__ w1,
                                               const float* __restrict__ w2) {
    int tile = blockIdx.x, b = blockIdx.y, z = blockIdx.z;
    const float* A = (z == 0 ? g_Cf : g_C0) + (size_t)b * NC * NC;
    const float* W = (z == 1 ? w1 : w2);
    float* P = g_P + ((size_t)z * NB + b) * NC * NC;
    int i0 = (tile >> 2) * 64, j0 = (tile & 3) * 64;
    __shared__ float As[64][33], Bs[64][33];
    float acc[4][4] = {};
    int ty = threadIdx.x >> 4, tx = threadIdx.x & 15;
    for (int kb = 0; kb < NC; kb += 32) {
        for (int idx = threadIdx.x; idx < 64 * 32; idx += 256) {
            int r = idx >> 5, c = idx & 31;
            As[r][c] = A[(i0 + r) * NC + kb + c];
            Bs[r][c] = W[(j0 + r) * NC + kb + c];
        }
        __syncthreads();
#pragma unroll
        for (int kk = 0; kk < 32; ++kk) {
            float a[4], bv[4];
#pragma unroll
            for (int ii = 0; ii < 4; ++ii) a[ii] = As[ty + 16 * ii][kk];
#pragma unroll
            for (int jj = 0; jj < 4; ++jj) bv[jj] = Bs[tx + 16 * jj][kk];
#pragma unroll
            for (int ii = 0; ii < 4; ++ii)
#pragma unroll
                for (int jj = 0; jj < 4; ++jj) acc[ii][jj] += a[ii] * bv[jj];
        }
        __syncthreads();
    }
    for (int ii = 0; ii < 4; ++ii)
        for (int jj = 0; jj < 4; ++jj)
            P[(i0 + ty + 16 * ii) * NC + j0 + tx + 16 * jj] = acc[ii][jj];
}

// ------------------------- attn -> softmax -> ifft_c -----------------------
__global__ __launch_bounds__(256) void k_attn(const float* __restrict__ w1,
                                              const float* __restrict__ w2,
                                              const float* __restrict__ b1,
                                              const float* __restrict__ b2,
                                              const float* __restrict__ temp) {
    int b = blockIdx.x >> 3, h = blockIdx.x & 7;
    int tid = threadIdx.x;
    __shared__ float Ps[NC][33];
    __shared__ float numS[CH][33];
    __shared__ float redA[CH][8], redB[CH][8];
    __shared__ float qn[CH], kn[CH], w1s[CH], w2s[CH];
    const float* P1 = g_P + ((size_t)0 * NB + b) * NC * NC;
    const float* P2 = g_P + ((size_t)1 * NB + b) * NC * NC;
    const float* P3 = g_P + ((size_t)2 * NB + b) * NC * NC;
    const float* Sb = g_S + b * NC;

    // ---- num[c][d] = sum_j W1[ch+c,j] * (Cf W2^T)[j, dh+d]
    for (int idx = tid; idx < NC * CH; idx += 256)
        Ps[idx >> 5][idx & 31] = P1[(size_t)(idx >> 5) * NC + h * CH + (idx & 31)];
    __syncthreads();
    {
        int c = tid >> 3, dg = tid & 7;
        float acc[4] = {0.f, 0.f, 0.f, 0.f};
        const float* wrow = w1 + (size_t)(h * CH + c) * NC;
        for (int j = 0; j < NC; ++j) {
            float w = wrow[j];
#pragma unroll
            for (int q = 0; q < 4; ++q) acc[q] += w * Ps[j][dg + 8 * q];
        }
#pragma unroll
        for (int q = 0; q < 4; ++q) numS[c][dg + 8 * q] = acc[q];
    }
    __syncthreads();

    // ---- qn (norms of q rows) and w1s = W1_c . S
    for (int idx = tid; idx < NC * CH; idx += 256)
        Ps[idx >> 5][idx & 31] = P2[(size_t)(idx >> 5) * NC + h * CH + (idx & 31)];
    __syncthreads();
    {
        int c = tid >> 3, g = tid & 7;
        const float* wrow = w1 + (size_t)(h * CH + c) * NC;
        float pa = 0.f, pb = 0.f;
        for (int j = g * 32; j < g * 32 + 32; ++j) {
            float w = wrow[j];
            pa += w * Ps[j][c];
            pb += w * Sb[j];
        }
        redA[c][g] = pa; redB[c][g] = pb;
    }
    __syncthreads();
    if (tid < CH) {
        float a = 0.f, bb = 0.f;
        for (int g = 0; g < 8; ++g) { a += redA[tid][g]; bb += redB[tid][g]; }
        float b1c = b1[h * CH + tid];
        w1s[tid] = bb;
        qn[tid] = fmaxf(sqrtf(fmaxf(a + 2.f * b1c * bb + 16384.f * b1c * b1c, 0.f)), 1e-12f);
    }
    __syncthreads();

    // ---- kn and w2s
    for (int idx = tid; idx < NC * CH; idx += 256)
        Ps[idx >> 5][idx & 31] = P3[(size_t)(idx >> 5) * NC + h * CH + (idx & 31)];
    __syncthreads();
    {
        int c = tid >> 3, g = tid & 7;
        const float* wrow = w2 + (size_t)(h * CH + c) * NC;
        float pa = 0.f, pb = 0.f;
        for (int j = g * 32; j < g * 32 + 32; ++j) {
            float w = wrow[j];
            pa += w * Ps[j][c];
            pb += w * Sb[j];
        }
        redA[c][g] = pa; redB[c][g] = pb;
    }
    __syncthreads();
    if (tid < CH) {
        float a = 0.f, bb = 0.f;
        for (int g = 0; g < 8; ++g) { a += redA[tid][g]; bb += redB[tid][g]; }
        float b2d = b2[h * CH + tid];
        w2s[tid] = bb;
        kn[tid] = fmaxf(sqrtf(fmaxf(a + 2.f * b2d * bb + 16384.f * b2d * b2d, 0.f)), 1e-12f);
    }
    __syncthreads();

    // ---- attn.real with bias corrections + temperature
    {
        float tH = temp[h];
        for (int idx = tid; idx < CH * CH; idx += 256) {
            int c = idx >> 5, d = idx & 31;
            float b1c = b1[h * CH + c], b2d = b2[h * CH + d];
            float numF = numS[c][d] + b1c * w2s[d] + b2d * w1s[c] + 16384.f * b1c * b2d;
            numS[c][d] = tH * numF / (qn[c] * kn[d]);
        }
    }
    __syncthreads();

    // ---- row softmax
    if (tid < CH) {
        float mx = -1e30f;
        for (int d = 0; d < CH; ++d) mx = fmaxf(mx, numS[tid][d]);
        float s = 0.f;
        for (int d = 0; d < CH; ++d) { float e = expf(numS[tid][d] - mx); numS[tid][d] = e; s += e; }
        float inv = 1.f / s;
        for (int d = 0; d < CH; ++d) numS[tid][d] *= inv;
    }
    __syncthreads();

    // ---- Atil[c'][d] = (1/32) sum_c aR[c][d] e^{+2pi i c c'/32}  (+ i/32 at c'=0)
    for (int idx = tid; idx < CH * CH; idx += 256) {
        int cp = idx >> 5, d = idx & 31;
        float re = 0.f, im = 0.f;
        for (int c = 0; c < CH; ++c) {
            int ph = (c * cp) & 31;
            float sv, cv;
            sincosf(0.19634954084936207f * (float)ph, &sv, &cv);  // 2*pi/32 * ph
            float a = numS[c][d];
            re += a * cv; im += a * sv;
        }
        re *= 0.03125f; im *= 0.03125f;
        if (cp == 0) im += 0.03125f;
        g_At[((size_t)blockIdx.x * CH + cp) * CH + d] = make_float2(re, im);
    }
}

// ------------------------- 1x1 conv GEMM: O = W @ X + bias -----------------
// mode 0: X = Xin (input x), O = g_vs.   mode 1: X = g_y, O = Outp (d_out).
__global__ __launch_bounds__(256) void k_conv(const float* __restrict__ W,
                                              const float* __restrict__ bias,
                                              const float* __restrict__ Xin,
                                              float* __restrict__ Outp,
                                              int mode) {
    int t0 = blockIdx.x * 64, o0 = blockIdx.y * 64, b = blockIdx.z;
    const float* X = (mode == 0 ? Xin : g_y) + (size_t)b * NC * NPIX;
    float* O = (mode == 0 ? g_vs : Outp) + (size_t)b * NC * NPIX;
    __shared__ float Ws[64][33];
    __shared__ float Xs[32][65];
    float acc[4][4] = {};
    int ty = threadIdx.x >> 4, tx = threadIdx.x & 15;
    for (int kb = 0; kb < NC; kb += 32) {
        for (int idx = threadIdx.x; idx < 64 * 32; idx += 256) {
            int r = idx >> 5, c = idx & 31;
            Ws[r][c] = W[(o0 + r) * NC + kb + c];
        }
        for (int idx = threadIdx.x; idx < 32 * 64; idx += 256) {
            int r = idx >> 6, c = idx & 63;
            Xs[r][c] = X[(size_t)(kb + r) * NPIX + t0 + c];
        }
        __syncthreads();
#pragma unroll
        for (int kk = 0; kk < 32; ++kk) {
            float a[4], v[4];
#pragma unroll
            for (int ii = 0; ii < 4; ++ii) a[ii] = Ws[ty + 16 * ii][kk];
#pragma unroll
            for (int jj = 0; jj < 4; ++jj) v[jj] = Xs[kk][tx + 16 * jj];
#pragma unroll
            for (int ii = 0; ii < 4; ++ii)
#pragma unroll
                for (int jj = 0; jj < 4; ++jj) acc[ii][jj] += a[ii] * v[jj];
        }
        __syncthreads();
    }
    for (int ii = 0; ii < 4; ++ii) {
        int o = o0 + ty + 16 * ii;
        float bo = bias[o];
        for (int jj = 0; jj < 4; ++jj)
            O[(size_t)o * NPIX + t0 + tx + 16 * jj] = acc[ii][jj] + bo;
    }
}

// ------------------------- Dirichlet Toeplitz table ------------------------
// D_s(m) = (1/128) * e^{i pi a 127/128} * sin(pi a)/sin(pi a/128), a = m + s/128
__global__ __launch_bounds__(256) void k_dtab() {
    int i = blockIdx.x * 256 + threadIdx.x;
    if (i >= 128 * 255) return;
    int s = i / 255, mi = i % 255, m = mi - 127;
    float2 v;
    if (s == 0) {
        v = make_float2(m == 0 ? 1.f : 0.f, 0.f);
    } else {
        double f = (double)s / 128.0;
        double al = (double)m + f;
        double mag = sinpi(f) / (128.0 * sinpi(al / 128.0));
        if (m & 1) mag = -mag;
        double ph = al * (127.0 / 128.0);
        v = make_float2((float)(cospi(ph) * mag), (float)(sinpi(ph) * mag));
    }
    g_Dtab[s * 256 + mi] = v;
}

// ------------------------- Vt[b][128p+s][d] = sum_x vs[d][s][x] D_s(p-x) ---
__global__ __launch_bounds__(256) void k_fft() {
    int s = blockIdx.x;
    int b = blockIdx.y >> 2, d0 = (blockIdx.y & 3) * 64;
    __shared__ float2 Ds[256];
    __shared__ float Vs[64][129];
    int tid = threadIdx.x;
    if (tid < 255) Ds[tid] = g_Dtab[s * 256 + tid];
    for (int idx = tid; idx < 64 * 128; idx += 256) {
        int r = idx >> 7, xx = idx & 127;
        Vs[r][xx] = g_vs[((size_t)(b * NC + d0 + r)) * NPIX + s * 128 + xx];
    }
    __syncthreads();
    int ty = tid >> 3, tx = tid & 7;   // ty: 32 p-groups, tx: 8 r-groups
    for (int rp = 0; rp < 2; ++rp) {
        int rbase = rp * 32 + tx * 4;
        float2 acc[4][4];
#pragma unroll
        for (int pp = 0; pp < 4; ++pp)
#pragma unroll
            for (int rr = 0; rr < 4; ++rr) acc[pp][rr] = make_float2(0.f, 0.f);
        for (int xx = 0; xx < 128; ++xx) {
            float2 dv[4]; float vv[4];
#pragma unroll
            for (int pp = 0; pp < 4; ++pp) dv[pp] = Ds[ty + 32 * pp - xx + 127];
#pragma unroll
            for (int rr = 0; rr < 4; ++rr) vv[rr] = Vs[rbase + rr][xx];
#pragma unroll
            for (int pp = 0; pp < 4; ++pp)
#pragma unroll
                for (int rr = 0; rr < 4; ++rr) {
                    acc[pp][rr].x += dv[pp].x * vv[rr];
                    acc[pp][rr].y += dv[pp].y * vv[rr];
                }
        }
#pragma unroll
        for (int pp = 0; pp < 4; ++pp)
            for (int rr = 0; rr < 4; ++rr) {
                int p = ty + 32 * pp;
                g_Vt[((size_t)b * NPIX + (p << 7) + s) * NC + d0 + rbase + rr] = acc[pp][rr];
            }
    }
}

// ------------------------- y = | Atil @ Vt | -------------------------------
__global__ __launch_bounds__(256) void k_attnv() {
    int bh = blockIdx.y;               // 0..31
    int b = bh >> 3, h = bh & 7;
    int t0 = blockIdx.x * 1024;
    int tid = threadIdx.x;
    __shared__ float2 Amat[CH][33];
    __shared__ float2 Vsm[64][33];
    for (int idx = tid; idx < CH * CH; idx += 256)
        Amat[idx >> 5][idx & 31] = g_At[(size_t)bh * CH * CH + idx];
    int ty = tid >> 4, tx = tid & 15;  // ty: 16 c-groups(x2), tx: 16 t-groups(x4 strided)
    for (int ck = 0; ck < 16; ++ck) {
        int tc = t0 + ck * 64;
        __syncthreads();
        for (int idx = tid; idx < 64 * CH; idx += 256) {
            int tt = idx >> 5, d = idx & 31;
            Vsm[tt][d] = g_Vt[((size_t)b * NPIX + tc + tt) * NC + h * CH + d];
        }
        __syncthreads();
        float accr[2][4] = {}, acci[2][4] = {};
        for (int d = 0; d < CH; ++d) {
            float2 a0 = Amat[ty * 2][d], a1 = Amat[ty * 2 + 1][d];
            float2 v[4];
#pragma unroll
            for (int q = 0; q < 4; ++q) v[q] = Vsm[tx + 16 * q][d];
#pragma unroll
            for (int q = 0; q < 4; ++q) {
                accr[0][q] += a0.x * v[q].x - a0.y * v[q].y;
                acci[0][q] += a0.x * v[q].y + a0.y * v[q].x;
                accr[1][q] += a1.x * v[q].x - a1.y * v[q].y;
                acci[1][q] += a1.x * v[q].y + a1.y * v[q].x;
            }
        }
        for (int i = 0; i < 2; ++i) {
            int cg = h * CH + ty * 2 + i;
            for (int q = 0; q < 4; ++q) {
                float re = accr[i][q], im = acci[i][q];
                g_y[((size_t)b * NC + cg) * NPIX + tc + tx + 16 * q] = sqrtf(re * re + im * im);
            }
        }
    }
}

// ------------------------- launch ------------------------------------------
extern "C" void kernel_launch(void* const* d_in, const int* in_sizes, int n_in,
                              void* d_out, int out_size) {
    const float* x  = (const float*)d_in[0];
    const float* w1 = (const float*)d_in[1];
    const float* b1 = (const float*)d_in[2];
    const float* w2 = (const float*)d_in[3];
    const float* b2 = (const float*)d_in[4];
    const float* w3 = (const float*)d_in[5];
    const float* b3 = (const float*)d_in[6];
    const float* wo = (const float*)d_in[7];
    const float* bo = (const float*)d_in[8];
    const float* temp = (const float*)d_in[9];
    float* out = (float*)d_out;

    k_dtab<<<128, 256>>>();
    k_sum<<<NB * NC, 256>>>(x);
    k_gram<<<dim3(16, NB, KSPLIT), 256>>>(x);
    k_gred<<<(NB * 2 * NC * NC) / 256, 256>>>();
    k_mm256<<<dim3(16, NB, 3), 256>>>(w1, w2);
    k_attn<<<NB * NHEADS, 256>>>(w1, w2, b1, b2, temp);
    k_conv<<<dim3(NPIX / 64, NC / 64, NB), 256>>>(w3, b3, x, nullptr, 0);   // vs = w3@x+b3
    k_fft<<<dim3(128, 16), 256>>>();
    k_attnv<<<dim3(16, 32), 256>>>();
    k_conv<<<dim3(NPIX / 64, NC / 64, NB), 256>>>(wo, bo, nullptr, out, 1); // out = wo@y+bo
}

// round 9
// speedup vs baseline: 1.1617x; 1.1580x over previous
#include <cuda_runtime.h>
#include <cuda_bf16.h>
#include <math.h>
#include <stdint.h>

#define NB 4
#define NC 256
#define NPIX 16384
#define NHEADS 8
#define CH 32
#define KSPLIT 8

// ------------------------- scratch ------------------------------------------
__device__ float  g_S[NB * NC];
__device__ float  g_part[KSPLIT * NB * 2 * NC * NC];
__device__ float  g_C0[NB * NC * NC];
__device__ float  g_Cf[NB * NC * NC];
__device__ float  g_P[3 * NB * NC * NC];
__device__ float2 g_At[NB * NHEADS * CH * CH];
__device__ float  g_vs[(size_t)NB * NC * NPIX];
__device__ float2 g_Vt[(size_t)NB * NPIX * NC];
__device__ float  g_y [(size_t)NB * NC * NPIX];
__device__ float2 g_Dtab[128 * 256];

// ------------------------- mma.sync helpers (sm_80+ baseline) ---------------
__device__ __forceinline__ uint32_t smem_u32(const void* p) {
    uint32_t a;
    asm("{ .reg .u64 t; cvta.to.shared.u64 t, %1; cvt.u32.u64 %0, t; }" : "=r"(a) : "l"(p));
    return a;
}
__device__ __forceinline__ void MMA(float* d, const uint32_t* a, const uint32_t* b) {
    asm volatile("mma.sync.aligned.m16n8k16.row.col.f32.bf16.bf16.f32 "
        "{%0,%1,%2,%3}, {%4,%5,%6,%7}, {%8,%9}, {%0,%1,%2,%3};"
        : "+f"(d[0]), "+f"(d[1]), "+f"(d[2]), "+f"(d[3])
        : "r"(a[0]), "r"(a[1]), "r"(a[2]), "r"(a[3]), "r"(b[0]), "r"(b[1]));
}
__device__ __forceinline__ void ldm_x4(uint32_t* r, uint32_t a) {
    asm volatile("ldmatrix.sync.aligned.m8n8.x4.shared.b16 {%0,%1,%2,%3}, [%4];"
        : "=r"(r[0]), "=r"(r[1]), "=r"(r[2]), "=r"(r[3]) : "r"(a));
}
__device__ __forceinline__ void ldm_x2(uint32_t* r, uint32_t a) {
    asm volatile("ldmatrix.sync.aligned.m8n8.x2.shared.b16 {%0,%1}, [%2];"
        : "=r"(r[0]), "=r"(r[1]) : "r"(a));
}
__device__ __forceinline__ void ldm_x2t(uint32_t* r, uint32_t a) {
    asm volatile("ldmatrix.sync.aligned.m8n8.x2.trans.shared.b16 {%0,%1}, [%2];"
        : "=r"(r[0]), "=r"(r[1]) : "r"(a));
}
__device__ __forceinline__ void split_pack(float4 v, uint2& hi, uint2& lo) {
    __nv_bfloat16 h0 = __float2bfloat16_rn(v.x), h1 = __float2bfloat16_rn(v.y);
    __nv_bfloat16 h2 = __float2bfloat16_rn(v.z), h3 = __float2bfloat16_rn(v.w);
    __nv_bfloat16 l0 = __float2bfloat16_rn(v.x - __bfloat162float(h0));
    __nv_bfloat16 l1 = __float2bfloat16_rn(v.y - __bfloat162float(h1));
    __nv_bfloat16 l2 = __float2bfloat16_rn(v.z - __bfloat162float(h2));
    __nv_bfloat16 l3 = __float2bfloat16_rn(v.w - __bfloat162float(h3));
    hi.x = (uint32_t)__bfloat16_as_ushort(h0) | ((uint32_t)__bfloat16_as_ushort(h1) << 16);
    hi.y = (uint32_t)__bfloat16_as_ushort(h2) | ((uint32_t)__bfloat16_as_ushort(h3) << 16);
    lo.x = (uint32_t)__bfloat16_as_ushort(l0) | ((uint32_t)__bfloat16_as_ushort(l1) << 16);
    lo.y = (uint32_t)__bfloat16_as_ushort(l2) | ((uint32_t)__bfloat16_as_ushort(l3) << 16);
}

// ------------------------- per-channel sums ---------------------------------
__global__ __launch_bounds__(256) void k_sum(const float* __restrict__ x) {
    int bc = blockIdx.x;
    const float* p = x + (size_t)bc * NPIX;
    float s = 0.f;
    for (int i = threadIdx.x; i < NPIX; i += 256) s += p[i];
    __shared__ float sm[256];
    sm[threadIdx.x] = s; __syncthreads();
    for (int w = 128; w > 0; w >>= 1) {
        if (threadIdx.x < w) sm[threadIdx.x] += sm[threadIdx.x + w];
        __syncthreads();
    }
    if (threadIdx.x == 0) g_S[bc] = sm[0];
}

// ------------------------- Gram via mma.sync ---------------------------------
// grid (4 = 2x2 tiles of 128, NB, KSPLIT*2). z = ks*2 + mode (0:C0, 1:Cf)
#define GSA 40
#define GTILE (128 * GSA)
#define GBUF (4 * GTILE)
#define GSMEM (2 * GBUF * 2)
__global__ __launch_bounds__(256, 1) void k_gram_mma(const float* __restrict__ x) {
    extern __shared__ __align__(16) __nv_bfloat16 smg[];
    int tid = threadIdx.x, wid = tid >> 5, lane = tid & 31;
    int i0 = (blockIdx.x >> 1) * 128, j0 = (blockIdx.x & 1) * 128;
    int b = blockIdx.y, ks = blockIdx.z >> 1, mode = blockIdx.z & 1;
    const float* Xb = x + (size_t)b * NC * NPIX;
    int wm = wid >> 2, wn = wid & 3;
    float acc[4][4][4] = {};
    float4 pA[4], pB[4];

    auto LD = [&](int ch) {
        int Kc = ks * 2048 + ch * 32;
#pragma unroll
        for (int q = 0; q < 4; ++q) {
            int f = tid + q * 256, r = f >> 3, c = (f & 7) * 4;
            pA[q] = *(const float4*)(Xb + (size_t)(i0 + r) * NPIX + Kc + c);
        }
        if (mode == 0) {
#pragma unroll
            for (int q = 0; q < 4; ++q) {
                int f = tid + q * 256, r = f >> 3, c = (f & 7) * 4;
                pB[q] = *(const float4*)(Xb + (size_t)(j0 + r) * NPIX + Kc + c);
            }
        } else {
            int fy = (128 - (Kc >> 7)) & 127, xc0 = Kc & 127;
#pragma unroll
            for (int q = 0; q < 4; ++q) {
                int f = tid + q * 256, r = f >> 3;
                int x0 = xc0 + (f & 7) * 4;
                const float* Fr = Xb + (size_t)(j0 + r) * NPIX + fy * 128;
                pB[q].x = Fr[(128 - x0) & 127];
                pB[q].y = Fr[127 - x0];
                pB[q].z = Fr[126 - x0];
                pB[q].w = Fr[125 - x0];
            }
        }
    };
    auto ST = [&](int buf) {
        __nv_bfloat16* Ah = smg + buf * GBUF;
        __nv_bfloat16* Al = Ah + GTILE;
        __nv_bfloat16* Bh = Ah + 2 * GTILE;
        __nv_bfloat16* Bl = Ah + 3 * GTILE;
#pragma unroll
        for (int q = 0; q < 4; ++q) {
            int f = tid + q * 256, r = f >> 3, c = (f & 7) * 4;
            uint2 hi, lo;
            split_pack(pA[q], hi, lo);
            *(uint2*)(Ah + r * GSA + c) = hi; *(uint2*)(Al + r * GSA + c) = lo;
            split_pack(pB[q], hi, lo);
            *(uint2*)(Bh + r * GSA + c) = hi; *(uint2*)(Bl + r * GSA + c) = lo;
        }
    };

    LD(0);
    for (int ch = 0; ch < 64; ++ch) {
        int buf = ch & 1;
        ST(buf);
        __syncthreads();
        if (ch < 63) LD(ch + 1);
        uint32_t sb = smem_u32(smg + buf * GBUF);
        uint32_t aH = sb, aL = sb + GTILE * 2, bH = sb + 4 * GTILE, bL = sb + 6 * GTILE;
#pragma unroll
        for (int k16 = 0; k16 < 32; k16 += 16) {
            uint32_t fah[4][4], fal[4][4], fbh[4][2], fbl[4][2];
            int arow = wm * 64 + (lane & 15), acol = k16 + ((lane >> 4) << 3);
#pragma unroll
            for (int ma = 0; ma < 4; ++ma) {
                uint32_t off = (uint32_t)((arow + ma * 16) * GSA + acol) * 2;
                ldm_x4(fah[ma], aH + off);
                ldm_x4(fal[ma], aL + off);
            }
            int brow = wn * 32 + (lane & 7), bcol = k16 + (lane & 8);
#pragma unroll
            for (int na = 0; na < 4; ++na) {
                uint32_t off = (uint32_t)((brow + na * 8) * GSA + bcol) * 2;
                ldm_x2(fbh[na], bH + off);
                ldm_x2(fbl[na], bL + off);
            }
#pragma unroll
            for (int ma = 0; ma < 4; ++ma)
#pragma unroll
                for (int na = 0; na < 4; ++na) {
                    MMA(acc[ma][na], fah[ma], fbh[na]);
                    MMA(acc[ma][na], fah[ma], fbl[na]);
                    MMA(acc[ma][na], fal[ma], fbh[na]);
                }
        }
        __syncthreads();
    }
    float* P = g_part + (((size_t)ks * NB + b) * 2 + mode) * (NC * NC);
#pragma unroll
    for (int ma = 0; ma < 4; ++ma)
#pragma unroll
        for (int na = 0; na < 4; ++na) {
            int r = i0 + wm * 64 + ma * 16 + (lane >> 2);
            int c = j0 + wn * 32 + na * 8 + (lane & 3) * 2;
            float2 v0 = make_float2(acc[ma][na][0], acc[ma][na][1]);
            float2 v1 = make_float2(acc[ma][na][2], acc[ma][na][3]);
            *(float2*)&P[(size_t)r * NC + c] = v0;
            *(float2*)&P[(size_t)(r + 8) * NC + c] = v1;
        }
}

__global__ __launch_bounds__(256) void k_gred() {
    int gid = blockIdx.x * 256 + threadIdx.x;
    if (gid >= NB * 2 * NC * NC) return;
    int e = gid % (NC * NC);
    int bm = gid / (NC * NC);
    int m = bm & 1, b = bm >> 1;
    float s = 0.f;
    for (int ks = 0; ks < KSPLIT; ++ks)
        s += g_part[(((size_t)ks * NB + b) * 2 + m) * (NC * NC) + e];
    (m == 0 ? g_C0 : g_Cf)[b * (NC * NC) + e] = s;
}

// ------------------------- 1x1 conv via mma.sync -----------------------------
// grid (128 t-tiles of 128, 2 o-tiles of 128, NB)
#define CSA 40
#define CATILE (128 * CSA)
#define CSB 136
#define CBTILE (32 * CSB)
#define CBUFE (2 * CATILE + 2 * CBTILE)
#define CSMEM (2 * CBUFE * 2)
__global__ __launch_bounds__(256, 1) void k_conv_mma(const float* __restrict__ W,
                                                     const float* __restrict__ bias,
                                                     const float* __restrict__ Xin,
                                                     float* __restrict__ Oout,
                                                     int mode) {
    extern __shared__ __align__(16) __nv_bfloat16 smc[];
    int tid = threadIdx.x, wid = tid >> 5, lane = tid & 31;
    int t0 = blockIdx.x * 128, o0 = blockIdx.y * 128, b = blockIdx.z;
    const float* X = (mode == 0 ? Xin : g_y) + (size_t)b * NC * NPIX;
    float* O = (mode == 0 ? g_vs : Oout) + (size_t)b * NC * NPIX;
    int wm = wid >> 2, wn = wid & 3;
    float acc[4][4][4] = {};
    float4 pA[4], pB[4];

    auto LD = [&](int ch) {
        int k0 = ch * 32;
#pragma unroll
        for (int q = 0; q < 4; ++q) {
            int f = tid + q * 256, r = f >> 3, c = (f & 7) * 4;
            pA[q] = *(const float4*)(W + (size_t)(o0 + r) * NC + k0 + c);
        }
#pragma unroll
        for (int q = 0; q < 4; ++q) {
            int f = tid + q * 256, k = f >> 5, t = (f & 31) * 4;
            pB[q] = *(const float4*)(X + (size_t)(k0 + k) * NPIX + t0 + t);
        }
    };
    auto ST = [&](int buf) {
        __nv_bfloat16* Ah = smc + buf * CBUFE;
        __nv_bfloat16* Al = Ah + CATILE;
        __nv_bfloat16* Bh = Ah + 2 * CATILE;
        __nv_bfloat16* Bl = Bh + CBTILE;
#pragma unroll
        for (int q = 0; q < 4; ++q) {
            int f = tid + q * 256, r = f >> 3, c = (f & 7) * 4;
            uint2 hi, lo;
            split_pack(pA[q], hi, lo);
            *(uint2*)(Ah + r * CSA + c) = hi; *(uint2*)(Al + r * CSA + c) = lo;
        }
#pragma unroll
        for (int q = 0; q < 4; ++q) {
            int f = tid + q * 256, k = f >> 5, t = (f & 31) * 4;
            uint2 hi, lo;
            split_pack(pB[q], hi, lo);
            *(uint2*)(Bh + k * CSB + t) = hi; *(uint2*)(Bl + k * CSB + t) = lo;
        }
    };

    LD(0);
    for (int ch = 0; ch < 8; ++ch) {
        int buf = ch & 1;
        ST(buf);
        __syncthreads();
        if (ch < 7) LD(ch + 1);
        uint32_t sb = smem_u32(smc + buf * CBUFE);
        uint32_t aH = sb, aL = sb + CATILE * 2, bH = sb + 4 * CATILE, bL = bH + CBTILE * 2;
#pragma unroll
        for (int k16 = 0; k16 < 32; k16 += 16) {
            uint32_t fah[4][4], fal[4][4], fbh[4][2], fbl[4][2];
            int arow = wm * 64 + (lane & 15), acol = k16 + ((lane >> 4) << 3);
#pragma unroll
            for (int ma = 0; ma < 4; ++ma) {
                uint32_t off = (uint32_t)((arow + ma * 16) * CSA + acol) * 2;
                ldm_x4(fah[ma], aH + off);
                ldm_x4(fal[ma], aL + off);
            }
            int krow = k16 + (lane & 15);
#pragma unroll
            for (int na = 0; na < 4; ++na) {
                uint32_t off = (uint32_t)(krow * CSB + wn * 32 + na * 8) * 2;
                ldm_x2t(fbh[na], bH + off);
                ldm_x2t(fbl[na], bL + off);
            }
#pragma unroll
            for (int ma = 0; ma < 4; ++ma)
#pragma unroll
                for (int na = 0; na < 4; ++na) {
                    MMA(acc[ma][na], fah[ma], fbh[na]);
                    MMA(acc[ma][na], fah[ma], fbl[na]);
                    MMA(acc[ma][na], fal[ma], fbh[na]);
                }
        }
        __syncthreads();
    }
#pragma unroll
    for (int ma = 0; ma < 4; ++ma) {
        int r = o0 + wm * 64 + ma * 16 + (lane >> 2);
        float b0v = bias[r], b1v = bias[r + 8];
#pragma unroll
        for (int na = 0; na < 4; ++na) {
            int c = t0 + wn * 32 + na * 8 + (lane & 3) * 2;
            float2 v0 = make_float2(acc[ma][na][0] + b0v, acc[ma][na][1] + b0v);
            float2 v1 = make_float2(acc[ma][na][2] + b1v, acc[ma][na][3] + b1v);
            *(float2*)&O[(size_t)r * NPIX + c] = v0;
            *(float2*)&O[(size_t)(r + 8) * NPIX + c] = v1;
        }
    }
}

// ------------------------- P matrices: A @ W^T (FFMA) ------------------------
__global__ __launch_bounds__(256) void k_mm256(const float* __restrict__ w1,
                                               const float* __restrict__ w2) {
    int tile = blockIdx.x, b = blockIdx.y, z = blockIdx.z;
    const float* A = (z == 0 ? g_Cf : g_C0) + (size_t)b * NC * NC;
    const float* W = (z == 1 ? w1 : w2);
    float* P = g_P + ((size_t)z * NB + b) * NC * NC;
    int i0 = (tile >> 2) * 64, j0 = (tile & 3) * 64;
    __shared__ float As[64][33], Bs[64][33];
    float acc[4][4] = {};
    int ty = threadIdx.x >> 4, tx = threadIdx.x & 15;
    for (int kb = 0; kb < NC; kb += 32) {
        for (int idx = threadIdx.x; idx < 64 * 32; idx += 256) {
            int r = idx >> 5, c = idx & 31;
            As[r][c] = A[(i0 + r) * NC + kb + c];
            Bs[r][c] = W[(j0 + r) * NC + kb + c];
        }
        __syncthreads();
#pragma unroll
        for (int kk = 0; kk < 32; ++kk) {
            float a[4], bv[4];
#pragma unroll
            for (int ii = 0; ii < 4; ++ii) a[ii] = As[ty + 16 * ii][kk];
#pragma unroll
            for (int jj = 0; jj < 4; ++jj) bv[jj] = Bs[tx + 16 * jj][kk];
#pragma unroll
            for (int ii = 0; ii < 4; ++ii)
#pragma unroll
                for (int jj = 0; jj < 4; ++jj) acc[ii][jj] += a[ii] * bv[jj];
        }
        __syncthreads();
    }
    for (int ii = 0; ii < 4; ++ii)
        for (int jj = 0; jj < 4; ++jj)
            P[(i0 + ty + 16 * ii) * NC + j0 + tx + 16 * jj] = acc[ii][jj];
}

// ------------------------- attn -> softmax -> ifft_c -------------------------
__global__ __launch_bounds__(256) void k_attn(const float* __restrict__ w1,
                                              const float* __restrict__ w2,
                                              const float* __restrict__ b1,
                                              const float* __restrict__ b2,
                                              const float* __restrict__ temp) {
    int b = blockIdx.x >> 3, h = blockIdx.x & 7;
    int tid = threadIdx.x;
    __shared__ float Ps[NC][33];
    __shared__ float numS[CH][33];
    __shared__ float redA[CH][8], redB[CH][8];
    __shared__ float qn[CH], kn[CH], w1s[CH], w2s[CH];
    const float* P1 = g_P + ((size_t)0 * NB + b) * NC * NC;
    const float* P2 = g_P + ((size_t)1 * NB + b) * NC * NC;
    const float* P3 = g_P + ((size_t)2 * NB + b) * NC * NC;
    const float* Sb = g_S + b * NC;

    for (int idx = tid; idx < NC * CH; idx += 256)
        Ps[idx >> 5][idx & 31] = P1[(size_t)(idx >> 5) * NC + h * CH + (idx & 31)];
    __syncthreads();
    {
        int c = tid >> 3, dg = tid & 7;
        float acc[4] = {0.f, 0.f, 0.f, 0.f};
        const float* wrow = w1 + (size_t)(h * CH + c) * NC;
        for (int j = 0; j < NC; ++j) {
            float w = wrow[j];
#pragma unroll
            for (int q = 0; q < 4; ++q) acc[q] += w * Ps[j][dg + 8 * q];
        }
#pragma unroll
        for (int q = 0; q < 4; ++q) numS[c][dg + 8 * q] = acc[q];
    }
    __syncthreads();

    for (int idx = tid; idx < NC * CH; idx += 256)
        Ps[idx >> 5][idx & 31] = P2[(size_t)(idx >> 5) * NC + h * CH + (idx & 31)];
    __syncthreads();
    {
        int c = tid >> 3, g = tid & 7;
        const float* wrow = w1 + (size_t)(h * CH + c) * NC;
        float pa = 0.f, pb = 0.f;
        for (int j = g * 32; j < g * 32 + 32; ++j) {
            float w = wrow[j];
            pa += w * Ps[j][c];
            pb += w * Sb[j];
        }
        redA[c][g] = pa; redB[c][g] = pb;
    }
    __syncthreads();
    if (tid < CH) {
        float a = 0.f, bb = 0.f;
        for (int g = 0; g < 8; ++g) { a += redA[tid][g]; bb += redB[tid][g]; }
        float b1c = b1[h * CH + tid];
        w1s[tid] = bb;
        qn[tid] = fmaxf(sqrtf(fmaxf(a + 2.f * b1c * bb + 16384.f * b1c * b1c, 0.f)), 1e-12f);
    }
    __syncthreads();

    for (int idx = tid; idx < NC * CH; idx += 256)
        Ps[idx >> 5][idx & 31] = P3[(size_t)(idx >> 5) * NC + h * CH + (idx & 31)];
    __syncthreads();
    {
        int c = tid >> 3, g = tid & 7;
        const float* wrow = w2 + (size_t)(h * CH + c) * NC;
        float pa = 0.f, pb = 0.f;
        for (int j = g * 32; j < g * 32 + 32; ++j) {
            float w = wrow[j];
            pa += w * Ps[j][c];
            pb += w * Sb[j];
        }
        redA[c][g] = pa; redB[c][g] = pb;
    }
    __syncthreads();
    if (tid < CH) {
        float a = 0.f, bb = 0.f;
        for (int g = 0; g < 8; ++g) { a += redA[tid][g]; bb += redB[tid][g]; }
        float b2d = b2[h * CH + tid];
        w2s[tid] = bb;
        kn[tid] = fmaxf(sqrtf(fmaxf(a + 2.f * b2d * bb + 16384.f * b2d * b2d, 0.f)), 1e-12f);
    }
    __syncthreads();

    {
        float tH = temp[h];
        for (int idx = tid; idx < CH * CH; idx += 256) {
            int c = idx >> 5, d = idx & 31;
            float b1c = b1[h * CH + c], b2d = b2[h * CH + d];
            float numF = numS[c][d] + b1c * w2s[d] + b2d * w1s[c] + 16384.f * b1c * b2d;
            numS[c][d] = tH * numF / (qn[c] * kn[d]);
        }
    }
    __syncthreads();

    if (tid < CH) {
        float mx = -1e30f;
        for (int d = 0; d < CH; ++d) mx = fmaxf(mx, numS[tid][d]);
        float s = 0.f;
        for (int d = 0; d < CH; ++d) { float e = expf(numS[tid][d] - mx); numS[tid][d] = e; s += e; }
        float inv = 1.f / s;
        for (int d = 0; d < CH; ++d) numS[tid][d] *= inv;
    }
    __syncthreads();

    for (int idx = tid; idx < CH * CH; idx += 256) {
        int cp = idx >> 5, d = idx & 31;
        float re = 0.f, im = 0.f;
        for (int c = 0; c < CH; ++c) {
            int ph = (c * cp) & 31;
            float sv, cv;
            sincosf(0.19634954084936207f * (float)ph, &sv, &cv);
            float a = numS[c][d];
            re += a * cv; im += a * sv;
        }
        re *= 0.03125f; im *= 0.03125f;
        if (cp == 0) im += 0.03125f;
        g_At[((size_t)blockIdx.x * CH + cp) * CH + d] = make_float2(re, im);
    }
}

// ------------------------- Dirichlet table -----------------------------------
__global__ __launch_bounds__(256) void k_dtab() {
    int i = blockIdx.x * 256 + threadIdx.x;
    if (i >= 128 * 255) return;
    int s = i / 255, mi = i % 255, m = mi - 127;
    float2 v;
    if (s == 0) {
        v = make_float2(m == 0 ? 1.f : 0.f, 0.f);
    } else {
        double f = (double)s / 128.0;
        double al = (double)m + f;
        double mag = sinpi(f) / (128.0 * sinpi(al / 128.0));
        if (m & 1) mag = -mag;
        double ph = al * (127.0 / 128.0);
        v = make_float2((float)(cospi(ph) * mag), (float)(sinpi(ph) * mag));
    }
    g_Dtab[s * 256 + mi] = v;
}

// ------------------------- Vt[b][128p+s][d] = sum_x vs[d][s][x] D_s(p-x) -----
__global__ __launch_bounds__(256) void k_fft() {
    int s = blockIdx.x;
    int b = blockIdx.y >> 2, d0 = (blockIdx.y & 3) * 64;
    __shared__ float2 Ds[256];
    __shared__ float Vs[64][129];
    int tid = threadIdx.x;
    if (tid < 255) Ds[tid] = g_Dtab[s * 256 + tid];
    for (int idx = tid; idx < 64 * 128; idx += 256) {
        int r = idx >> 7, xx = idx & 127;
        Vs[r][xx] = g_vs[((size_t)(b * NC + d0 + r)) * NPIX + s * 128 + xx];
    }
    __syncthreads();
    int ty = tid >> 3, tx = tid & 7;
    for (int rp = 0; rp < 2; ++rp) {
        int rbase = rp * 32 + tx * 4;
        float2 acc[4][4];
#pragma unroll
        for (int pp = 0; pp < 4; ++pp)
#pragma unroll
            for (int rr = 0; rr < 4; ++rr) acc[pp][rr] = make_float2(0.f, 0.f);
        for (int xx = 0; xx < 128; ++xx) {
            float2 dv[4]; float vv[4];
#pragma unroll
            for (int pp = 0; pp < 4; ++pp) dv[pp] = Ds[ty + 32 * pp - xx + 127];
#pragma unroll
            for (int rr = 0; rr < 4; ++rr) vv[rr] = Vs[rbase + rr][xx];
#pragma unroll
            for (int pp = 0; pp < 4; ++pp)
#pragma unroll
                for (int rr = 0; rr < 4; ++rr) {
                    acc[pp][rr].x += dv[pp].x * vv[rr];
                    acc[pp][rr].y += dv[pp].y * vv[rr];
                }
        }
#pragma unroll
        for (int pp = 0; pp < 4; ++pp)
            for (int rr = 0; rr < 4; ++rr) {
                int p = ty + 32 * pp;
                g_Vt[((size_t)b * NPIX + (p << 7) + s) * NC + d0 + rbase + rr] = acc[pp][rr];
            }
    }
}

// ------------------------- y = | Atil @ Vt | ---------------------------------
__global__ __launch_bounds__(256) void k_attnv() {
    int bh = blockIdx.y;
    int b = bh >> 3, h = bh & 7;
    int t0 = blockIdx.x * 1024;
    int tid = threadIdx.x;
    __shared__ float2 Amat[CH][33];
    __shared__ float2 Vsm[64][33];
    for (int idx = tid; idx < CH * CH; idx += 256)
        Amat[idx >> 5][idx & 31] = g_At[(size_t)bh * CH * CH + idx];
    int ty = tid >> 4, tx = tid & 15;
    for (int ck = 0; ck < 16; ++ck) {
        int tc = t0 + ck * 64;
        __syncthreads();
        for (int idx = tid; idx < 64 * CH; idx += 256) {
            int tt = idx >> 5, d = idx & 31;
            Vsm[tt][d] = g_Vt[((size_t)b * NPIX + tc + tt) * NC + h * CH + d];
        }
        __syncthreads();
        float accr[2][4] = {}, acci[2][4] = {};
        for (int d = 0; d < CH; ++d) {
            float2 a0 = Amat[ty * 2][d], a1 = Amat[ty * 2 + 1][d];
            float2 v[4];
#pragma unroll
            for (int q = 0; q < 4; ++q) v[q] = Vsm[tx + 16 * q][d];
#pragma unroll
            for (int q = 0; q < 4; ++q) {
                accr[0][q] += a0.x * v[q].x - a0.y * v[q].y;
                acci[0][q] += a0.x * v[q].y + a0.y * v[q].x;
                accr[1][q] += a1.x * v[q].x - a1.y * v[q].y;
                acci[1][q] += a1.x * v[q].y + a1.y * v[q].x;
            }
        }
        for (int i = 0; i < 2; ++i) {
            int cg = h * CH + ty * 2 + i;
            for (int q = 0; q < 4; ++q) {
                float re = accr[i][q], im = acci[i][q];
                g_y[((size_t)b * NC + cg) * NPIX + tc + tx + 16 * q] = sqrtf(re * re + im * im);
            }
        }
    }
}

// ------------------------- launch --------------------------------------------
extern "C" void kernel_launch(void* const* d_in, const int* in_sizes, int n_in,
                              void* d_out, int out_size) {
    const float* x  = (const float*)d_in[0];
    const float* w1 = (const float*)d_in[1];
    const float* b1 = (const float*)d_in[2];
    const float* w2 = (const float*)d_in[3];
    const float* b2 = (const float*)d_in[4];
    const float* w3 = (const float*)d_in[5];
    const float* b3 = (const float*)d_in[6];
    const float* wo = (const float*)d_in[7];
    const float* bo = (const float*)d_in[8];
    const float* temp = (const float*)d_in[9];
    float* out = (float*)d_out;

    cudaFuncSetAttribute(k_gram_mma, cudaFuncAttributeMaxDynamicSharedMemorySize, GSMEM);
    cudaFuncSetAttribute(k_conv_mma, cudaFuncAttributeMaxDynamicSharedMemorySize, CSMEM);

    k_dtab<<<128, 256>>>();
    k_sum<<<NB * NC, 256>>>(x);
    k_gram_mma<<<dim3(4, NB, KSPLIT * 2), 256, GSMEM>>>(x);
    k_gred<<<(NB * 2 * NC * NC) / 256, 256>>>();
    k_mm256<<<dim3(16, NB, 3), 256>>>(w1, w2);
    k_attn<<<NB * NHEADS, 256>>>(w1, w2, b1, b2, temp);
    k_conv_mma<<<dim3(128, 2, NB), 256, CSMEM>>>(w3, b3, x, nullptr, 0);
    k_fft<<<dim3(128, 16), 256>>>();
    k_attnv<<<dim3(16, 32), 256>>>();
    k_conv_mma<<<dim3(128, 2, NB), 256, CSMEM>>>(wo, bo, nullptr, out, 1);
}

// round 11
// speedup vs baseline: 1.8037x; 1.5526x over previous
#include <cuda_runtime.h>
#include <cuda_bf16.h>
#include <math.h>
#include <stdint.h>

#define NB 4
#define NC 256
#define NPIX 16384
#define NHEADS 8
#define CH 32
#define KSPLIT 8

// ------------------------- scratch ------------------------------------------
__device__ float  g_S[NB * NC];
__device__ float  g_part[KSPLIT * NB * 2 * NC * NC];
__device__ float  g_C0[NB * NC * NC];
__device__ float  g_Cf[NB * NC * NC];
__device__ float  g_P[3 * NB * NC * NC];
__device__ float2 g_At[NB * NHEADS * CH * CH];
__device__ float  g_vs[(size_t)NB * NC * NPIX];
__device__ float2 g_Vt[(size_t)NB * NPIX * NC];
__device__ float2 g_Dtab[128 * 256];
// prepacked bf16 hi/lo splits
__device__ unsigned short g_xh[(size_t)NB * NC * NPIX];
__device__ unsigned short g_xl[(size_t)NB * NC * NPIX];
__device__ unsigned short g_yh[(size_t)NB * NC * NPIX];
__device__ unsigned short g_yl[(size_t)NB * NC * NPIX];
__device__ unsigned short g_wh[2 * NC * NC];
__device__ unsigned short g_wl[2 * NC * NC];

// ------------------------- mma.sync helpers (sm_80+ baseline) ---------------
__device__ __forceinline__ uint32_t smem_u32(const void* p) {
    uint32_t a;
    asm("{ .reg .u64 t; cvta.to.shared.u64 t, %1; cvt.u32.u64 %0, t; }" : "=r"(a) : "l"(p));
    return a;
}
__device__ __forceinline__ void MMA(float* d, const uint32_t* a, const uint32_t* b) {
    asm volatile("mma.sync.aligned.m16n8k16.row.col.f32.bf16.bf16.f32 "
        "{%0,%1,%2,%3}, {%4,%5,%6,%7}, {%8,%9}, {%0,%1,%2,%3};"
        : "+f"(d[0]), "+f"(d[1]), "+f"(d[2]), "+f"(d[3])
        : "r"(a[0]), "r"(a[1]), "r"(a[2]), "r"(a[3]), "r"(b[0]), "r"(b[1]));
}
__device__ __forceinline__ void ldm_x4(uint32_t* r, uint32_t a) {
    asm volatile("ldmatrix.sync.aligned.m8n8.x4.shared.b16 {%0,%1,%2,%3}, [%4];"
        : "=r"(r[0]), "=r"(r[1]), "=r"(r[2]), "=r"(r[3]) : "r"(a));
}
__device__ __forceinline__ void ldm_x2(uint32_t* r, uint32_t a) {
    asm volatile("ldmatrix.sync.aligned.m8n8.x2.shared.b16 {%0,%1}, [%2];"
        : "=r"(r[0]), "=r"(r[1]) : "r"(a));
}
__device__ __forceinline__ void ldm_x2t(uint32_t* r, uint32_t a) {
    asm volatile("ldmatrix.sync.aligned.m8n8.x2.trans.shared.b16 {%0,%1}, [%2];"
        : "=r"(r[0]), "=r"(r[1]) : "r"(a));
}
__device__ __forceinline__ void split_pack(float4 v, uint2& hi, uint2& lo) {
    __nv_bfloat16 h0 = __float2bfloat16_rn(v.x), h1 = __float2bfloat16_rn(v.y);
    __nv_bfloat16 h2 = __float2bfloat16_rn(v.z), h3 = __float2bfloat16_rn(v.w);
    __nv_bfloat16 l0 = __float2bfloat16_rn(v.x - __bfloat162float(h0));
    __nv_bfloat16 l1 = __float2bfloat16_rn(v.y - __bfloat162float(h1));
    __nv_bfloat16 l2 = __float2bfloat16_rn(v.z - __bfloat162float(h2));
    __nv_bfloat16 l3 = __float2bfloat16_rn(v.w - __bfloat162float(h3));
    hi.x = (uint32_t)__bfloat16_as_ushort(h0) | ((uint32_t)__bfloat16_as_ushort(h1) << 16);
    hi.y = (uint32_t)__bfloat16_as_ushort(h2) | ((uint32_t)__bfloat16_as_ushort(h3) << 16);
    lo.x = (uint32_t)__bfloat16_as_ushort(l0) | ((uint32_t)__bfloat16_as_ushort(l1) << 16);
    lo.y = (uint32_t)__bfloat16_as_ushort(l2) | ((uint32_t)__bfloat16_as_ushort(l3) << 16);
}

// ------------------------- split precompute ----------------------------------
__global__ __launch_bounds__(256) void k_xsplit(const float* __restrict__ x) {
    size_t gid = (size_t)blockIdx.x * 256 + threadIdx.x;   // over float4s
    float4 v = ((const float4*)x)[gid];
    uint2 hi, lo;
    split_pack(v, hi, lo);
    ((uint2*)g_xh)[gid] = hi;
    ((uint2*)g_xl)[gid] = lo;
}
__global__ __launch_bounds__(256) void k_wsplit(const float* __restrict__ w3,
                                                const float* __restrict__ wo) {
    int gid = blockIdx.x * 256 + threadIdx.x;              // over 2*65536/4 float4s
    int per = NC * NC / 4;
    int m = gid / per, e = gid % per;
    const float* src = (m == 0 ? w3 : wo);
    float4 v = ((const float4*)src)[e];
    uint2 hi, lo;
    split_pack(v, hi, lo);
    ((uint2*)g_wh)[gid] = hi;
    ((uint2*)g_wl)[gid] = lo;
}

// ------------------------- per-channel sums ---------------------------------
__global__ __launch_bounds__(256) void k_sum(const float* __restrict__ x) {
    int bc = blockIdx.x;
    const float* p = x + (size_t)bc * NPIX;
    float s = 0.f;
    for (int i = threadIdx.x; i < NPIX; i += 256) s += p[i];
    __shared__ float sm[256];
    sm[threadIdx.x] = s; __syncthreads();
    for (int w = 128; w > 0; w >>= 1) {
        if (threadIdx.x < w) sm[threadIdx.x] += sm[threadIdx.x + w];
        __syncthreads();
    }
    if (threadIdx.x == 0) g_S[bc] = sm[0];
}

// ------------------------- Gram via mma.sync ---------------------------------
// grid (4 = 2x2 tiles of 128, NB, KSPLIT*2). z = ks*2 + mode (0:C0, 1:Cf)
#define GSA 40
#define GTILE (128 * GSA)
#define GBUF (4 * GTILE)
#define GSMEM (2 * GBUF * 2)
__global__ __launch_bounds__(256, 1) void k_gram_mma() {
    extern __shared__ __align__(16) __nv_bfloat16 smg[];
    int tid = threadIdx.x, wid = tid >> 5, lane = tid & 31;
    int i0 = (blockIdx.x >> 1) * 128, j0 = (blockIdx.x & 1) * 128;
    int b = blockIdx.y, ks = blockIdx.z >> 1, mode = blockIdx.z & 1;
    const unsigned short* Xh = g_xh + (size_t)b * NC * NPIX;
    const unsigned short* Xl = g_xl + (size_t)b * NC * NPIX;
    int wm = wid >> 2, wn = wid & 3;
    float acc[4][4][4] = {};
    uint2 pAh[4], pAl[4], pBh[4], pBl[4];

    auto LD = [&](int ch) {
        int Kc = ks * 2048 + ch * 32;
#pragma unroll
        for (int q = 0; q < 4; ++q) {
            int f = tid + q * 256, r = f >> 3, c = (f & 7) * 4;
            size_t off = (size_t)(i0 + r) * NPIX + Kc + c;
            pAh[q] = *(const uint2*)(Xh + off);
            pAl[q] = *(const uint2*)(Xl + off);
        }
        if (mode == 0) {
#pragma unroll
            for (int q = 0; q < 4; ++q) {
                int f = tid + q * 256, r = f >> 3, c = (f & 7) * 4;
                size_t off = (size_t)(j0 + r) * NPIX + Kc + c;
                pBh[q] = *(const uint2*)(Xh + off);
                pBl[q] = *(const uint2*)(Xl + off);
            }
        } else {
            int fy = (128 - (Kc >> 7)) & 127, xc0 = Kc & 127;
#pragma unroll
            for (int q = 0; q < 4; ++q) {
                int f = tid + q * 256, r = f >> 3;
                int x0 = xc0 + (f & 7) * 4;
                size_t ro = (size_t)(j0 + r) * NPIX + fy * 128;
                int c0 = (128 - x0) & 127, c1 = 127 - x0, c2 = 126 - x0, c3 = 125 - x0;
                pBh[q].x = (uint32_t)Xh[ro + c0] | ((uint32_t)Xh[ro + c1] << 16);
                pBh[q].y = (uint32_t)Xh[ro + c2] | ((uint32_t)Xh[ro + c3] << 16);
                pBl[q].x = (uint32_t)Xl[ro + c0] | ((uint32_t)Xl[ro + c1] << 16);
                pBl[q].y = (uint32_t)Xl[ro + c2] | ((uint32_t)Xl[ro + c3] << 16);
            }
        }
    };
    auto ST = [&](int buf) {
        __nv_bfloat16* Ah = smg + buf * GBUF;
        __nv_bfloat16* Al = Ah + GTILE;
        __nv_bfloat16* Bh = Ah + 2 * GTILE;
        __nv_bfloat16* Bl = Ah + 3 * GTILE;
#pragma unroll
        for (int q = 0; q < 4; ++q) {
            int f = tid + q * 256, r = f >> 3, c = (f & 7) * 4;
            *(uint2*)(Ah + r * GSA + c) = pAh[q];
            *(uint2*)(Al + r * GSA + c) = pAl[q];
            *(uint2*)(Bh + r * GSA + c) = pBh[q];
            *(uint2*)(Bl + r * GSA + c) = pBl[q];
        }
    };

    LD(0);
    for (int ch = 0; ch < 64; ++ch) {
        int buf = ch & 1;
        ST(buf);
        __syncthreads();
        if (ch < 63) LD(ch + 1);
        uint32_t sb = smem_u32(smg + buf * GBUF);
        uint32_t aH = sb, aL = sb + GTILE * 2, bH = sb + 4 * GTILE, bL = sb + 6 * GTILE;
#pragma unroll
        for (int k16 = 0; k16 < 32; k16 += 16) {
            uint32_t fah[4][4], fal[4][4], fbh[4][2], fbl[4][2];
            int arow = wm * 64 + (lane & 15), acol = k16 + ((lane >> 4) << 3);
#pragma unroll
            for (int ma = 0; ma < 4; ++ma) {
                uint32_t off = (uint32_t)((arow + ma * 16) * GSA + acol) * 2;
                ldm_x4(fah[ma], aH + off);
                ldm_x4(fal[ma], aL + off);
            }
            int brow = wn * 32 + (lane & 7), bcol = k16 + (lane & 8);
#pragma unroll
            for (int na = 0; na < 4; ++na) {
                uint32_t off = (uint32_t)((brow + na * 8) * GSA + bcol) * 2;
                ldm_x2(fbh[na], bH + off);
                ldm_x2(fbl[na], bL + off);
            }
#pragma unroll
            for (int ma = 0; ma < 4; ++ma)
#pragma unroll
                for (int na = 0; na < 4; ++na) {
                    MMA(acc[ma][na], fah[ma], fbh[na]);
                    MMA(acc[ma][na], fah[ma], fbl[na]);
                    MMA(acc[ma][na], fal[ma], fbh[na]);
                }
        }
        __syncthreads();
    }
    float* P = g_part + (((size_t)ks * NB + b) * 2 + mode) * (NC * NC);
#pragma unroll
    for (int ma = 0; ma < 4; ++ma)
#pragma unroll
        for (int na = 0; na < 4; ++na) {
            int r = i0 + wm * 64 + ma * 16 + (lane >> 2);
            int c = j0 + wn * 32 + na * 8 + (lane & 3) * 2;
            float2 v0 = make_float2(acc[ma][na][0], acc[ma][na][1]);
            float2 v1 = make_float2(acc[ma][na][2], acc[ma][na][3]);
            *(float2*)&P[(size_t)r * NC + c] = v0;
            *(float2*)&P[(size_t)(r + 8) * NC + c] = v1;
        }
}

__global__ __launch_bounds__(256) void k_gred() {
    int gid = blockIdx.x * 256 + threadIdx.x;
    if (gid >= NB * 2 * NC * NC) return;
    int e = gid % (NC * NC);
    int bm = gid / (NC * NC);
    int m = bm & 1, b = bm >> 1;
    float s = 0.f;
    for (int ks = 0; ks < KSPLIT; ++ks)
        s += g_part[(((size_t)ks * NB + b) * 2 + m) * (NC * NC) + e];
    (m == 0 ? g_C0 : g_Cf)[b * (NC * NC) + e] = s;
}

// ------------------------- 1x1 conv via mma.sync -----------------------------
// grid (128 t-tiles of 128, 2 o-tiles of 128, NB). mode0: B=x, O=g_vs; mode1: B=y, O=out
#define CSA 40
#define CATILE (128 * CSA)
#define CSB 136
#define CBTILE (32 * CSB)
#define CBUFE (2 * CATILE + 2 * CBTILE)
#define CSMEM (2 * CBUFE * 2)
__global__ __launch_bounds__(256, 1) void k_conv_mma(int widx,
                                                     const float* __restrict__ bias,
                                                     float* __restrict__ Oout,
                                                     int mode) {
    extern __shared__ __align__(16) __nv_bfloat16 smc[];
    int tid = threadIdx.x, wid = tid >> 5, lane = tid & 31;
    int t0 = blockIdx.x * 128, o0 = blockIdx.y * 128, b = blockIdx.z;
    const unsigned short* Wh = g_wh + (size_t)widx * NC * NC;
    const unsigned short* Wl = g_wl + (size_t)widx * NC * NC;
    const unsigned short* Bxh = (mode == 0 ? g_xh : g_yh) + (size_t)b * NC * NPIX;
    const unsigned short* Bxl = (mode == 0 ? g_xl : g_yl) + (size_t)b * NC * NPIX;
    float* O = (mode == 0 ? g_vs + (size_t)b * NC * NPIX : Oout + (size_t)b * NC * NPIX);
    int wm = wid >> 2, wn = wid & 3;
    float acc[4][4][4] = {};
    uint2 pAh[4], pAl[4], pBh[4], pBl[4];

    auto LD = [&](int ch) {
        int k0 = ch * 32;
#pragma unroll
        for (int q = 0; q < 4; ++q) {
            int f = tid + q * 256, r = f >> 3, c = (f & 7) * 4;
            size_t off = (size_t)(o0 + r) * NC + k0 + c;
            pAh[q] = *(const uint2*)(Wh + off);
            pAl[q] = *(const uint2*)(Wl + off);
        }
#pragma unroll
        for (int q = 0; q < 4; ++q) {
            int f = tid + q * 256, k = f >> 5, t = (f & 31) * 4;
            size_t off = (size_t)(k0 + k) * NPIX + t0 + t;
            pBh[q] = *(const uint2*)(Bxh + off);
            pBl[q] = *(const uint2*)(Bxl + off);
        }
    };
    auto ST = [&](int buf) {
        __nv_bfloat16* Ah = smc + buf * CBUFE;
        __nv_bfloat16* Al = Ah + CATILE;
        __nv_bfloat16* Bh = Ah + 2 * CATILE;
        __nv_bfloat16* Bl = Bh + CBTILE;
#pragma unroll
        for (int q = 0; q < 4; ++q) {
            int f = tid + q * 256, r = f >> 3, c = (f & 7) * 4;
            *(uint2*)(Ah + r * CSA + c) = pAh[q];
            *(uint2*)(Al + r * CSA + c) = pAl[q];
        }
#pragma unroll
        for (int q = 0; q < 4; ++q) {
            int f = tid + q * 256, k = f >> 5, t = (f & 31) * 4;
            *(uint2*)(Bh + k * CSB + t) = pBh[q];
            *(uint2*)(Bl + k * CSB + t) = pBl[q];
        }
    };

    LD(0);
    for (int ch = 0; ch < 8; ++ch) {
        int buf = ch & 1;
        ST(buf);
        __syncthreads();
        if (ch < 7) LD(ch + 1);
        uint32_t sb = smem_u32(smc + buf * CBUFE);
        uint32_t aH = sb, aL = sb + CATILE * 2, bH = sb + 4 * CATILE, bL = bH + CBTILE * 2;
#pragma unroll
        for (int k16 = 0; k16 < 32; k16 += 16) {
            uint32_t fah[4][4], fal[4][4], fbh[4][2], fbl[4][2];
            int arow = wm * 64 + (lane & 15), acol = k16 + ((lane >> 4) << 3);
#pragma unroll
            for (int ma = 0; ma < 4; ++ma) {
                uint32_t off = (uint32_t)((arow + ma * 16) * CSA + acol) * 2;
                ldm_x4(fah[ma], aH + off);
                ldm_x4(fal[ma], aL + off);
            }
            int krow = k16 + (lane & 15);
#pragma unroll
            for (int na = 0; na < 4; ++na) {
                uint32_t off = (uint32_t)(krow * CSB + wn * 32 + na * 8) * 2;
                ldm_x2t(fbh[na], bH + off);
                ldm_x2t(fbl[na], bL + off);
            }
#pragma unroll
            for (int ma = 0; ma < 4; ++ma)
#pragma unroll
                for (int na = 0; na < 4; ++na) {
                    MMA(acc[ma][na], fah[ma], fbh[na]);
                    MMA(acc[ma][na], fah[ma], fbl[na]);
                    MMA(acc[ma][na], fal[ma], fbh[na]);
                }
        }
        __syncthreads();
    }
#pragma unroll
    for (int ma = 0; ma < 4; ++ma) {
        int r = o0 + wm * 64 + ma * 16 + (lane >> 2);
        float b0v = bias[r], b1v = bias[r + 8];
#pragma unroll
        for (int na = 0; na < 4; ++na) {
            int c = t0 + wn * 32 + na * 8 + (lane & 3) * 2;
            float2 v0 = make_float2(acc[ma][na][0] + b0v, acc[ma][na][1] + b0v);
            float2 v1 = make_float2(acc[ma][na][2] + b1v, acc[ma][na][3] + b1v);
            *(float2*)&O[(size_t)r * NPIX + c] = v0;
            *(float2*)&O[(size_t)(r + 8) * NPIX + c] = v1;
        }
    }
}

// ------------------------- P matrices: A @ W^T (FFMA) ------------------------
__global__ __launch_bounds__(256) void k_mm256(const float* __restrict__ w1,
                                               const float* __restrict__ w2) {
    int tile = blockIdx.x, b = blockIdx.y, z = blockIdx.z;
    const float* A = (z == 0 ? g_Cf : g_C0) + (size_t)b * NC * NC;
    const float* W = (z == 1 ? w1 : w2);
    float* P = g_P + ((size_t)z * NB + b) * NC * NC;
    int i0 = (tile >> 2) * 64, j0 = (tile & 3) * 64;
    __shared__ float As[64][33], Bs[64][33];
    float acc[4][4] = {};
    int ty = threadIdx.x >> 4, tx = threadIdx.x & 15;
    for (int kb = 0; kb < NC; kb += 32) {
        for (int idx = threadIdx.x; idx < 64 * 32; idx += 256) {
            int r = idx >> 5, c = idx & 31;
            As[r][c] = A[(i0 + r) * NC + kb + c];
            Bs[r][c] = W[(j0 + r) * NC + kb + c];
        }
        __syncthreads();
#pragma unroll
        for (int kk = 0; kk < 32; ++kk) {
            float a[4], bv[4];
#pragma unroll
            for (int ii = 0; ii < 4; ++ii) a[ii] = As[ty + 16 * ii][kk];
#pragma unroll
            for (int jj = 0; jj < 4; ++jj) bv[jj] = Bs[tx + 16 * jj][kk];
#pragma unroll
            for (int ii = 0; ii < 4; ++ii)
#pragma unroll
                for (int jj = 0; jj < 4; ++jj) acc[ii][jj] += a[ii] * bv[jj];
        }
        __syncthreads();
    }
    for (int ii = 0; ii < 4; ++ii)
        for (int jj = 0; jj < 4; ++jj)
            P[(i0 + ty + 16 * ii) * NC + j0 + tx + 16 * jj] = acc[ii][jj];
}

// ------------------------- attn -> softmax -> ifft_c -------------------------
__global__ __launch_bounds__(256) void k_attn(const float* __restrict__ w1,
                                              const float* __restrict__ w2,
                                              const float* __restrict__ b1,
                                              const float* __restrict__ b2,
                                              const float* __restrict__ temp) {
    int b = blockIdx.x >> 3, h = blockIdx.x & 7;
    int tid = threadIdx.x;
    __shared__ float Ps[NC][33];
    __shared__ float numS[CH][33];
    __shared__ float redA[CH][8], redB[CH][8];
    __shared__ float qn[CH], kn[CH], w1s[CH], w2s[CH];
    const float* P1 = g_P + ((size_t)0 * NB + b) * NC * NC;
    const float* P2 = g_P + ((size_t)1 * NB + b) * NC * NC;
    const float* P3 = g_P + ((size_t)2 * NB + b) * NC * NC;
    const float* Sb = g_S + b * NC;

    for (int idx = tid; idx < NC * CH; idx += 256)
        Ps[idx >> 5][idx & 31] = P1[(size_t)(idx >> 5) * NC + h * CH + (idx & 31)];
    __syncthreads();
    {
        int c = tid >> 3, dg = tid & 7;
        float acc[4] = {0.f, 0.f, 0.f, 0.f};
        const float* wrow = w1 + (size_t)(h * CH + c) * NC;
        for (int j = 0; j < NC; ++j) {
            float w = wrow[j];
#pragma unroll
            for (int q = 0; q < 4; ++q) acc[q] += w * Ps[j][dg + 8 * q];
        }
#pragma unroll
        for (int q = 0; q < 4; ++q) numS[c][dg + 8 * q] = acc[q];
    }
    __syncthreads();

    for (int idx = tid; idx < NC * CH; idx += 256)
        Ps[idx >> 5][idx & 31] = P2[(size_t)(idx >> 5) * NC + h * CH + (idx & 31)];
    __syncthreads();
    {
        int c = tid >> 3, g = tid & 7;
        const float* wrow = w1 + (size_t)(h * CH + c) * NC;
        float pa = 0.f, pb = 0.f;
        for (int j = g * 32; j < g * 32 + 32; ++j) {
            float w = wrow[j];
            pa += w * Ps[j][c];
            pb += w * Sb[j];
        }
        redA[c][g] = pa; redB[c][g] = pb;
    }
    __syncthreads();
    if (tid < CH) {
        float a = 0.f, bb = 0.f;
        for (int g = 0; g < 8; ++g) { a += redA[tid][g]; bb += redB[tid][g]; }
        float b1c = b1[h * CH + tid];
        w1s[tid] = bb;
        qn[tid] = fmaxf(sqrtf(fmaxf(a + 2.f * b1c * bb + 16384.f * b1c * b1c, 0.f)), 1e-12f);
    }
    __syncthreads();

    for (int idx = tid; idx < NC * CH; idx += 256)
        Ps[idx >> 5][idx & 31] = P3[(size_t)(idx >> 5) * NC + h * CH + (idx & 31)];
    __syncthreads();
    {
        int c = tid >> 3, g = tid & 7;
        const float* wrow = w2 + (size_t)(h * CH + c) * NC;
        float pa = 0.f, pb = 0.f;
        for (int j = g * 32; j < g * 32 + 32; ++j) {
            float w = wrow[j];
            pa += w * Ps[j][c];
            pb += w * Sb[j];
        }
        redA[c][g] = pa; redB[c][g] = pb;
    }
    __syncthreads();
    if (tid < CH) {
        float a = 0.f, bb = 0.f;
        for (int g = 0; g < 8; ++g) { a += redA[tid][g]; bb += redB[tid][g]; }
        float b2d = b2[h * CH + tid];
        w2s[tid] = bb;
        kn[tid] = fmaxf(sqrtf(fmaxf(a + 2.f * b2d * bb + 16384.f * b2d * b2d, 0.f)), 1e-12f);
    }
    __syncthreads();

    {
        float tH = temp[h];
        for (int idx = tid; idx < CH * CH; idx += 256) {
            int c = idx >> 5, d = idx & 31;
            float b1c = b1[h * CH + c], b2d = b2[h * CH + d];
            float numF = numS[c][d] + b1c * w2s[d] + b2d * w1s[c] + 16384.f * b1c * b2d;
            numS[c][d] = tH * numF / (qn[c] * kn[d]);
        }
    }
    __syncthreads();

    if (tid < CH) {
        float mx = -1e30f;
        for (int d = 0; d < CH; ++d) mx = fmaxf(mx, numS[tid][d]);
        float s = 0.f;
        for (int d = 0; d < CH; ++d) { float e = expf(numS[tid][d] - mx); numS[tid][d] = e; s += e; }
        float inv = 1.f / s;
        for (int d = 0; d < CH; ++d) numS[tid][d] *= inv;
    }
    __syncthreads();

    for (int idx = tid; idx < CH * CH; idx += 256) {
        int cp = idx >> 5, d = idx & 31;
        float re = 0.f, im = 0.f;
        for (int c = 0; c < CH; ++c) {
            int ph = (c * cp) & 31;
            float sv, cv;
            sincosf(0.19634954084936207f * (float)ph, &sv, &cv);
            float a = numS[c][d];
            re += a * cv; im += a * sv;
        }
        re *= 0.03125f; im *= 0.03125f;
        if (cp == 0) im += 0.03125f;
        g_At[((size_t)blockIdx.x * CH + cp) * CH + d] = make_float2(re, im);
    }
}

// ------------------------- Dirichlet table -----------------------------------
__global__ __launch_bounds__(256) void k_dtab() {
    int i = blockIdx.x * 256 + threadIdx.x;
    if (i >= 128 * 255) return;
    int s = i / 255, mi = i % 255, m = mi - 127;
    float2 v;
    if (s == 0) {
        v = make_float2(m == 0 ? 1.f : 0.f, 0.f);
    } else {
        double f = (double)s / 128.0;
        double al = (double)m + f;
        double mag = sinpi(f) / (128.0 * sinpi(al / 128.0));
        if (m & 1) mag = -mag;
        double ph = al * (127.0 / 128.0);
        v = make_float2((float)(cospi(ph) * mag), (float)(sinpi(ph) * mag));
    }
    g_Dtab[s * 256 + mi] = v;
}

// ------------------------- Vt[b][128p+s][d] = sum_x vs[d][s][x] D_s(p-x) -----
__global__ __launch_bounds__(256) void k_fft() {
    int s = blockIdx.x;
    int b = blockIdx.y >> 2, d0 = (blockIdx.y & 3) * 64;
    __shared__ float2 Ds[256];
    __shared__ float Vs[64][129];
    int tid = threadIdx.x;
    if (tid < 255) Ds[tid] = g_Dtab[s * 256 + tid];
    for (int idx = tid; idx < 64 * 128; idx += 256) {
        int r = idx >> 7, xx = idx & 127;
        Vs[r][xx] = g_vs[((size_t)(b * NC + d0 + r)) * NPIX + s * 128 + xx];
    }
    __syncthreads();
    int ty = tid >> 3, tx = tid & 7;
    for (int rp = 0; rp < 2; ++rp) {
        int rbase = rp * 32 + tx * 4;
        float2 acc[4][4];
#pragma unroll
        for (int pp = 0; pp < 4; ++pp)
#pragma unroll
            for (int rr = 0; rr < 4; ++rr) acc[pp][rr] = make_float2(0.f, 0.f);
        for (int xx = 0; xx < 128; ++xx) {
            float2 dv[4]; float vv[4];
#pragma unroll
            for (int pp = 0; pp < 4; ++pp) dv[pp] = Ds[ty + 32 * pp - xx + 127];
#pragma unroll
            for (int rr = 0; rr < 4; ++rr) vv[rr] = Vs[rbase + rr][xx];
#pragma unroll
            for (int pp = 0; pp < 4; ++pp)
#pragma unroll
                for (int rr = 0; rr < 4; ++rr) {
                    acc[pp][rr].x += dv[pp].x * vv[rr];
                    acc[pp][rr].y += dv[pp].y * vv[rr];
                }
        }
#pragma unroll
        for (int pp = 0; pp < 4; ++pp)
            for (int rr = 0; rr < 4; ++rr) {
                int p = ty + 32 * pp;
                g_Vt[((size_t)b * NPIX + (p << 7) + s) * NC + d0 + rbase + rr] = acc[pp][rr];
            }
    }
}

// ------------------------- y = | Atil @ Vt |, written as bf16 split ----------
__global__ __launch_bounds__(256) void k_attnv() {
    int bh = blockIdx.y;
    int b = bh >> 3, h = bh & 7;
    int t0 = blockIdx.x * 1024;
    int tid = threadIdx.x;
    __shared__ float2 Amat[CH][33];
    __shared__ float2 Vsm[64][33];
    for (int idx = tid; idx < CH * CH; idx += 256)
        Amat[idx >> 5][idx & 31] = g_At[(size_t)bh * CH * CH + idx];
    int ty = tid >> 4, tx = tid & 15;
    for (int ck = 0; ck < 16; ++ck) {
        int tc = t0 + ck * 64;
        __syncthreads();
        for (int idx = tid; idx < 64 * CH; idx += 256) {
            int tt = idx >> 5, d = idx & 31;
            Vsm[tt][d] = g_Vt[((size_t)b * NPIX + tc + tt) * NC + h * CH + d];
        }
        __syncthreads();
        float accr[2][4] = {}, acci[2][4] = {};
        for (int d = 0; d < CH; ++d) {
            float2 a0 = Amat[ty * 2][d], a1 = Amat[ty * 2 + 1][d];
            float2 v[4];
#pragma unroll
            for (int q = 0; q < 4; ++q) v[q] = Vsm[tx + 16 * q][d];
#pragma unroll
            for (int q = 0; q < 4; ++q) {
                accr[0][q] += a0.x * v[q].x - a0.y * v[q].y;
                acci[0][q] += a0.x * v[q].y + a0.y * v[q].x;
                accr[1][q] += a1.x * v[q].x - a1.y * v[q].y;
                acci[1][q] += a1.x * v[q].y + a1.y * v[q].x;
            }
        }
        for (int i = 0; i < 2; ++i) {
            int cg = h * CH + ty * 2 + i;
            for (int q = 0; q < 4; ++q) {
                float re = accr[i][q], im = acci[i][q];
                float yv = sqrtf(re * re + im * im);
                size_t oidx = ((size_t)b * NC + cg) * NPIX + tc + tx + 16 * q;
                __nv_bfloat16 hh = __float2bfloat16_rn(yv);
                g_yh[oidx] = __bfloat16_as_ushort(hh);
                g_yl[oidx] = __bfloat16_as_ushort(__float2bfloat16_rn(yv - __bfloat162float(hh)));
            }
        }
    }
}

// ------------------------- launch --------------------------------------------
extern "C" void kernel_launch(void* const* d_in, const int* in_sizes, int n_in,
                              void* d_out, int out_size) {
    const float* x  = (const float*)d_in[0];
    const float* w1 = (const float*)d_in[1];
    const float* b1 = (const float*)d_in[2];
    const float* w2 = (const float*)d_in[3];
    const float* b2 = (const float*)d_in[4];
    const float* w3 = (const float*)d_in[5];
    const float* b3 = (const float*)d_in[6];
    const float* wo = (const float*)d_in[7];
    const float* bo = (const float*)d_in[8];
    const float* temp = (const float*)d_in[9];
    float* out = (float*)d_out;

    cudaFuncSetAttribute(k_gram_mma, cudaFuncAttributeMaxDynamicSharedMemorySize, GSMEM);
    cudaFuncSetAttribute(k_conv_mma, cudaFuncAttributeMaxDynamicSharedMemorySize, CSMEM);

    k_dtab<<<128, 256>>>();
    k_xsplit<<<NB * NC * NPIX / 4 / 256, 256>>>(x);
    k_wsplit<<<2 * NC * NC / 4 / 256, 256>>>(w3, wo);
    k_sum<<<NB * NC, 256>>>(x);
    k_gram_mma<<<dim3(4, NB, KSPLIT * 2), 256, GSMEM>>>();
    k_gred<<<(NB * 2 * NC * NC) / 256, 256>>>();
    k_mm256<<<dim3(16, NB, 3), 256>>>(w1, w2);
    k_attn<<<NB * NHEADS, 256>>>(w1, w2, b1, b2, temp);
    k_conv_mma<<<dim3(128, 2, NB), 256, CSMEM>>>(0, b3, nullptr, 0);
    k_fft<<<dim3(128, 16), 256>>>();
    k_attnv<<<dim3(16, 32), 256>>>();
    k_conv_mma<<<dim3(128, 2, NB), 256, CSMEM>>>(1, bo, out, 1);
}

// round 12
// speedup vs baseline: 1.9626x; 1.0881x over previous
#include <cuda_runtime.h>
#include <cuda_bf16.h>
#include <math.h>
#include <stdint.h>

#define NB 4
#define NC 256
#define NPIX 16384
#define NHEADS 8
#define CH 32
#define KSPLIT 8

// ------------------------- scratch ------------------------------------------
__device__ float  g_S[NB * NC];
__device__ float  g_part[KSPLIT * NB * 2 * NC * NC];
__device__ float  g_C0[NB * NC * NC];
__device__ float  g_Cf[NB * NC * NC];
__device__ float  g_P[3 * NB * NC * NC];
__device__ float2 g_At[NB * NHEADS * CH * CH];
__device__ float2 g_Vt[(size_t)NB * NPIX * NC];
__device__ float2 g_Dtab[128 * 256];
// prepacked bf16 hi/lo splits
__device__ unsigned short g_xh[(size_t)NB * NC * NPIX];
__device__ unsigned short g_xl[(size_t)NB * NC * NPIX];
__device__ unsigned short g_yh[(size_t)NB * NC * NPIX];
__device__ unsigned short g_yl[(size_t)NB * NC * NPIX];
__device__ unsigned short g_vsh[(size_t)NB * NC * NPIX];
__device__ unsigned short g_vsl[(size_t)NB * NC * NPIX];
__device__ unsigned short g_wh[2 * NC * NC];
__device__ unsigned short g_wl[2 * NC * NC];
// expanded Dirichlet matrices, [s][p][x], bf16 hi/lo, re/im
__device__ unsigned short g_DreH[128 * 128 * 128];
__device__ unsigned short g_DreL[128 * 128 * 128];
__device__ unsigned short g_DimH[128 * 128 * 128];
__device__ unsigned short g_DimL[128 * 128 * 128];

// ------------------------- mma.sync helpers ----------------------------------
__device__ __forceinline__ uint32_t smem_u32(const void* p) {
    uint32_t a;
    asm("{ .reg .u64 t; cvta.to.shared.u64 t, %1; cvt.u32.u64 %0, t; }" : "=r"(a) : "l"(p));
    return a;
}
__device__ __forceinline__ void MMA(float* d, const uint32_t* a, const uint32_t* b) {
    asm volatile("mma.sync.aligned.m16n8k16.row.col.f32.bf16.bf16.f32 "
        "{%0,%1,%2,%3}, {%4,%5,%6,%7}, {%8,%9}, {%0,%1,%2,%3};"
        : "+f"(d[0]), "+f"(d[1]), "+f"(d[2]), "+f"(d[3])
        : "r"(a[0]), "r"(a[1]), "r"(a[2]), "r"(a[3]), "r"(b[0]), "r"(b[1]));
}
__device__ __forceinline__ void ldm_x4(uint32_t* r, uint32_t a) {
    asm volatile("ldmatrix.sync.aligned.m8n8.x4.shared.b16 {%0,%1,%2,%3}, [%4];"
        : "=r"(r[0]), "=r"(r[1]), "=r"(r[2]), "=r"(r[3]) : "r"(a));
}
__device__ __forceinline__ void ldm_x2(uint32_t* r, uint32_t a) {
    asm volatile("ldmatrix.sync.aligned.m8n8.x2.shared.b16 {%0,%1}, [%2];"
        : "=r"(r[0]), "=r"(r[1]) : "r"(a));
}
__device__ __forceinline__ void ldm_x2t(uint32_t* r, uint32_t a) {
    asm volatile("ldmatrix.sync.aligned.m8n8.x2.trans.shared.b16 {%0,%1}, [%2];"
        : "=r"(r[0]), "=r"(r[1]) : "r"(a));
}
__device__ __forceinline__ void split_pack(float4 v, uint2& hi, uint2& lo) {
    __nv_bfloat16 h0 = __float2bfloat16_rn(v.x), h1 = __float2bfloat16_rn(v.y);
    __nv_bfloat16 h2 = __float2bfloat16_rn(v.z), h3 = __float2bfloat16_rn(v.w);
    __nv_bfloat16 l0 = __float2bfloat16_rn(v.x - __bfloat162float(h0));
    __nv_bfloat16 l1 = __float2bfloat16_rn(v.y - __bfloat162float(h1));
    __nv_bfloat16 l2 = __float2bfloat16_rn(v.z - __bfloat162float(h2));
    __nv_bfloat16 l3 = __float2bfloat16_rn(v.w - __bfloat162float(h3));
    hi.x = (uint32_t)__bfloat16_as_ushort(h0) | ((uint32_t)__bfloat16_as_ushort(h1) << 16);
    hi.y = (uint32_t)__bfloat16_as_ushort(h2) | ((uint32_t)__bfloat16_as_ushort(h3) << 16);
    lo.x = (uint32_t)__bfloat16_as_ushort(l0) | ((uint32_t)__bfloat16_as_ushort(l1) << 16);
    lo.y = (uint32_t)__bfloat16_as_ushort(l2) | ((uint32_t)__bfloat16_as_ushort(l3) << 16);
}
__device__ __forceinline__ void pack2(float a, float b, uint32_t& hi, uint32_t& lo) {
    __nv_bfloat16 ha = __float2bfloat16_rn(a), hb = __float2bfloat16_rn(b);
    __nv_bfloat16 la = __float2bfloat16_rn(a - __bfloat162float(ha));
    __nv_bfloat16 lb = __float2bfloat16_rn(b - __bfloat162float(hb));
    hi = (uint32_t)__bfloat16_as_ushort(ha) | ((uint32_t)__bfloat16_as_ushort(hb) << 16);
    lo = (uint32_t)__bfloat16_as_ushort(la) | ((uint32_t)__bfloat16_as_ushort(lb) << 16);
}

// ------------------------- split precompute ----------------------------------
__global__ __launch_bounds__(256) void k_xsplit(const float* __restrict__ x) {
    size_t gid = (size_t)blockIdx.x * 256 + threadIdx.x;
    float4 v = ((const float4*)x)[gid];
    uint2 hi, lo;
    split_pack(v, hi, lo);
    ((uint2*)g_xh)[gid] = hi;
    ((uint2*)g_xl)[gid] = lo;
}
__global__ __launch_bounds__(256) void k_wsplit(const float* __restrict__ w3,
                                                const float* __restrict__ wo) {
    int gid = blockIdx.x * 256 + threadIdx.x;
    int per = NC * NC / 4;
    int m = gid / per, e = gid % per;
    const float* src = (m == 0 ? w3 : wo);
    float4 v = ((const float4*)src)[e];
    uint2 hi, lo;
    split_pack(v, hi, lo);
    ((uint2*)g_wh)[gid] = hi;
    ((uint2*)g_wl)[gid] = lo;
}

// ------------------------- per-channel sums ---------------------------------
__global__ __launch_bounds__(256) void k_sum(const float* __restrict__ x) {
    int bc = blockIdx.x;
    const float* p = x + (size_t)bc * NPIX;
    float s = 0.f;
    for (int i = threadIdx.x; i < NPIX; i += 256) s += p[i];
    __shared__ float sm[256];
    sm[threadIdx.x] = s; __syncthreads();
    for (int w = 128; w > 0; w >>= 1) {
        if (threadIdx.x < w) sm[threadIdx.x] += sm[threadIdx.x + w];
        __syncthreads();
    }
    if (threadIdx.x == 0) g_S[bc] = sm[0];
}

// ------------------------- Gram via mma.sync (symmetric: 3 tiles) ------------
#define GSA 40
#define GTILE (128 * GSA)
#define GBUF (4 * GTILE)
#define GSMEM (2 * GBUF * 2)
__global__ __launch_bounds__(256, 1) void k_gram_mma() {
    extern __shared__ __align__(16) __nv_bfloat16 smg[];
    int tid = threadIdx.x, wid = tid >> 5, lane = tid & 31;
    int tile = blockIdx.x;   // 0:(0,0) 1:(0,128) 2:(128,128)
    int i0 = (tile == 2) ? 128 : 0;
    int j0 = (tile == 0) ? 0 : 128;
    int b = blockIdx.y, ks = blockIdx.z >> 1, mode = blockIdx.z & 1;
    const unsigned short* Xh = g_xh + (size_t)b * NC * NPIX;
    const unsigned short* Xl = g_xl + (size_t)b * NC * NPIX;
    int wm = wid >> 2, wn = wid & 3;
    float acc[4][4][4] = {};
    uint2 pAh[4], pAl[4], pBh[4], pBl[4];

    auto LD = [&](int ch) {
        int Kc = ks * 2048 + ch * 32;
#pragma unroll
        for (int q = 0; q < 4; ++q) {
            int f = tid + q * 256, r = f >> 3, c = (f & 7) * 4;
            size_t off = (size_t)(i0 + r) * NPIX + Kc + c;
            pAh[q] = *(const uint2*)(Xh + off);
            pAl[q] = *(const uint2*)(Xl + off);
        }
        if (mode == 0) {
#pragma unroll
            for (int q = 0; q < 4; ++q) {
                int f = tid + q * 256, r = f >> 3, c = (f & 7) * 4;
                size_t off = (size_t)(j0 + r) * NPIX + Kc + c;
                pBh[q] = *(const uint2*)(Xh + off);
                pBl[q] = *(const uint2*)(Xl + off);
            }
        } else {
            int fy = (128 - (Kc >> 7)) & 127, xc0 = Kc & 127;
#pragma unroll
            for (int q = 0; q < 4; ++q) {
                int f = tid + q * 256, r = f >> 3;
                int x0 = xc0 + (f & 7) * 4;
                size_t ro = (size_t)(j0 + r) * NPIX + fy * 128;
                int c0 = (128 - x0) & 127, c1 = 127 - x0, c2 = 126 - x0, c3 = 125 - x0;
                pBh[q].x = (uint32_t)Xh[ro + c0] | ((uint32_t)Xh[ro + c1] << 16);
                pBh[q].y = (uint32_t)Xh[ro + c2] | ((uint32_t)Xh[ro + c3] << 16);
                pBl[q].x = (uint32_t)Xl[ro + c0] | ((uint32_t)Xl[ro + c1] << 16);
                pBl[q].y = (uint32_t)Xl[ro + c2] | ((uint32_t)Xl[ro + c3] << 16);
            }
        }
    };
    auto ST = [&](int buf) {
        __nv_bfloat16* Ah = smg + buf * GBUF;
        __nv_bfloat16* Al = Ah + GTILE;
        __nv_bfloat16* Bh = Ah + 2 * GTILE;
        __nv_bfloat16* Bl = Ah + 3 * GTILE;
#pragma unroll
        for (int q = 0; q < 4; ++q) {
            int f = tid + q * 256, r = f >> 3, c = (f & 7) * 4;
            *(uint2*)(Ah + r * GSA + c) = pAh[q];
            *(uint2*)(Al + r * GSA + c) = pAl[q];
            *(uint2*)(Bh + r * GSA + c) = pBh[q];
            *(uint2*)(Bl + r * GSA + c) = pBl[q];
        }
    };

    LD(0);
    for (int ch = 0; ch < 64; ++ch) {
        int buf = ch & 1;
        ST(buf);
        __syncthreads();
        if (ch < 63) LD(ch + 1);
        uint32_t sb = smem_u32(smg + buf * GBUF);
        uint32_t aH = sb, aL = sb + GTILE * 2, bH = sb + 4 * GTILE, bL = sb + 6 * GTILE;
#pragma unroll
        for (int k16 = 0; k16 < 32; k16 += 16) {
            uint32_t fah[4][4], fal[4][4], fbh[4][2], fbl[4][2];
            int arow = wm * 64 + (lane & 15), acol = k16 + ((lane >> 4) << 3);
#pragma unroll
            for (int ma = 0; ma < 4; ++ma) {
                uint32_t off = (uint32_t)((arow + ma * 16) * GSA + acol) * 2;
                ldm_x4(fah[ma], aH + off);
                ldm_x4(fal[ma], aL + off);
            }
            int brow = wn * 32 + (lane & 7), bcol = k16 + (lane & 8);
#pragma unroll
            for (int na = 0; na < 4; ++na) {
                uint32_t off = (uint32_t)((brow + na * 8) * GSA + bcol) * 2;
                ldm_x2(fbh[na], bH + off);
                ldm_x2(fbl[na], bL + off);
            }
#pragma unroll
            for (int ma = 0; ma < 4; ++ma)
#pragma unroll
                for (int na = 0; na < 4; ++na) {
                    MMA(acc[ma][na], fah[ma], fbh[na]);
                    MMA(acc[ma][na], fah[ma], fbl[na]);
                    MMA(acc[ma][na], fal[ma], fbh[na]);
                }
        }
        __syncthreads();
    }
    float* P = g_part + (((size_t)ks * NB + b) * 2 + mode) * (NC * NC);
#pragma unroll
    for (int ma = 0; ma < 4; ++ma)
#pragma unroll
        for (int na = 0; na < 4; ++na) {
            int r = i0 + wm * 64 + ma * 16 + (lane >> 2);
            int c = j0 + wn * 32 + na * 8 + (lane & 3) * 2;
            float2 v0 = make_float2(acc[ma][na][0], acc[ma][na][1]);
            float2 v1 = make_float2(acc[ma][na][2], acc[ma][na][3]);
            *(float2*)&P[(size_t)r * NC + c] = v0;
            *(float2*)&P[(size_t)(r + 8) * NC + c] = v1;
        }
}

__global__ __launch_bounds__(256) void k_gred() {
    int gid = blockIdx.x * 256 + threadIdx.x;
    if (gid >= NB * 2 * NC * NC) return;
    int e = gid % (NC * NC);
    int bm = gid / (NC * NC);
    int m = bm & 1, b = bm >> 1;
    int r = e / NC, c = e % NC;
    int esrc = (r >= 128 && c < 128) ? (c * NC + r) : e;   // symmetric mirror
    float s = 0.f;
    for (int ks = 0; ks < KSPLIT; ++ks)
        s += g_part[(((size_t)ks * NB + b) * 2 + m) * (NC * NC) + esrc];
    (m == 0 ? g_C0 : g_Cf)[b * (NC * NC) + e] = s;
}

// ------------------------- 1x1 conv via mma.sync -----------------------------
// mode0: B=x split, O=g_vsh/g_vsl (bf16 split); mode1: B=y split, O=out fp32
#define CSA 40
#define CATILE (128 * CSA)
#define CSB 136
#define CBTILE (32 * CSB)
#define CBUFE (2 * CATILE + 2 * CBTILE)
#define CSMEM (2 * CBUFE * 2)
__global__ __launch_bounds__(256, 1) void k_conv_mma(int widx,
                                                     const float* __restrict__ bias,
                                                     float* __restrict__ Oout,
                                                     int mode) {
    extern __shared__ __align__(16) __nv_bfloat16 smc[];
    int tid = threadIdx.x, wid = tid >> 5, lane = tid & 31;
    int t0 = blockIdx.x * 128, o0 = blockIdx.y * 128, b = blockIdx.z;
    const unsigned short* Wh = g_wh + (size_t)widx * NC * NC;
    const unsigned short* Wl = g_wl + (size_t)widx * NC * NC;
    const unsigned short* Bxh = (mode == 0 ? g_xh : g_yh) + (size_t)b * NC * NPIX;
    const unsigned short* Bxl = (mode == 0 ? g_xl : g_yl) + (size_t)b * NC * NPIX;
    int wm = wid >> 2, wn = wid & 3;
    float acc[4][4][4] = {};
    uint2 pAh[4], pAl[4], pBh[4], pBl[4];

    auto LD = [&](int ch) {
        int k0 = ch * 32;
#pragma unroll
        for (int q = 0; q < 4; ++q) {
            int f = tid + q * 256, r = f >> 3, c = (f & 7) * 4;
            size_t off = (size_t)(o0 + r) * NC + k0 + c;
            pAh[q] = *(const uint2*)(Wh + off);
            pAl[q] = *(const uint2*)(Wl + off);
        }
#pragma unroll
        for (int q = 0; q < 4; ++q) {
            int f = tid + q * 256, k = f >> 5, t = (f & 31) * 4;
            size_t off = (size_t)(k0 + k) * NPIX + t0 + t;
            pBh[q] = *(const uint2*)(Bxh + off);
            pBl[q] = *(const uint2*)(Bxl + off);
        }
    };
    auto ST = [&](int buf) {
        __nv_bfloat16* Ah = smc + buf * CBUFE;
        __nv_bfloat16* Al = Ah + CATILE;
        __nv_bfloat16* Bh = Ah + 2 * CATILE;
        __nv_bfloat16* Bl = Bh + CBTILE;
#pragma unroll
        for (int q = 0; q < 4; ++q) {
            int f = tid + q * 256, r = f >> 3, c = (f & 7) * 4;
            *(uint2*)(Ah + r * CSA + c) = pAh[q];
            *(uint2*)(Al + r * CSA + c) = pAl[q];
        }
#pragma unroll
        for (int q = 0; q < 4; ++q) {
            int f = tid + q * 256, k = f >> 5, t = (f & 31) * 4;
            *(uint2*)(Bh + k * CSB + t) = pBh[q];
            *(uint2*)(Bl + k * CSB + t) = pBl[q];
        }
    };

    LD(0);
    for (int ch = 0; ch < 8; ++ch) {
        int buf = ch & 1;
        ST(buf);
        __syncthreads();
        if (ch < 7) LD(ch + 1);
        uint32_t sb = smem_u32(smc + buf * CBUFE);
        uint32_t aH = sb, aL = sb + CATILE * 2, bH = sb + 4 * CATILE, bL = bH + CBTILE * 2;
#pragma unroll
        for (int k16 = 0; k16 < 32; k16 += 16) {
            uint32_t fah[4][4], fal[4][4], fbh[4][2], fbl[4][2];
            int arow = wm * 64 + (lane & 15), acol = k16 + ((lane >> 4) << 3);
#pragma unroll
            for (int ma = 0; ma < 4; ++ma) {
                uint32_t off = (uint32_t)((arow + ma * 16) * CSA + acol) * 2;
                ldm_x4(fah[ma], aH + off);
                ldm_x4(fal[ma], aL + off);
            }
            int krow = k16 + (lane & 15);
#pragma unroll
            for (int na = 0; na < 4; ++na) {
                uint32_t off = (uint32_t)(krow * CSB + wn * 32 + na * 8) * 2;
                ldm_x2t(fbh[na], bH + off);
                ldm_x2t(fbl[na], bL + off);
            }
#pragma unroll
            for (int ma = 0; ma < 4; ++ma)
#pragma unroll
                for (int na = 0; na < 4; ++na) {
                    MMA(acc[ma][na], fah[ma], fbh[na]);
                    MMA(acc[ma][na], fah[ma], fbl[na]);
                    MMA(acc[ma][na], fal[ma], fbh[na]);
                }
        }
        __syncthreads();
    }
#pragma unroll
    for (int ma = 0; ma < 4; ++ma) {
        int r = o0 + wm * 64 + ma * 16 + (lane >> 2);
        float b0v = bias[r], b1v = bias[r + 8];
#pragma unroll
        for (int na = 0; na < 4; ++na) {
            int c = t0 + wn * 32 + na * 8 + (lane & 3) * 2;
            if (mode == 0) {
                uint32_t h0, l0, h1, l1;
                pack2(acc[ma][na][0] + b0v, acc[ma][na][1] + b0v, h0, l0);
                pack2(acc[ma][na][2] + b1v, acc[ma][na][3] + b1v, h1, l1);
                size_t i0v = (size_t)(b * NC + r) * NPIX + c;
                *(uint32_t*)(g_vsh + i0v) = h0;
                *(uint32_t*)(g_vsl + i0v) = l0;
                size_t i1v = i0v + (size_t)8 * NPIX;
                *(uint32_t*)(g_vsh + i1v) = h1;
                *(uint32_t*)(g_vsl + i1v) = l1;
            } else {
                float* O = Oout + (size_t)b * NC * NPIX;
                float2 v0 = make_float2(acc[ma][na][0] + b0v, acc[ma][na][1] + b0v);
                float2 v1 = make_float2(acc[ma][na][2] + b1v, acc[ma][na][3] + b1v);
                *(float2*)&O[(size_t)r * NPIX + c] = v0;
                *(float2*)&O[(size_t)(r + 8) * NPIX + c] = v1;
            }
        }
    }
}

// ------------------------- P matrices: A @ W^T (FFMA) ------------------------
__global__ __launch_bounds__(256) void k_mm256(const float* __restrict__ w1,
                                               const float* __restrict__ w2) {
    int tile = blockIdx.x, b = blockIdx.y, z = blockIdx.z;
    const float* A = (z == 0 ? g_Cf : g_C0) + (size_t)b * NC * NC;
    const float* W = (z == 1 ? w1 : w2);
    float* P = g_P + ((size_t)z * NB + b) * NC * NC;
    int i0 = (tile >> 2) * 64, j0 = (tile & 3) * 64;
    __shared__ float As[64][33], Bs[64][33];
    float acc[4][4] = {};
    int ty = threadIdx.x >> 4, tx = threadIdx.x & 15;
    for (int kb = 0; kb < NC; kb += 32) {
        for (int idx = threadIdx.x; idx < 64 * 32; idx += 256) {
            int r = idx >> 5, c = idx & 31;
            As[r][c] = A[(i0 + r) * NC + kb + c];
            Bs[r][c] = W[(j0 + r) * NC + kb + c];
        }
        __syncthreads();
#pragma unroll
        for (int kk = 0; kk < 32; ++kk) {
            float a[4], bv[4];
#pragma unroll
            for (int ii = 0; ii < 4; ++ii) a[ii] = As[ty + 16 * ii][kk];
#pragma unroll
            for (int jj = 0; jj < 4; ++jj) bv[jj] = Bs[tx + 16 * jj][kk];
#pragma unroll
            for (int ii = 0; ii < 4; ++ii)
#pragma unroll
                for (int jj = 0; jj < 4; ++jj) acc[ii][jj] += a[ii] * bv[jj];
        }
        __syncthreads();
    }
    for (int ii = 0; ii < 4; ++ii)
        for (int jj = 0; jj < 4; ++jj)
            P[(i0 + ty + 16 * ii) * NC + j0 + tx + 16 * jj] = acc[ii][jj];
}

// ------------------------- attn -> softmax -> ifft_c -------------------------
__global__ __launch_bounds__(256) void k_attn(const float* __restrict__ w1,
                                              const float* __restrict__ w2,
                                              const float* __restrict__ b1,
                                              const float* __restrict__ b2,
                                              const float* __restrict__ temp) {
    int b = blockIdx.x >> 3, h = blockIdx.x & 7;
    int tid = threadIdx.x;
    __shared__ float Ps[NC][33];
    __shared__ float numS[CH][33];
    __shared__ float redA[CH][8], redB[CH][8];
    __shared__ float qn[CH], kn[CH], w1s[CH], w2s[CH];
    const float* P1 = g_P + ((size_t)0 * NB + b) * NC * NC;
    const float* P2 = g_P + ((size_t)1 * NB + b) * NC * NC;
    const float* P3 = g_P + ((size_t)2 * NB + b) * NC * NC;
    const float* Sb = g_S + b * NC;

    for (int idx = tid; idx < NC * CH; idx += 256)
        Ps[idx >> 5][idx & 31] = P1[(size_t)(idx >> 5) * NC + h * CH + (idx & 31)];
    __syncthreads();
    {
        int c = tid >> 3, dg = tid & 7;
        float acc[4] = {0.f, 0.f, 0.f, 0.f};
        const float* wrow = w1 + (size_t)(h * CH + c) * NC;
        for (int j = 0; j < NC; ++j) {
            float w = wrow[j];
#pragma unroll
            for (int q = 0; q < 4; ++q) acc[q] += w * Ps[j][dg + 8 * q];
        }
#pragma unroll
        for (int q = 0; q < 4; ++q) numS[c][dg + 8 * q] = acc[q];
    }
    __syncthreads();

    for (int idx = tid; idx < NC * CH; idx += 256)
        Ps[idx >> 5][idx & 31] = P2[(size_t)(idx >> 5) * NC + h * CH + (idx & 31)];
    __syncthreads();
    {
        int c = tid >> 3, g = tid & 7;
        const float* wrow = w1 + (size_t)(h * CH + c) * NC;
        float pa = 0.f, pb = 0.f;
        for (int j = g * 32; j < g * 32 + 32; ++j) {
            float w = wrow[j];
            pa += w * Ps[j][c];
            pb += w * Sb[j];
        }
        redA[c][g] = pa; redB[c][g] = pb;
    }
    __syncthreads();
    if (tid < CH) {
        float a = 0.f, bb = 0.f;
        for (int g = 0; g < 8; ++g) { a += redA[tid][g]; bb += redB[tid][g]; }
        float b1c = b1[h * CH + tid];
        w1s[tid] = bb;
        qn[tid] = fmaxf(sqrtf(fmaxf(a + 2.f * b1c * bb + 16384.f * b1c * b1c, 0.f)), 1e-12f);
    }
    __syncthreads();

    for (int idx = tid; idx < NC * CH; idx += 256)
        Ps[idx >> 5][idx & 31] = P3[(size_t)(idx >> 5) * NC + h * CH + (idx & 31)];
    __syncthreads();
    {
        int c = tid >> 3, g = tid & 7;
        const float* wrow = w2 + (size_t)(h * CH + c) * NC;
        float pa = 0.f, pb = 0.f;
        for (int j = g * 32; j < g * 32 + 32; ++j) {
            float w = wrow[j];
            pa += w * Ps[j][c];
            pb += w * Sb[j];
        }
        redA[c][g] = pa; redB[c][g] = pb;
    }
    __syncthreads();
    if (tid < CH) {
        float a = 0.f, bb = 0.f;
        for (int g = 0; g < 8; ++g) { a += redA[tid][g]; bb += redB[tid][g]; }
        float b2d = b2[h * CH + tid];
        w2s[tid] = bb;
        kn[tid] = fmaxf(sqrtf(fmaxf(a + 2.f * b2d * bb + 16384.f * b2d * b2d, 0.f)), 1e-12f);
    }
    __syncthreads();

    {
        float tH = temp[h];
        for (int idx = tid; idx < CH * CH; idx += 256) {
            int c = idx >> 5, d = idx & 31;
            float b1c = b1[h * CH + c], b2d = b2[h * CH + d];
            float numF = numS[c][d] + b1c * w2s[d] + b2d * w1s[c] + 16384.f * b1c * b2d;
            numS[c][d] = tH * numF / (qn[c] * kn[d]);
        }
    }
    __syncthreads();

    if (tid < CH) {
        float mx = -1e30f;
        for (int d = 0; d < CH; ++d) mx = fmaxf(mx, numS[tid][d]);
        float s = 0.f;
        for (int d = 0; d < CH; ++d) { float e = expf(numS[tid][d] - mx); numS[tid][d] = e; s += e; }
        float inv = 1.f / s;
        for (int d = 0; d < CH; ++d) numS[tid][d] *= inv;
    }
    __syncthreads();

    for (int idx = tid; idx < CH * CH; idx += 256) {
        int cp = idx >> 5, d = idx & 31;
        float re = 0.f, im = 0.f;
        for (int c = 0; c < CH; ++c) {
            int ph = (c * cp) & 31;
            float sv, cv;
            sincosf(0.19634954084936207f * (float)ph, &sv, &cv);
            float a = numS[c][d];
            re += a * cv; im += a * sv;
        }
        re *= 0.03125f; im *= 0.03125f;
        if (cp == 0) im += 0.03125f;
        g_At[((size_t)blockIdx.x * CH + cp) * CH + d] = make_float2(re, im);
    }
}

// ------------------------- Dirichlet table + bf16 expansion ------------------
__global__ __launch_bounds__(256) void k_dtab() {
    int i = blockIdx.x * 256 + threadIdx.x;
    if (i >= 128 * 255) return;
    int s = i / 255, mi = i % 255, m = mi - 127;
    float2 v;
    if (s == 0) {
        v = make_float2(m == 0 ? 1.f : 0.f, 0.f);
    } else {
        double f = (double)s / 128.0;
        double al = (double)m + f;
        double mag = sinpi(f) / (128.0 * sinpi(al / 128.0));
        if (m & 1) mag = -mag;
        double ph = al * (127.0 / 128.0);
        v = make_float2((float)(cospi(ph) * mag), (float)(sinpi(ph) * mag));
    }
    g_Dtab[s * 256 + mi] = v;
}
__global__ __launch_bounds__(256) void k_dexp() {
    int gid = blockIdx.x * 256 + threadIdx.x;   // over 2M = 128*128*128
    int x = gid & 127, p = (gid >> 7) & 127, s = gid >> 14;
    float2 v = g_Dtab[s * 256 + (p - x + 127)];
    __nv_bfloat16 hr = __float2bfloat16_rn(v.x);
    __nv_bfloat16 hi = __float2bfloat16_rn(v.y);
    g_DreH[gid] = __bfloat16_as_ushort(hr);
    g_DreL[gid] = __bfloat16_as_ushort(__float2bfloat16_rn(v.x - __bfloat162float(hr)));
    g_DimH[gid] = __bfloat16_as_ushort(hi);
    g_DimL[gid] = __bfloat16_as_ushort(__float2bfloat16_rn(v.y - __bfloat162float(hi)));
}

// ------------------------- Dirichlet transform via mma.sync ------------------
// Vt[p][d] = sum_x D_s[p][x] * vs[d][s*128+x]   (re and im GEMMs share B)
#define FSA 40
#define FSMEM ((4 * 128 * FSA + 2 * 64 * FSA) * 2)   // 51200 B
__global__ __launch_bounds__(256) void k_fft_mma() {
    extern __shared__ __align__(16) __nv_bfloat16 smf[];
    int tid = threadIdx.x, wid = tid >> 5, lane = tid & 31;
    int s = blockIdx.x;
    int b = blockIdx.y >> 2, d0 = (blockIdx.y & 3) * 64;
    int wm = wid >> 1, wn = wid & 1;   // 4 x 2 warp grid: M=128 (wm*32), N=64 (wn*32)
    float accRe[2][4][4] = {}, accIm[2][4][4] = {};
    const uint32_t sb = smem_u32(smf);
    const uint32_t oReH = 0, oReL = 5120, oImH = 10240, oImL = 15360, oBH = 20480, oBL = 23040;

    for (int kc = 0; kc < 128; kc += 32) {
        __syncthreads();
#pragma unroll
        for (int q = 0; q < 4; ++q) {
            int f = tid + q * 256, r = f >> 3, c = (f & 7) * 4;
            size_t so = (size_t)s * 16384 + r * 128 + kc + c;
            uint32_t dofs = r * FSA + c;
            *(uint2*)(smf + oReH + dofs) = *(const uint2*)(g_DreH + so);
            *(uint2*)(smf + oReL + dofs) = *(const uint2*)(g_DreL + so);
            *(uint2*)(smf + oImH + dofs) = *(const uint2*)(g_DimH + so);
            *(uint2*)(smf + oImL + dofs) = *(const uint2*)(g_DimL + so);
        }
#pragma unroll
        for (int q = 0; q < 2; ++q) {
            int f = tid + q * 256, r = f >> 3, c = (f & 7) * 4;
            size_t so = (size_t)(b * NC + d0 + r) * NPIX + s * 128 + kc + c;
            uint32_t dofs = r * FSA + c;
            *(uint2*)(smf + oBH + dofs) = *(const uint2*)(g_vsh + so);
            *(uint2*)(smf + oBL + dofs) = *(const uint2*)(g_vsl + so);
        }
        __syncthreads();
#pragma unroll
        for (int k16 = 0; k16 < 32; k16 += 16) {
            uint32_t fbh[4][2], fbl[4][2];
            int brow = wn * 32 + (lane & 7), bcol = k16 + (lane & 8);
#pragma unroll
            for (int na = 0; na < 4; ++na) {
                uint32_t off = (uint32_t)((brow + na * 8) * FSA + bcol) * 2;
                ldm_x2(fbh[na], sb + oBH * 2 + off);
                ldm_x2(fbl[na], sb + oBL * 2 + off);
            }
            int arow = wm * 32 + (lane & 15), acol = k16 + ((lane >> 4) << 3);
            {
                uint32_t fh[2][4], fl[2][4];
#pragma unroll
                for (int ma = 0; ma < 2; ++ma) {
                    uint32_t off = (uint32_t)((arow + ma * 16) * FSA + acol) * 2;
                    ldm_x4(fh[ma], sb + oReH * 2 + off);
                    ldm_x4(fl[ma], sb + oReL * 2 + off);
                }
#pragma unroll
                for (int ma = 0; ma < 2; ++ma)
#pragma unroll
                    for (int na = 0; na < 4; ++na) {
                        MMA(accRe[ma][na], fh[ma], fbh[na]);
                        MMA(accRe[ma][na], fh[ma], fbl[na]);
                        MMA(accRe[ma][na], fl[ma], fbh[na]);
                    }
            }
            {
                uint32_t fh[2][4], fl[2][4];
#pragma unroll
                for (int ma = 0; ma < 2; ++ma) {
                    uint32_t off = (uint32_t)((arow + ma * 16) * FSA + acol) * 2;
                    ldm_x4(fh[ma], sb + oImH * 2 + off);
                    ldm_x4(fl[ma], sb + oImL * 2 + off);
                }
#pragma unroll
                for (int ma = 0; ma < 2; ++ma)
#pragma unroll
                    for (int na = 0; na < 4; ++na) {
                        MMA(accIm[ma][na], fh[ma], fbh[na]);
                        MMA(accIm[ma][na], fh[ma], fbl[na]);
                        MMA(accIm[ma][na], fl[ma], fbh[na]);
                    }
            }
        }
    }
#pragma unroll
    for (int ma = 0; ma < 2; ++ma) {
        int p = wm * 32 + ma * 16 + (lane >> 2);
#pragma unroll
        for (int na = 0; na < 4; ++na) {
            int d = d0 + wn * 32 + na * 8 + (lane & 3) * 2;
            size_t bi0 = ((size_t)b * NPIX + (p << 7) + s) * NC + d;
            g_Vt[bi0]     = make_float2(accRe[ma][na][0], accIm[ma][na][0]);
            g_Vt[bi0 + 1] = make_float2(accRe[ma][na][1], accIm[ma][na][1]);
            size_t bi8 = ((size_t)b * NPIX + ((p + 8) << 7) + s) * NC + d;
            g_Vt[bi8]     = make_float2(accRe[ma][na][2], accIm[ma][na][2]);
            g_Vt[bi8 + 1] = make_float2(accRe[ma][na][3], accIm[ma][na][3]);
        }
    }
}

// ------------------------- y = | Atil @ Vt |, written as bf16 split ----------
__global__ __launch_bounds__(256) void k_attnv() {
    int bh = blockIdx.y;
    int b = bh >> 3, h = bh & 7;
    int t0 = blockIdx.x * 1024;
    int tid = threadIdx.x;
    __shared__ float2 Amat[CH][33];
    __shared__ float2 Vsm[64][33];
    for (int idx = tid; idx < CH * CH; idx += 256)
        Amat[idx >> 5][idx & 31] = g_At[(size_t)bh * CH * CH + idx];
    int ty = tid >> 4, tx = tid & 15;
    for (int ck = 0; ck < 16; ++ck) {
        int tc = t0 + ck * 64;
        __syncthreads();
        for (int idx = tid; idx < 64 * CH; idx += 256) {
            int tt = idx >> 5, d = idx & 31;
            Vsm[tt][d] = g_Vt[((size_t)b * NPIX + tc + tt) * NC + h * CH + d];
        }
        __syncthreads();
        float accr[2][4] = {}, acci[2][4] = {};
        for (int d = 0; d < CH; ++d) {
            float2 a0 = Amat[ty * 2][d], a1 = Amat[ty * 2 + 1][d];
            float2 v[4];
#pragma unroll
            for (int q = 0; q < 4; ++q) v[q] = Vsm[tx + 16 * q][d];
#pragma unroll
            for (int q = 0; q < 4; ++q) {
                accr[0][q] += a0.x * v[q].x - a0.y * v[q].y;
                acci[0][q] += a0.x * v[q].y + a0.y * v[q].x;
                accr[1][q] += a1.x * v[q].x - a1.y * v[q].y;
                acci[1][q] += a1.x * v[q].y + a1.y * v[q].x;
            }
        }
        for (int i = 0; i < 2; ++i) {
            int cg = h * CH + ty * 2 + i;
            for (int q = 0; q < 4; ++q) {
                float re = accr[i][q], im = acci[i][q];
                float yv = sqrtf(re * re + im * im);
                size_t oidx = ((size_t)b * NC + cg) * NPIX + tc + tx + 16 * q;
                __nv_bfloat16 hh = __float2bfloat16_rn(yv);
                g_yh[oidx] = __bfloat16_as_ushort(hh);
                g_yl[oidx] = __bfloat16_as_ushort(__float2bfloat16_rn(yv - __bfloat162float(hh)));
            }
        }
    }
}

// ------------------------- launch --------------------------------------------
extern "C" void kernel_launch(void* const* d_in, const int* in_sizes, int n_in,
                              void* d_out, int out_size) {
    const float* x  = (const float*)d_in[0];
    const float* w1 = (const float*)d_in[1];
    const float* b1 = (const float*)d_in[2];
    const float* w2 = (const float*)d_in[3];
    const float* b2 = (const float*)d_in[4];
    const float* w3 = (const float*)d_in[5];
    const float* b3 = (const float*)d_in[6];
    const float* wo = (const float*)d_in[7];
    const float* bo = (const float*)d_in[8];
    const float* temp = (const float*)d_in[9];
    float* out = (float*)d_out;

    cudaFuncSetAttribute(k_gram_mma, cudaFuncAttributeMaxDynamicSharedMemorySize, GSMEM);
    cudaFuncSetAttribute(k_conv_mma, cudaFuncAttributeMaxDynamicSharedMemorySize, CSMEM);
    cudaFuncSetAttribute(k_fft_mma, cudaFuncAttributeMaxDynamicSharedMemorySize, FSMEM);

    k_dtab<<<128, 256>>>();
    k_dexp<<<8192, 256>>>();
    k_xsplit<<<NB * NC * NPIX / 4 / 256, 256>>>(x);
    k_wsplit<<<2 * NC * NC / 4 / 256, 256>>>(w3, wo);
    k_sum<<<NB * NC, 256>>>(x);
    k_gram_mma<<<dim3(3, NB, KSPLIT * 2), 256, GSMEM>>>();
    k_gred<<<(NB * 2 * NC * NC) / 256, 256>>>();
    k_mm256<<<dim3(16, NB, 3), 256>>>(w1, w2);
    k_attn<<<NB * NHEADS, 256>>>(w1, w2, b1, b2, temp);
    k_conv_mma<<<dim3(128, 2, NB), 256, CSMEM>>>(0, b3, nullptr, 0);
    k_fft_mma<<<dim3(128, 16), 256, FSMEM>>>();
    k_attnv<<<dim3(16, 32), 256>>>();
    k_conv_mma<<<dim3(128, 2, NB), 256, CSMEM>>>(1, bo, out, 1);
}

// round 13
// speedup vs baseline: 2.0706x; 1.0550x over previous
#include <cuda_runtime.h>
#include <cuda_bf16.h>
#include <math.h>
#include <stdint.h>

#define NB 4
#define NC 256
#define NPIX 16384
#define NHEADS 8
#define CH 32
#define KSPLIT 8

// ------------------------- scratch ------------------------------------------
__device__ float  g_S[NB * NC];
__device__ float  g_part[KSPLIT * NB * 2 * NC * NC];
__device__ float  g_C0[NB * NC * NC];
__device__ float  g_Cf[NB * NC * NC];
__device__ float  g_P[3 * NB * NC * NC];
__device__ float2 g_At[NB * NHEADS * CH * CH];
__device__ float2 g_Dtab[128 * 256];
// prepacked bf16 hi/lo splits
__device__ unsigned short g_xh[(size_t)NB * NC * NPIX];
__device__ unsigned short g_xl[(size_t)NB * NC * NPIX];
__device__ unsigned short g_vsh[(size_t)NB * NC * NPIX];
__device__ unsigned short g_vsl[(size_t)NB * NC * NPIX];
__device__ unsigned short g_wh[2 * NC * NC];
__device__ unsigned short g_wl[2 * NC * NC];
// y stored [b][t][c], each uint32 = bf16 hi | (bf16 lo << 16)
__device__ uint32_t g_y2[(size_t)NB * NPIX * NC];
// expanded Dirichlet matrices, [s][p][x], bf16 hi/lo, re/im
__device__ unsigned short g_DreH[128 * 128 * 128];
__device__ unsigned short g_DreL[128 * 128 * 128];
__device__ unsigned short g_DimH[128 * 128 * 128];
__device__ unsigned short g_DimL[128 * 128 * 128];

// ------------------------- mma.sync helpers ----------------------------------
__device__ __forceinline__ uint32_t smem_u32(const void* p) {
    uint32_t a;
    asm("{ .reg .u64 t; cvta.to.shared.u64 t, %1; cvt.u32.u64 %0, t; }" : "=r"(a) : "l"(p));
    return a;
}
__device__ __forceinline__ void MMA(float* d, const uint32_t* a, const uint32_t* b) {
    asm volatile("mma.sync.aligned.m16n8k16.row.col.f32.bf16.bf16.f32 "
        "{%0,%1,%2,%3}, {%4,%5,%6,%7}, {%8,%9}, {%0,%1,%2,%3};"
        : "+f"(d[0]), "+f"(d[1]), "+f"(d[2]), "+f"(d[3])
        : "r"(a[0]), "r"(a[1]), "r"(a[2]), "r"(a[3]), "r"(b[0]), "r"(b[1]));
}
__device__ __forceinline__ void ldm_x4(uint32_t* r, uint32_t a) {
    asm volatile("ldmatrix.sync.aligned.m8n8.x4.shared.b16 {%0,%1,%2,%3}, [%4];"
        : "=r"(r[0]), "=r"(r[1]), "=r"(r[2]), "=r"(r[3]) : "r"(a));
}
__device__ __forceinline__ void ldm_x2(uint32_t* r, uint32_t a) {
    asm volatile("ldmatrix.sync.aligned.m8n8.x2.shared.b16 {%0,%1}, [%2];"
        : "=r"(r[0]), "=r"(r[1]) : "r"(a));
}
__device__ __forceinline__ void ldm_x2t(uint32_t* r, uint32_t a) {
    asm volatile("ldmatrix.sync.aligned.m8n8.x2.trans.shared.b16 {%0,%1}, [%2];"
        : "=r"(r[0]), "=r"(r[1]) : "r"(a));
}
__device__ __forceinline__ void split_pack(float4 v, uint2& hi, uint2& lo) {
    __nv_bfloat16 h0 = __float2bfloat16_rn(v.x), h1 = __float2bfloat16_rn(v.y);
    __nv_bfloat16 h2 = __float2bfloat16_rn(v.z), h3 = __float2bfloat16_rn(v.w);
    __nv_bfloat16 l0 = __float2bfloat16_rn(v.x - __bfloat162float(h0));
    __nv_bfloat16 l1 = __float2bfloat16_rn(v.y - __bfloat162float(h1));
    __nv_bfloat16 l2 = __float2bfloat16_rn(v.z - __bfloat162float(h2));
    __nv_bfloat16 l3 = __float2bfloat16_rn(v.w - __bfloat162float(h3));
    hi.x = (uint32_t)__bfloat16_as_ushort(h0) | ((uint32_t)__bfloat16_as_ushort(h1) << 16);
    hi.y = (uint32_t)__bfloat16_as_ushort(h2) | ((uint32_t)__bfloat16_as_ushort(h3) << 16);
    lo.x = (uint32_t)__bfloat16_as_ushort(l0) | ((uint32_t)__bfloat16_as_ushort(l1) << 16);
    lo.y = (uint32_t)__bfloat16_as_ushort(l2) | ((uint32_t)__bfloat16_as_ushort(l3) << 16);
}
__device__ __forceinline__ uint32_t pack_hl(float y) {
    __nv_bfloat16 h = __float2bfloat16_rn(y);
    __nv_bfloat16 l = __float2bfloat16_rn(y - __bfloat162float(h));
    return (uint32_t)__bfloat16_as_ushort(h) | ((uint32_t)__bfloat16_as_ushort(l) << 16);
}
__device__ __forceinline__ void pack2(float a, float b, uint32_t& hi, uint32_t& lo) {
    __nv_bfloat16 ha = __float2bfloat16_rn(a), hb = __float2bfloat16_rn(b);
    __nv_bfloat16 la = __float2bfloat16_rn(a - __bfloat162float(ha));
    __nv_bfloat16 lb = __float2bfloat16_rn(b - __bfloat162float(hb));
    hi = (uint32_t)__bfloat16_as_ushort(ha) | ((uint32_t)__bfloat16_as_ushort(hb) << 16);
    lo = (uint32_t)__bfloat16_as_ushort(la) | ((uint32_t)__bfloat16_as_ushort(lb) << 16);
}

// ------------------------- fused sum + x split -------------------------------
__global__ __launch_bounds__(256) void k_sumsplit(const float* __restrict__ x) {
    int bc = blockIdx.x;
    const float4* p = (const float4*)(x + (size_t)bc * NPIX);
    uint2* Xh = (uint2*)g_xh + (size_t)bc * 4096;
    uint2* Xl = (uint2*)g_xl + (size_t)bc * 4096;
    float s = 0.f;
    for (int q = 0; q < 16; ++q) {
        int idx = threadIdx.x + q * 256;
        float4 v = p[idx];
        uint2 hi, lo;
        split_pack(v, hi, lo);
        Xh[idx] = hi; Xl[idx] = lo;
        s += (v.x + v.y) + (v.z + v.w);
    }
    __shared__ float sm[256];
    sm[threadIdx.x] = s; __syncthreads();
    for (int w = 128; w > 0; w >>= 1) {
        if (threadIdx.x < w) sm[threadIdx.x] += sm[threadIdx.x + w];
        __syncthreads();
    }
    if (threadIdx.x == 0) g_S[bc] = sm[0];
}
__global__ __launch_bounds__(256) void k_wsplit(const float* __restrict__ w3,
                                                const float* __restrict__ wo) {
    int gid = blockIdx.x * 256 + threadIdx.x;
    int per = NC * NC / 4;
    int m = gid / per, e = gid % per;
    const float* src = (m == 0 ? w3 : wo);
    float4 v = ((const float4*)src)[e];
    uint2 hi, lo;
    split_pack(v, hi, lo);
    ((uint2*)g_wh)[gid] = hi;
    ((uint2*)g_wl)[gid] = lo;
}

// ------------------------- Gram via mma.sync (symmetric: 3 tiles) ------------
#define GSA 40
#define GTILE (128 * GSA)
#define GBUF (4 * GTILE)
#define GSMEM (2 * GBUF * 2)
__global__ __launch_bounds__(256, 1) void k_gram_mma() {
    extern __shared__ __align__(16) __nv_bfloat16 smg[];
    int tid = threadIdx.x, wid = tid >> 5, lane = tid & 31;
    int tile = blockIdx.x;
    int i0 = (tile == 2) ? 128 : 0;
    int j0 = (tile == 0) ? 0 : 128;
    int b = blockIdx.y, ks = blockIdx.z >> 1, mode = blockIdx.z & 1;
    const unsigned short* Xh = g_xh + (size_t)b * NC * NPIX;
    const unsigned short* Xl = g_xl + (size_t)b * NC * NPIX;
    int wm = wid >> 2, wn = wid & 3;
    float acc[4][4][4] = {};
    uint2 pAh[4], pAl[4], pBh[4], pBl[4];

    auto LD = [&](int ch) {
        int Kc = ks * 2048 + ch * 32;
#pragma unroll
        for (int q = 0; q < 4; ++q) {
            int f = tid + q * 256, r = f >> 3, c = (f & 7) * 4;
            size_t off = (size_t)(i0 + r) * NPIX + Kc + c;
            pAh[q] = *(const uint2*)(Xh + off);
            pAl[q] = *(const uint2*)(Xl + off);
        }
        if (mode == 0) {
#pragma unroll
            for (int q = 0; q < 4; ++q) {
                int f = tid + q * 256, r = f >> 3, c = (f & 7) * 4;
                size_t off = (size_t)(j0 + r) * NPIX + Kc + c;
                pBh[q] = *(const uint2*)(Xh + off);
                pBl[q] = *(const uint2*)(Xl + off);
            }
        } else {
            int fy = (128 - (Kc >> 7)) & 127, xc0 = Kc & 127;
#pragma unroll
            for (int q = 0; q < 4; ++q) {
                int f = tid + q * 256, r = f >> 3;
                int x0 = xc0 + (f & 7) * 4;
                size_t ro = (size_t)(j0 + r) * NPIX + fy * 128;
                int c0 = (128 - x0) & 127, c1 = 127 - x0, c2 = 126 - x0, c3 = 125 - x0;
                pBh[q].x = (uint32_t)Xh[ro + c0] | ((uint32_t)Xh[ro + c1] << 16);
                pBh[q].y = (uint32_t)Xh[ro + c2] | ((uint32_t)Xh[ro + c3] << 16);
                pBl[q].x = (uint32_t)Xl[ro + c0] | ((uint32_t)Xl[ro + c1] << 16);
                pBl[q].y = (uint32_t)Xl[ro + c2] | ((uint32_t)Xl[ro + c3] << 16);
            }
        }
    };
    auto ST = [&](int buf) {
        __nv_bfloat16* Ah = smg + buf * GBUF;
        __nv_bfloat16* Al = Ah + GTILE;
        __nv_bfloat16* Bh = Ah + 2 * GTILE;
        __nv_bfloat16* Bl = Ah + 3 * GTILE;
#pragma unroll
        for (int q = 0; q < 4; ++q) {
            int f = tid + q * 256, r = f >> 3, c = (f & 7) * 4;
            *(uint2*)(Ah + r * GSA + c) = pAh[q];
            *(uint2*)(Al + r * GSA + c) = pAl[q];
            *(uint2*)(Bh + r * GSA + c) = pBh[q];
            *(uint2*)(Bl + r * GSA + c) = pBl[q];
        }
    };

    LD(0);
    for (int ch = 0; ch < 64; ++ch) {
        int buf = ch & 1;
        ST(buf);
        __syncthreads();
        if (ch < 63) LD(ch + 1);
        uint32_t sb = smem_u32(smg + buf * GBUF);
        uint32_t aH = sb, aL = sb + GTILE * 2, bH = sb + 4 * GTILE, bL = sb + 6 * GTILE;
#pragma unroll
        for (int k16 = 0; k16 < 32; k16 += 16) {
            uint32_t fah[4][4], fal[4][4], fbh[4][2], fbl[4][2];
            int arow = wm * 64 + (lane & 15), acol = k16 + ((lane >> 4) << 3);
#pragma unroll
            for (int ma = 0; ma < 4; ++ma) {
                uint32_t off = (uint32_t)((arow + ma * 16) * GSA + acol) * 2;
                ldm_x4(fah[ma], aH + off);
                ldm_x4(fal[ma], aL + off);
            }
            int brow = wn * 32 + (lane & 7), bcol = k16 + (lane & 8);
#pragma unroll
            for (int na = 0; na < 4; ++na) {
                uint32_t off = (uint32_t)((brow + na * 8) * GSA + bcol) * 2;
                ldm_x2(fbh[na], bH + off);
                ldm_x2(fbl[na], bL + off);
            }
#pragma unroll
            for (int ma = 0; ma < 4; ++ma)
#pragma unroll
                for (int na = 0; na < 4; ++na) {
                    MMA(acc[ma][na], fah[ma], fbh[na]);
                    MMA(acc[ma][na], fah[ma], fbl[na]);
                    MMA(acc[ma][na], fal[ma], fbh[na]);
                }
        }
        __syncthreads();
    }
    float* P = g_part + (((size_t)ks * NB + b) * 2 + mode) * (NC * NC);
#pragma unroll
    for (int ma = 0; ma < 4; ++ma)
#pragma unroll
        for (int na = 0; na < 4; ++na) {
            int r = i0 + wm * 64 + ma * 16 + (lane >> 2);
            int c = j0 + wn * 32 + na * 8 + (lane & 3) * 2;
            float2 v0 = make_float2(acc[ma][na][0], acc[ma][na][1]);
            float2 v1 = make_float2(acc[ma][na][2], acc[ma][na][3]);
            *(float2*)&P[(size_t)r * NC + c] = v0;
            *(float2*)&P[(size_t)(r + 8) * NC + c] = v1;
        }
}

__global__ __launch_bounds__(256) void k_gred() {
    int gid = blockIdx.x * 256 + threadIdx.x;
    if (gid >= NB * 2 * NC * NC) return;
    int e = gid % (NC * NC);
    int bm = gid / (NC * NC);
    int m = bm & 1, b = bm >> 1;
    int r = e / NC, c = e % NC;
    int esrc = (r >= 128 && c < 128) ? (c * NC + r) : e;
    float s = 0.f;
    for (int ks = 0; ks < KSPLIT; ++ks)
        s += g_part[(((size_t)ks * NB + b) * 2 + m) * (NC * NC) + esrc];
    (m == 0 ? g_C0 : g_Cf)[b * (NC * NC) + e] = s;
}

// ------------------------- 1x1 conv via mma.sync -----------------------------
// mode0: B = x split [k][t] (trans ldmatrix), O = vs split
// mode1: B = g_y2 [t][c] packed (non-trans ldmatrix), O = out fp32
#define CSA 40
#define CATILE (128 * CSA)
#define CBT 5120
#define CSB0 136
#define CBUFE (2 * CATILE + 2 * CBT)
#define CSMEM (2 * CBUFE * 2)
__global__ __launch_bounds__(256, 1) void k_conv_mma(int widx,
                                                     const float* __restrict__ bias,
                                                     float* __restrict__ Oout,
                                                     int mode) {
    extern __shared__ __align__(16) __nv_bfloat16 smc[];
    int tid = threadIdx.x, wid = tid >> 5, lane = tid & 31;
    int t0 = blockIdx.x * 128, o0 = blockIdx.y * 128, b = blockIdx.z;
    const unsigned short* Wh = g_wh + (size_t)widx * NC * NC;
    const unsigned short* Wl = g_wl + (size_t)widx * NC * NC;
    const unsigned short* Bxh = g_xh + (size_t)b * NC * NPIX;
    const unsigned short* Bxl = g_xl + (size_t)b * NC * NPIX;
    const uint32_t* Ybuf = g_y2 + (size_t)b * NPIX * NC;
    int wm = wid >> 2, wn = wid & 3;
    float acc[4][4][4] = {};
    uint2 pAh[4], pAl[4], pBh[4], pBl[4];
    uint32_t pY[16];

    auto LD = [&](int ch) {
        int k0 = ch * 32;
#pragma unroll
        for (int q = 0; q < 4; ++q) {
            int f = tid + q * 256, r = f >> 3, c = (f & 7) * 4;
            size_t off = (size_t)(o0 + r) * NC + k0 + c;
            pAh[q] = *(const uint2*)(Wh + off);
            pAl[q] = *(const uint2*)(Wl + off);
        }
        if (mode == 0) {
#pragma unroll
            for (int q = 0; q < 4; ++q) {
                int f = tid + q * 256, k = f >> 5, t = (f & 31) * 4;
                size_t off = (size_t)(k0 + k) * NPIX + t0 + t;
                pBh[q] = *(const uint2*)(Bxh + off);
                pBl[q] = *(const uint2*)(Bxl + off);
            }
        } else {
#pragma unroll
            for (int q = 0; q < 16; ++q) {
                int f = tid + q * 256, t = f >> 5, k = f & 31;
                pY[q] = Ybuf[(size_t)(t0 + t) * NC + k0 + k];
            }
        }
    };
    auto ST = [&](int buf) {
        __nv_bfloat16* Ah = smc + buf * CBUFE;
        __nv_bfloat16* Al = Ah + CATILE;
        unsigned short* Bh = (unsigned short*)(Ah + 2 * CATILE);
        unsigned short* Bl = Bh + CBT;
#pragma unroll
        for (int q = 0; q < 4; ++q) {
            int f = tid + q * 256, r = f >> 3, c = (f & 7) * 4;
            *(uint2*)(Ah + r * CSA + c) = pAh[q];
            *(uint2*)(Al + r * CSA + c) = pAl[q];
        }
        if (mode == 0) {
#pragma unroll
            for (int q = 0; q < 4; ++q) {
                int f = tid + q * 256, k = f >> 5, t = (f & 31) * 4;
                *(uint2*)(Bh + k * CSB0 + t) = pBh[q];
                *(uint2*)(Bl + k * CSB0 + t) = pBl[q];
            }
        } else {
#pragma unroll
            for (int q = 0; q < 16; ++q) {
                int f = tid + q * 256, t = f >> 5, k = f & 31;
                uint32_t v = pY[q];
                Bh[t * 40 + k] = (unsigned short)(v & 0xFFFF);
                Bl[t * 40 + k] = (unsigned short)(v >> 16);
            }
        }
    };

    LD(0);
    for (int ch = 0; ch < 8; ++ch) {
        int buf = ch & 1;
        ST(buf);
        __syncthreads();
        if (ch < 7) LD(ch + 1);
        uint32_t sb = smem_u32(smc + buf * CBUFE);
        uint32_t aH = sb, aL = sb + CATILE * 2, bH = sb + 4 * CATILE, bL = bH + CBT * 2;
#pragma unroll
        for (int k16 = 0; k16 < 32; k16 += 16) {
            uint32_t fah[4][4], fal[4][4], fbh[4][2], fbl[4][2];
            int arow = wm * 64 + (lane & 15), acol = k16 + ((lane >> 4) << 3);
#pragma unroll
            for (int ma = 0; ma < 4; ++ma) {
                uint32_t off = (uint32_t)((arow + ma * 16) * CSA + acol) * 2;
                ldm_x4(fah[ma], aH + off);
                ldm_x4(fal[ma], aL + off);
            }
            if (mode == 0) {
                int krow = k16 + (lane & 15);
#pragma unroll
                for (int na = 0; na < 4; ++na) {
                    uint32_t off = (uint32_t)(krow * CSB0 + wn * 32 + na * 8) * 2;
                    ldm_x2t(fbh[na], bH + off);
                    ldm_x2t(fbl[na], bL + off);
                }
            } else {
                int brow = wn * 32 + (lane & 7), bcol = k16 + (lane & 8);
#pragma unroll
                for (int na = 0; na < 4; ++na) {
                    uint32_t off = (uint32_t)((brow + na * 8) * 40 + bcol) * 2;
                    ldm_x2(fbh[na], bH + off);
                    ldm_x2(fbl[na], bL + off);
                }
            }
#pragma unroll
            for (int ma = 0; ma < 4; ++ma)
#pragma unroll
                for (int na = 0; na < 4; ++na) {
                    MMA(acc[ma][na], fah[ma], fbh[na]);
                    MMA(acc[ma][na], fah[ma], fbl[na]);
                    MMA(acc[ma][na], fal[ma], fbh[na]);
                }
        }
        __syncthreads();
    }
#pragma unroll
    for (int ma = 0; ma < 4; ++ma) {
        int r = o0 + wm * 64 + ma * 16 + (lane >> 2);
        float b0v = bias[r], b1v = bias[r + 8];
#pragma unroll
        for (int na = 0; na < 4; ++na) {
            int c = t0 + wn * 32 + na * 8 + (lane & 3) * 2;
            if (mode == 0) {
                uint32_t h0, l0, h1, l1;
                pack2(acc[ma][na][0] + b0v, acc[ma][na][1] + b0v, h0, l0);
                pack2(acc[ma][na][2] + b1v, acc[ma][na][3] + b1v, h1, l1);
                size_t i0v = (size_t)(b * NC + r) * NPIX + c;
                *(uint32_t*)(g_vsh + i0v) = h0;
                *(uint32_t*)(g_vsl + i0v) = l0;
                size_t i1v = i0v + (size_t)8 * NPIX;
                *(uint32_t*)(g_vsh + i1v) = h1;
                *(uint32_t*)(g_vsl + i1v) = l1;
            } else {
                float* O = Oout + (size_t)b * NC * NPIX;
                float2 v0 = make_float2(acc[ma][na][0] + b0v, acc[ma][na][1] + b0v);
                float2 v1 = make_float2(acc[ma][na][2] + b1v, acc[ma][na][3] + b1v);
                *(float2*)&O[(size_t)r * NPIX + c] = v0;
                *(float2*)&O[(size_t)(r + 8) * NPIX + c] = v1;
            }
        }
    }
}

// ------------------------- P matrices: A @ W^T (FFMA) ------------------------
__global__ __launch_bounds__(256) void k_mm256(const float* __restrict__ w1,
                                               const float* __restrict__ w2) {
    int tile = blockIdx.x, b = blockIdx.y, z = blockIdx.z;
    const float* A = (z == 0 ? g_Cf : g_C0) + (size_t)b * NC * NC;
    const float* W = (z == 1 ? w1 : w2);
    float* P = g_P + ((size_t)z * NB + b) * NC * NC;
    int i0 = (tile >> 2) * 64, j0 = (tile & 3) * 64;
    __shared__ float As[64][33], Bs[64][33];
    float acc[4][4] = {};
    int ty = threadIdx.x >> 4, tx = threadIdx.x & 15;
    for (int kb = 0; kb < NC; kb += 32) {
        for (int idx = threadIdx.x; idx < 64 * 32; idx += 256) {
            int r = idx >> 5, c = idx & 31;
            As[r][c] = A[(i0 + r) * NC + kb + c];
            Bs[r][c] = W[(j0 + r) * NC + kb + c];
        }
        __syncthreads();
#pragma unroll
        for (int kk = 0; kk < 32; ++kk) {
            float a[4], bv[4];
#pragma unroll
            for (int ii = 0; ii < 4; ++ii) a[ii] = As[ty + 16 * ii][kk];
#pragma unroll
            for (int jj = 0; jj < 4; ++jj) bv[jj] = Bs[tx + 16 * jj][kk];
#pragma unroll
            for (int ii = 0; ii < 4; ++ii)
#pragma unroll
                for (int jj = 0; jj < 4; ++jj) acc[ii][jj] += a[ii] * bv[jj];
        }
        __syncthreads();
    }
    for (int ii = 0; ii < 4; ++ii)
        for (int jj = 0; jj < 4; ++jj)
            P[(i0 + ty + 16 * ii) * NC + j0 + tx + 16 * jj] = acc[ii][jj];
}

// ------------------------- attn -> softmax -> ifft_c -------------------------
__global__ __launch_bounds__(256) void k_attn(const float* __restrict__ w1,
                                              const float* __restrict__ w2,
                                              const float* __restrict__ b1,
                                              const float* __restrict__ b2,
                                              const float* __restrict__ temp) {
    int b = blockIdx.x >> 3, h = blockIdx.x & 7;
    int tid = threadIdx.x;
    __shared__ float Ps[NC][33];
    __shared__ float numS[CH][33];
    __shared__ float redA[CH][8], redB[CH][8];
    __shared__ float qn[CH], kn[CH], w1s[CH], w2s[CH];
    const float* P1 = g_P + ((size_t)0 * NB + b) * NC * NC;
    const float* P2 = g_P + ((size_t)1 * NB + b) * NC * NC;
    const float* P3 = g_P + ((size_t)2 * NB + b) * NC * NC;
    const float* Sb = g_S + b * NC;

    for (int idx = tid; idx < NC * CH; idx += 256)
        Ps[idx >> 5][idx & 31] = P1[(size_t)(idx >> 5) * NC + h * CH + (idx & 31)];
    __syncthreads();
    {
        int c = tid >> 3, dg = tid & 7;
        float acc[4] = {0.f, 0.f, 0.f, 0.f};
        const float* wrow = w1 + (size_t)(h * CH + c) * NC;
        for (int j = 0; j < NC; ++j) {
            float w = wrow[j];
#pragma unroll
            for (int q = 0; q < 4; ++q) acc[q] += w * Ps[j][dg + 8 * q];
        }
#pragma unroll
        for (int q = 0; q < 4; ++q) numS[c][dg + 8 * q] = acc[q];
    }
    __syncthreads();

    for (int idx = tid; idx < NC * CH; idx += 256)
        Ps[idx >> 5][idx & 31] = P2[(size_t)(idx >> 5) * NC + h * CH + (idx & 31)];
    __syncthreads();
    {
        int c = tid >> 3, g = tid & 7;
        const float* wrow = w1 + (size_t)(h * CH + c) * NC;
        float pa = 0.f, pb = 0.f;
        for (int j = g * 32; j < g * 32 + 32; ++j) {
            float w = wrow[j];
            pa += w * Ps[j][c];
            pb += w * Sb[j];
        }
        redA[c][g] = pa; redB[c][g] = pb;
    }
    __syncthreads();
    if (tid < CH) {
        float a = 0.f, bb = 0.f;
        for (int g = 0; g < 8; ++g) { a += redA[tid][g]; bb += redB[tid][g]; }
        float b1c = b1[h * CH + tid];
        w1s[tid] = bb;
        qn[tid] = fmaxf(sqrtf(fmaxf(a + 2.f * b1c * bb + 16384.f * b1c * b1c, 0.f)), 1e-12f);
    }
    __syncthreads();

    for (int idx = tid; idx < NC * CH; idx += 256)
        Ps[idx >> 5][idx & 31] = P3[(size_t)(idx >> 5) * NC + h * CH + (idx & 31)];
    __syncthreads();
    {
        int c = tid >> 3, g = tid & 7;
        const float* wrow = w2 + (size_t)(h * CH + c) * NC;
        float pa = 0.f, pb = 0.f;
        for (int j = g * 32; j < g * 32 + 32; ++j) {
            float w = wrow[j];
            pa += w * Ps[j][c];
            pb += w * Sb[j];
        }
        redA[c][g] = pa; redB[c][g] = pb;
    }
    __syncthreads();
    if (tid < CH) {
        float a = 0.f, bb = 0.f;
        for (int g = 0; g < 8; ++g) { a += redA[tid][g]; bb += redB[tid][g]; }
        float b2d = b2[h * CH + tid];
        w2s[tid] = bb;
        kn[tid] = fmaxf(sqrtf(fmaxf(a + 2.f * b2d * bb + 16384.f * b2d * b2d, 0.f)), 1e-12f);
    }
    __syncthreads();

    {
        float tH = temp[h];
        for (int idx = tid; idx < CH * CH; idx += 256) {
            int c = idx >> 5, d = idx & 31;
            float b1c = b1[h * CH + c], b2d = b2[h * CH + d];
            float numF = numS[c][d] + b1c * w2s[d] + b2d * w1s[c] + 16384.f * b1c * b2d;
            numS[c][d] = tH * numF / (qn[c] * kn[d]);
        }
    }
    __syncthreads();

    if (tid < CH) {
        float mx = -1e30f;
        for (int d = 0; d < CH; ++d) mx = fmaxf(mx, numS[tid][d]);
        float s = 0.f;
        for (int d = 0; d < CH; ++d) { float e = expf(numS[tid][d] - mx); numS[tid][d] = e; s += e; }
        float inv = 1.f / s;
        for (int d = 0; d < CH; ++d) numS[tid][d] *= inv;
    }
    __syncthreads();

    for (int idx = tid; idx < CH * CH; idx += 256) {
        int cp = idx >> 5, d = idx & 31;
        float re = 0.f, im = 0.f;
        for (int c = 0; c < CH; ++c) {
            int ph = (c * cp) & 31;
            float sv, cv;
            sincosf(0.19634954084936207f * (float)ph, &sv, &cv);
            float a = numS[c][d];
            re += a * cv; im += a * sv;
        }
        re *= 0.03125f; im *= 0.03125f;
        if (cp == 0) im += 0.03125f;
        g_At[((size_t)blockIdx.x * CH + cp) * CH + d] = make_float2(re, im);
    }
}

// ------------------------- Dirichlet table + bf16 expansion ------------------
__global__ __launch_bounds__(256) void k_dtab() {
    int i = blockIdx.x * 256 + threadIdx.x;
    if (i >= 128 * 255) return;
    int s = i / 255, mi = i % 255, m = mi - 127;
    float2 v;
    if (s == 0) {
        v = make_float2(m == 0 ? 1.f : 0.f, 0.f);
    } else {
        double f = (double)s / 128.0;
        double al = (double)m + f;
        double mag = sinpi(f) / (128.0 * sinpi(al / 128.0));
        if (m & 1) mag = -mag;
        double ph = al * (127.0 / 128.0);
        v = make_float2((float)(cospi(ph) * mag), (float)(sinpi(ph) * mag));
    }
    g_Dtab[s * 256 + mi] = v;
}
__global__ __launch_bounds__(256) void k_dexp() {
    int gid = blockIdx.x * 256 + threadIdx.x;
    int x = gid & 127, p = (gid >> 7) & 127, s = gid >> 14;
    float2 v = g_Dtab[s * 256 + (p - x + 127)];
    __nv_bfloat16 hr = __float2bfloat16_rn(v.x);
    __nv_bfloat16 hi = __float2bfloat16_rn(v.y);
    g_DreH[gid] = __bfloat16_as_ushort(hr);
    g_DreL[gid] = __bfloat16_as_ushort(__float2bfloat16_rn(v.x - __bfloat162float(hr)));
    g_DimH[gid] = __bfloat16_as_ushort(hi);
    g_DimL[gid] = __bfloat16_as_ushort(__float2bfloat16_rn(v.y - __bfloat162float(hi)));
}

// ------------------------- fused Dirichlet transform + channel attn ----------
// Per CTA (s, b, dblk): Vt[128p][64d] via mma, then y = |Atil @ Vt| for the
// 2 heads in this d-block, written to g_y2 [t][c] packed.
#define FSA 40
#define FGEMM 51200
#define FEPI (66560 + 2 * 2112 * 4)
#define FSMEM (FEPI > FGEMM ? FEPI : FGEMM)
__global__ __launch_bounds__(256, 1) void k_fft_fused() {
    extern __shared__ __align__(16) char smf[];
    __nv_bfloat16* smb = (__nv_bfloat16*)smf;
    int tid = threadIdx.x, wid = tid >> 5, lane = tid & 31;
    int s = blockIdx.x;
    int b = blockIdx.y >> 2, dblk = blockIdx.y & 3;
    int d0 = dblk * 64;
    int wm = wid >> 1, wn = wid & 1;
    float accRe[2][4][4] = {}, accIm[2][4][4] = {};
    const uint32_t sb = smem_u32(smf);
    const uint32_t oReH = 0, oReL = 5120, oImH = 10240, oImL = 15360, oBH = 20480, oBL = 23040;

    for (int kc = 0; kc < 128; kc += 32) {
        __syncthreads();
#pragma unroll
        for (int q = 0; q < 4; ++q) {
            int f = tid + q * 256, r = f >> 3, c = (f & 7) * 4;
            size_t so = (size_t)s * 16384 + r * 128 + kc + c;
            uint32_t dofs = r * FSA + c;
            *(uint2*)(smb + oReH + dofs) = *(const uint2*)(g_DreH + so);
            *(uint2*)(smb + oReL + dofs) = *(const uint2*)(g_DreL + so);
            *(uint2*)(smb + oImH + dofs) = *(const uint2*)(g_DimH + so);
            *(uint2*)(smb + oImL + dofs) = *(const uint2*)(g_DimL + so);
        }
#pragma unroll
        for (int q = 0; q < 2; ++q) {
            int f = tid + q * 256, r = f >> 3, c = (f & 7) * 4;
            size_t so = (size_t)(b * NC + d0 + r) * NPIX + s * 128 + kc + c;
            uint32_t dofs = r * FSA + c;
            *(uint2*)(smb + oBH + dofs) = *(const uint2*)(g_vsh + so);
            *(uint2*)(smb + oBL + dofs) = *(const uint2*)(g_vsl + so);
        }
        __syncthreads();
#pragma unroll
        for (int k16 = 0; k16 < 32; k16 += 16) {
            uint32_t fbh[4][2], fbl[4][2];
            int brow = wn * 32 + (lane & 7), bcol = k16 + (lane & 8);
#pragma unroll
            for (int na = 0; na < 4; ++na) {
                uint32_t off = (uint32_t)((brow + na * 8) * FSA + bcol) * 2;
                ldm_x2(fbh[na], sb + oBH * 2 + off);
                ldm_x2(fbl[na], sb + oBL * 2 + off);
            }
            int arow = wm * 32 + (lane & 15), acol = k16 + ((lane >> 4) << 3);
            {
                uint32_t fh[2][4], fl[2][4];
#pragma unroll
                for (int ma = 0; ma < 2; ++ma) {
                    uint32_t off = (uint32_t)((arow + ma * 16) * FSA + acol) * 2;
                    ldm_x4(fh[ma], sb + oReH * 2 + off);
                    ldm_x4(fl[ma], sb + oReL * 2 + off);
                }
#pragma unroll
                for (int ma = 0; ma < 2; ++ma)
#pragma unroll
                    for (int na = 0; na < 4; ++na) {
                        MMA(accRe[ma][na], fh[ma], fbh[na]);
                        MMA(accRe[ma][na], fh[ma], fbl[na]);
                        MMA(accRe[ma][na], fl[ma], fbh[na]);
                    }
            }
            {
                uint32_t fh[2][4], fl[2][4];
#pragma unroll
                for (int ma = 0; ma < 2; ++ma) {
                    uint32_t off = (uint32_t)((arow + ma * 16) * FSA + acol) * 2;
                    ldm_x4(fh[ma], sb + oImH * 2 + off);
                    ldm_x4(fl[ma], sb + oImL * 2 + off);
                }
#pragma unroll
                for (int ma = 0; ma < 2; ++ma)
#pragma unroll
                    for (int na = 0; na < 4; ++na) {
                        MMA(accIm[ma][na], fh[ma], fbh[na]);
                        MMA(accIm[ma][na], fh[ma], fbl[na]);
                        MMA(accIm[ma][na], fl[ma], fbh[na]);
                    }
            }
        }
    }
    // ---- epilogue: stash Vt tile in smem, apply per-head Atil, write y2 ----
    __syncthreads();
    float2* VtS = (float2*)smf;                       // [128][65]
    float* Are = (float*)(smf + 66560);               // [2][32][33]
    float* Aim = Are + 2112;
#pragma unroll
    for (int ma = 0; ma < 2; ++ma)
#pragma unroll
        for (int na = 0; na < 4; ++na) {
            int p = wm * 32 + ma * 16 + (lane >> 2);
            int d = wn * 32 + na * 8 + (lane & 3) * 2;
            VtS[p * 65 + d]     = make_float2(accRe[ma][na][0], accIm[ma][na][0]);
            VtS[p * 65 + d + 1] = make_float2(accRe[ma][na][1], accIm[ma][na][1]);
            VtS[(p + 8) * 65 + d]     = make_float2(accRe[ma][na][2], accIm[ma][na][2]);
            VtS[(p + 8) * 65 + d + 1] = make_float2(accRe[ma][na][3], accIm[ma][na][3]);
        }
    int h0 = dblk * 2;
    for (int idx = tid; idx < 2048; idx += 256) {
        int hh = idx >> 10, rest = idx & 1023, c = rest >> 5, d = rest & 31;
        float2 a = g_At[(size_t)(b * NHEADS + h0 + hh) * 1024 + c * 32 + d];
        Are[(hh * 32 + c) * 33 + d] = a.x;
        Aim[(hh * 32 + c) * 33 + d] = a.y;
    }
    __syncthreads();
    int pg = tid >> 5, cg = tid & 31;
    int head = cg >> 4, cl0 = (2 * cg) & 31;
    const float* ArH = Are + head * 1056;
    const float* AiH = Aim + head * 1056;
    float accr[2][16] = {}, acci[2][16] = {};
    for (int d = 0; d < 32; ++d) {
        float a0r = ArH[cl0 * 33 + d],       a0i = AiH[cl0 * 33 + d];
        float a1r = ArH[(cl0 + 1) * 33 + d], a1i = AiH[(cl0 + 1) * 33 + d];
        int dv = head * 32 + d;
#pragma unroll
        for (int i = 0; i < 16; ++i) {
            float2 v = VtS[(pg * 16 + i) * 65 + dv];
            accr[0][i] += a0r * v.x - a0i * v.y;
            acci[0][i] += a0r * v.y + a0i * v.x;
            accr[1][i] += a1r * v.x - a1i * v.y;
            acci[1][i] += a1r * v.y + a1i * v.x;
        }
    }
    uint32_t* Y = g_y2 + (size_t)b * NPIX * NC;
#pragma unroll
    for (int i = 0; i < 16; ++i) {
        int p = pg * 16 + i;
        int t = (p << 7) + s;
        float y0 = sqrtf(accr[0][i] * accr[0][i] + acci[0][i] * acci[0][i]);
        float y1 = sqrtf(accr[1][i] * accr[1][i] + acci[1][i] * acci[1][i]);
        uint2 w;
        w.x = pack_hl(y0);
        w.y = pack_hl(y1);
        *(uint2*)&Y[(size_t)t * NC + d0 + 2 * cg] = w;
    }
}

// ------------------------- launch --------------------------------------------
extern "C" void kernel_launch(void* const* d_in, const int* in_sizes, int n_in,
                              void* d_out, int out_size) {
    const float* x  = (const float*)d_in[0];
    const float* w1 = (const float*)d_in[1];
    const float* b1 = (const float*)d_in[2];
    const float* w2 = (const float*)d_in[3];
    const float* b2 = (const float*)d_in[4];
    const float* w3 = (const float*)d_in[5];
    const float* b3 = (const float*)d_in[6];
    const float* wo = (const float*)d_in[7];
    const float* bo = (const float*)d_in[8];
    const float* temp = (const float*)d_in[9];
    float* out = (float*)d_out;

    cudaFuncSetAttribute(k_gram_mma, cudaFuncAttributeMaxDynamicSharedMemorySize, GSMEM);
    cudaFuncSetAttribute(k_conv_mma, cudaFuncAttributeMaxDynamicSharedMemorySize, CSMEM);
    cudaFuncSetAttribute(k_fft_fused, cudaFuncAttributeMaxDynamicSharedMemorySize, FSMEM);

    k_dtab<<<128, 256>>>();
    k_dexp<<<8192, 256>>>();
    k_wsplit<<<2 * NC * NC / 4 / 256, 256>>>(w3, wo);
    k_sumsplit<<<NB * NC, 256>>>(x);
    k_gram_mma<<<dim3(3, NB, KSPLIT * 2), 256, GSMEM>>>();
    k_gred<<<(NB * 2 * NC * NC) / 256, 256>>>();
    k_mm256<<<dim3(16, NB, 3), 256>>>(w1, w2);
    k_attn<<<NB * NHEADS, 256>>>(w1, w2, b1, b2, temp);
    k_conv_mma<<<dim3(128, 2, NB), 256, CSMEM>>>(0, b3, nullptr, 0);
    k_fft_fused<<<dim3(128, 16), 256, FSMEM>>>();
    k_conv_mma<<<dim3(128, 2, NB), 256, CSMEM>>>(1, bo, out, 1);
}

// round 15
// speedup vs baseline: 2.3500x; 1.1349x over previous
#include <cuda_runtime.h>
#include <cuda_bf16.h>
#include <math.h>
#include <stdint.h>

#define NB 4
#define NC 256
#define NPIX 16384
#define NHEADS 8
#define CH 32
#define KSPLIT 8

// ------------------------- scratch ------------------------------------------
__device__ float  g_S[NB * NC];
__device__ float  g_part[KSPLIT * NB * 2 * NC * NC];
__device__ float  g_C0[NB * NC * NC];
__device__ float  g_Cf[NB * NC * NC];
__device__ float  g_P[3 * NB * NC * NC];
__device__ float2 g_At[NB * NHEADS * CH * CH];
__device__ float2 g_Dtab[128 * 256];
// prepacked bf16 hi/lo splits
__device__ unsigned short g_xh[(size_t)NB * NC * NPIX];
__device__ unsigned short g_xl[(size_t)NB * NC * NPIX];
__device__ unsigned short g_xfh[(size_t)NB * NC * NPIX];   // flipped-pixel copy
__device__ unsigned short g_xfl[(size_t)NB * NC * NPIX];
__device__ unsigned short g_vsh[(size_t)NB * NC * NPIX];
__device__ unsigned short g_vsl[(size_t)NB * NC * NPIX];
__device__ unsigned short g_wh[2 * NC * NC];
__device__ unsigned short g_wl[2 * NC * NC];
// y stored [b][t][c], each uint32 = bf16 hi | (bf16 lo << 16)
__device__ uint32_t g_y2[(size_t)NB * NPIX * NC];
// expanded Dirichlet matrices, [s][p][x], bf16 hi/lo, re/im
__device__ unsigned short g_DreH[128 * 128 * 128];
__device__ unsigned short g_DreL[128 * 128 * 128];
__device__ unsigned short g_DimH[128 * 128 * 128];
__device__ unsigned short g_DimL[128 * 128 * 128];

// ------------------------- mma.sync helpers ----------------------------------
__device__ __forceinline__ uint32_t smem_u32(const void* p) {
    uint32_t a;
    asm("{ .reg .u64 t; cvta.to.shared.u64 t, %1; cvt.u32.u64 %0, t; }" : "=r"(a) : "l"(p));
    return a;
}
__device__ __forceinline__ void MMA(float* d, const uint32_t* a, const uint32_t* b) {
    asm volatile("mma.sync.aligned.m16n8k16.row.col.f32.bf16.bf16.f32 "
        "{%0,%1,%2,%3}, {%4,%5,%6,%7}, {%8,%9}, {%0,%1,%2,%3};"
        : "+f"(d[0]), "+f"(d[1]), "+f"(d[2]), "+f"(d[3])
        : "r"(a[0]), "r"(a[1]), "r"(a[2]), "r"(a[3]), "r"(b[0]), "r"(b[1]));
}
__device__ __forceinline__ void ldm_x4(uint32_t* r, uint32_t a) {
    asm volatile("ldmatrix.sync.aligned.m8n8.x4.shared.b16 {%0,%1,%2,%3}, [%4];"
        : "=r"(r[0]), "=r"(r[1]), "=r"(r[2]), "=r"(r[3]) : "r"(a));
}
__device__ __forceinline__ void ldm_x2(uint32_t* r, uint32_t a) {
    asm volatile("ldmatrix.sync.aligned.m8n8.x2.shared.b16 {%0,%1}, [%2];"
        : "=r"(r[0]), "=r"(r[1]) : "r"(a));
}
__device__ __forceinline__ void ldm_x2t(uint32_t* r, uint32_t a) {
    asm volatile("ldmatrix.sync.aligned.m8n8.x2.trans.shared.b16 {%0,%1}, [%2];"
        : "=r"(r[0]), "=r"(r[1]) : "r"(a));
}
__device__ __forceinline__ void split_pack(float4 v, uint2& hi, uint2& lo) {
    __nv_bfloat16 h0 = __float2bfloat16_rn(v.x), h1 = __float2bfloat16_rn(v.y);
    __nv_bfloat16 h2 = __float2bfloat16_rn(v.z), h3 = __float2bfloat16_rn(v.w);
    __nv_bfloat16 l0 = __float2bfloat16_rn(v.x - __bfloat162float(h0));
    __nv_bfloat16 l1 = __float2bfloat16_rn(v.y - __bfloat162float(h1));
    __nv_bfloat16 l2 = __float2bfloat16_rn(v.z - __bfloat162float(h2));
    __nv_bfloat16 l3 = __float2bfloat16_rn(v.w - __bfloat162float(h3));
    hi.x = (uint32_t)__bfloat16_as_ushort(h0) | ((uint32_t)__bfloat16_as_ushort(h1) << 16);
    hi.y = (uint32_t)__bfloat16_as_ushort(h2) | ((uint32_t)__bfloat16_as_ushort(h3) << 16);
    lo.x = (uint32_t)__bfloat16_as_ushort(l0) | ((uint32_t)__bfloat16_as_ushort(l1) << 16);
    lo.y = (uint32_t)__bfloat16_as_ushort(l2) | ((uint32_t)__bfloat16_as_ushort(l3) << 16);
}
__device__ __forceinline__ uint32_t pack_hl(float y) {
    __nv_bfloat16 h = __float2bfloat16_rn(y);
    __nv_bfloat16 l = __float2bfloat16_rn(y - __bfloat162float(h));
    return (uint32_t)__bfloat16_as_ushort(h) | ((uint32_t)__bfloat16_as_ushort(l) << 16);
}
__device__ __forceinline__ void pack2(float a, float b, uint32_t& hi, uint32_t& lo) {
    __nv_bfloat16 ha = __float2bfloat16_rn(a), hb = __float2bfloat16_rn(b);
    __nv_bfloat16 la = __float2bfloat16_rn(a - __bfloat162float(ha));
    __nv_bfloat16 lb = __float2bfloat16_rn(b - __bfloat162float(hb));
    hi = (uint32_t)__bfloat16_as_ushort(ha) | ((uint32_t)__bfloat16_as_ushort(hb) << 16);
    lo = (uint32_t)__bfloat16_as_ushort(la) | ((uint32_t)__bfloat16_as_ushort(lb) << 16);
}

// ------------------------- fused sum + x split (+ flipped copy) --------------
__global__ __launch_bounds__(256) void k_sumsplit(const float* __restrict__ x) {
    int bc = blockIdx.x;
    const float4* p = (const float4*)(x + (size_t)bc * NPIX);
    uint2* Xh = (uint2*)g_xh + (size_t)bc * 4096;
    uint2* Xl = (uint2*)g_xl + (size_t)bc * 4096;
    unsigned short* Fh = g_xfh + (size_t)bc * NPIX;
    unsigned short* Fl = g_xfl + (size_t)bc * NPIX;
    float s = 0.f;
    for (int q = 0; q < 16; ++q) {
        int idx = threadIdx.x + q * 256;
        float4 v = p[idx];
        uint2 hi, lo;
        split_pack(v, hi, lo);
        Xh[idx] = hi; Xl[idx] = lo;
        s += (v.x + v.y) + (v.z + v.w);
        int e0 = idx * 4;
        int y = e0 >> 7, x0 = e0 & 127;
        size_t ro = (size_t)(((128 - y) & 127)) * 128;
        unsigned short h0 = (unsigned short)(hi.x & 0xFFFF), h1 = (unsigned short)(hi.x >> 16);
        unsigned short h2 = (unsigned short)(hi.y & 0xFFFF), h3 = (unsigned short)(hi.y >> 16);
        unsigned short l0 = (unsigned short)(lo.x & 0xFFFF), l1 = (unsigned short)(lo.x >> 16);
        unsigned short l2 = (unsigned short)(lo.y & 0xFFFF), l3 = (unsigned short)(lo.y >> 16);
        int f0 = (128 - x0) & 127;
        Fh[ro + f0] = h0;        Fl[ro + f0] = l0;
        Fh[ro + 127 - x0] = h1;  Fl[ro + 127 - x0] = l1;
        Fh[ro + 126 - x0] = h2;  Fl[ro + 126 - x0] = l2;
        Fh[ro + 125 - x0] = h3;  Fl[ro + 125 - x0] = l3;
    }
    __shared__ float sm[256];
    sm[threadIdx.x] = s; __syncthreads();
    for (int w = 128; w > 0; w >>= 1) {
        if (threadIdx.x < w) sm[threadIdx.x] += sm[threadIdx.x + w];
        __syncthreads();
    }
    if (threadIdx.x == 0) g_S[bc] = sm[0];
}
__global__ __launch_bounds__(256) void k_wsplit(const float* __restrict__ w3,
                                                const float* __restrict__ wo) {
    int gid = blockIdx.x * 256 + threadIdx.x;
    int per = NC * NC / 4;
    int m = gid / per, e = gid % per;
    const float* src = (m == 0 ? w3 : wo);
    float4 v = ((const float4*)src)[e];
    uint2 hi, lo;
    split_pack(v, hi, lo);
    ((uint2*)g_wh)[gid] = hi;
    ((uint2*)g_wl)[gid] = lo;
}

// ------------------------- Gram via mma.sync (symmetric: 3 tiles) ------------
#define GSA 40
#define GTILE (128 * GSA)
#define GBUF (4 * GTILE)
#define GSMEM (2 * GBUF * 2)
__global__ __launch_bounds__(256, 1) void k_gram_mma() {
    extern __shared__ __align__(16) __nv_bfloat16 smg[];
    int tid = threadIdx.x, wid = tid >> 5, lane = tid & 31;
    int tile = blockIdx.x;
    int i0 = (tile == 2) ? 128 : 0;
    int j0 = (tile == 0) ? 0 : 128;
    int b = blockIdx.y, ks = blockIdx.z >> 1, mode = blockIdx.z & 1;
    const unsigned short* Xh = g_xh + (size_t)b * NC * NPIX;
    const unsigned short* Xl = g_xl + (size_t)b * NC * NPIX;
    const unsigned short* Bh_g = (mode == 0 ? g_xh : g_xfh) + (size_t)b * NC * NPIX;
    const unsigned short* Bl_g = (mode == 0 ? g_xl : g_xfl) + (size_t)b * NC * NPIX;
    int wm = wid >> 2, wn = wid & 3;
    float acc[4][4][4] = {};
    uint2 pAh[4], pAl[4], pBh[4], pBl[4];

    auto LD = [&](int ch) {
        int Kc = ks * 2048 + ch * 32;
#pragma unroll
        for (int q = 0; q < 4; ++q) {
            int f = tid + q * 256, r = f >> 3, c = (f & 7) * 4;
            size_t off = (size_t)(i0 + r) * NPIX + Kc + c;
            pAh[q] = *(const uint2*)(Xh + off);
            pAl[q] = *(const uint2*)(Xl + off);
        }
#pragma unroll
        for (int q = 0; q < 4; ++q) {
            int f = tid + q * 256, r = f >> 3, c = (f & 7) * 4;
            size_t off = (size_t)(j0 + r) * NPIX + Kc + c;
            pBh[q] = *(const uint2*)(Bh_g + off);
            pBl[q] = *(const uint2*)(Bl_g + off);
        }
    };
    auto ST = [&](int buf) {
        __nv_bfloat16* Ah = smg + buf * GBUF;
        __nv_bfloat16* Al = Ah + GTILE;
        __nv_bfloat16* Bh = Ah + 2 * GTILE;
        __nv_bfloat16* Bl = Ah + 3 * GTILE;
#pragma unroll
        for (int q = 0; q < 4; ++q) {
            int f = tid + q * 256, r = f >> 3, c = (f & 7) * 4;
            *(uint2*)(Ah + r * GSA + c) = pAh[q];
            *(uint2*)(Al + r * GSA + c) = pAl[q];
            *(uint2*)(Bh + r * GSA + c) = pBh[q];
            *(uint2*)(Bl + r * GSA + c) = pBl[q];
        }
    };

    LD(0);
    for (int ch = 0; ch < 64; ++ch) {
        int buf = ch & 1;
        ST(buf);
        __syncthreads();
        if (ch < 63) LD(ch + 1);
        uint32_t sb = smem_u32(smg + buf * GBUF);
        uint32_t aH = sb, aL = sb + GTILE * 2, bH = sb + 4 * GTILE, bL = sb + 6 * GTILE;
#pragma unroll
        for (int k16 = 0; k16 < 32; k16 += 16) {
            uint32_t fah[4][4], fal[4][4], fbh[4][2], fbl[4][2];
            int arow = wm * 64 + (lane & 15), acol = k16 + ((lane >> 4) << 3);
#pragma unroll
            for (int ma = 0; ma < 4; ++ma) {
                uint32_t off = (uint32_t)((arow + ma * 16) * GSA + acol) * 2;
                ldm_x4(fah[ma], aH + off);
                ldm_x4(fal[ma], aL + off);
            }
            int brow = wn * 32 + (lane & 7), bcol = k16 + (lane & 8);
#pragma unroll
            for (int na = 0; na < 4; ++na) {
                uint32_t off = (uint32_t)((brow + na * 8) * GSA + bcol) * 2;
                ldm_x2(fbh[na], bH + off);
                ldm_x2(fbl[na], bL + off);
            }
#pragma unroll
            for (int ma = 0; ma < 4; ++ma)
#pragma unroll
                for (int na = 0; na < 4; ++na) {
                    MMA(acc[ma][na], fah[ma], fbh[na]);
                    MMA(acc[ma][na], fah[ma], fbl[na]);
                    MMA(acc[ma][na], fal[ma], fbh[na]);
                }
        }
        __syncthreads();
    }
    float* P = g_part + (((size_t)ks * NB + b) * 2 + mode) * (NC * NC);
#pragma unroll
    for (int ma = 0; ma < 4; ++ma)
#pragma unroll
        for (int na = 0; na < 4; ++na) {
            int r = i0 + wm * 64 + ma * 16 + (lane >> 2);
            int c = j0 + wn * 32 + na * 8 + (lane & 3) * 2;
            float2 v0 = make_float2(acc[ma][na][0], acc[ma][na][1]);
            float2 v1 = make_float2(acc[ma][na][2], acc[ma][na][3]);
            *(float2*)&P[(size_t)r * NC + c] = v0;
            *(float2*)&P[(size_t)(r + 8) * NC + c] = v1;
        }
}

__global__ __launch_bounds__(256) void k_gred() {
    int gid = blockIdx.x * 256 + threadIdx.x;
    if (gid >= NB * 2 * NC * NC) return;
    int e = gid % (NC * NC);
    int bm = gid / (NC * NC);
    int m = bm & 1, b = bm >> 1;
    int r = e / NC, c = e % NC;
    int esrc = (r >= 128 && c < 128) ? (c * NC + r) : e;
    float s = 0.f;
    for (int ks = 0; ks < KSPLIT; ++ks)
        s += g_part[(((size_t)ks * NB + b) * 2 + m) * (NC * NC) + esrc];
    (m == 0 ? g_C0 : g_Cf)[b * (NC * NC) + e] = s;
}

// ------------------------- 1x1 conv via mma.sync -----------------------------
#define CSA 40
#define CATILE (128 * CSA)
#define CBT 5120
#define CSB0 136
#define CBUFE (2 * CATILE + 2 * CBT)
#define CSMEM (2 * CBUFE * 2)
__global__ __launch_bounds__(256, 1) void k_conv_mma(int widx,
                                                     const float* __restrict__ bias,
                                                     float* __restrict__ Oout,
                                                     int mode) {
    extern __shared__ __align__(16) __nv_bfloat16 smc[];
    int tid = threadIdx.x, wid = tid >> 5, lane = tid & 31;
    int t0 = blockIdx.x * 128, o0 = blockIdx.y * 128, b = blockIdx.z;
    const unsigned short* Wh = g_wh + (size_t)widx * NC * NC;
    const unsigned short* Wl = g_wl + (size_t)widx * NC * NC;
    const unsigned short* Bxh = g_xh + (size_t)b * NC * NPIX;
    const unsigned short* Bxl = g_xl + (size_t)b * NC * NPIX;
    const uint32_t* Ybuf = g_y2 + (size_t)b * NPIX * NC;
    int wm = wid >> 2, wn = wid & 3;
    float acc[4][4][4] = {};
    uint2 pAh[4], pAl[4], pBh[4], pBl[4];
    uint32_t pY[16];

    auto LD = [&](int ch) {
        int k0 = ch * 32;
#pragma unroll
        for (int q = 0; q < 4; ++q) {
            int f = tid + q * 256, r = f >> 3, c = (f & 7) * 4;
            size_t off = (size_t)(o0 + r) * NC + k0 + c;
            pAh[q] = *(const uint2*)(Wh + off);
            pAl[q] = *(const uint2*)(Wl + off);
        }
        if (mode == 0) {
#pragma unroll
            for (int q = 0; q < 4; ++q) {
                int f = tid + q * 256, k = f >> 5, t = (f & 31) * 4;
                size_t off = (size_t)(k0 + k) * NPIX + t0 + t;
                pBh[q] = *(const uint2*)(Bxh + off);
                pBl[q] = *(const uint2*)(Bxl + off);
            }
        } else {
#pragma unroll
            for (int q = 0; q < 16; ++q) {
                int f = tid + q * 256, t = f >> 5, k = f & 31;
                pY[q] = Ybuf[(size_t)(t0 + t) * NC + k0 + k];
            }
        }
    };
    auto ST = [&](int buf) {
        __nv_bfloat16* Ah = smc + buf * CBUFE;
        __nv_bfloat16* Al = Ah + CATILE;
        unsigned short* Bh = (unsigned short*)(Ah + 2 * CATILE);
        unsigned short* Bl = Bh + CBT;
#pragma unroll
        for (int q = 0; q < 4; ++q) {
            int f = tid + q * 256, r = f >> 3, c = (f & 7) * 4;
            *(uint2*)(Ah + r * CSA + c) = pAh[q];
            *(uint2*)(Al + r * CSA + c) = pAl[q];
        }
        if (mode == 0) {
#pragma unroll
            for (int q = 0; q < 4; ++q) {
                int f = tid + q * 256, k = f >> 5, t = (f & 31) * 4;
                *(uint2*)(Bh + k * CSB0 + t) = pBh[q];
                *(uint2*)(Bl + k * CSB0 + t) = pBl[q];
            }
        } else {
#pragma unroll
            for (int q = 0; q < 16; ++q) {
                int f = tid + q * 256, t = f >> 5, k = f & 31;
                uint32_t v = pY[q];
                Bh[t * 40 + k] = (unsigned short)(v & 0xFFFF);
                Bl[t * 40 + k] = (unsigned short)(v >> 16);
            }
        }
    };

    LD(0);
    for (int ch = 0; ch < 8; ++ch) {
        int buf = ch & 1;
        ST(buf);
        __syncthreads();
        if (ch < 7) LD(ch + 1);
        uint32_t sb = smem_u32(smc + buf * CBUFE);
        uint32_t aH = sb, aL = sb + CATILE * 2, bH = sb + 4 * CATILE, bL = bH + CBT * 2;
#pragma unroll
        for (int k16 = 0; k16 < 32; k16 += 16) {
            uint32_t fah[4][4], fal[4][4], fbh[4][2], fbl[4][2];
            int arow = wm * 64 + (lane & 15), acol = k16 + ((lane >> 4) << 3);
#pragma unroll
            for (int ma = 0; ma < 4; ++ma) {
                uint32_t off = (uint32_t)((arow + ma * 16) * CSA + acol) * 2;
                ldm_x4(fah[ma], aH + off);
                ldm_x4(fal[ma], aL + off);
            }
            if (mode == 0) {
                int krow = k16 + (lane & 15);
#pragma unroll
                for (int na = 0; na < 4; ++na) {
                    uint32_t off = (uint32_t)(krow * CSB0 + wn * 32 + na * 8) * 2;
                    ldm_x2t(fbh[na], bH + off);
                    ldm_x2t(fbl[na], bL + off);
                }
            } else {
                int brow = wn * 32 + (lane & 7), bcol = k16 + (lane & 8);
#pragma unroll
                for (int na = 0; na < 4; ++na) {
                    uint32_t off = (uint32_t)((brow + na * 8) * 40 + bcol) * 2;
                    ldm_x2(fbh[na], bH + off);
                    ldm_x2(fbl[na], bL + off);
                }
            }
#pragma unroll
            for (int ma = 0; ma < 4; ++ma)
#pragma unroll
                for (int na = 0; na < 4; ++na) {
                    MMA(acc[ma][na], fah[ma], fbh[na]);
                    MMA(acc[ma][na], fah[ma], fbl[na]);
                    MMA(acc[ma][na], fal[ma], fbh[na]);
                }
        }
        __syncthreads();
    }
#pragma unroll
    for (int ma = 0; ma < 4; ++ma) {
        int r = o0 + wm * 64 + ma * 16 + (lane >> 2);
        float b0v = bias[r], b1v = bias[r + 8];
#pragma unroll
        for (int na = 0; na < 4; ++na) {
            int c = t0 + wn * 32 + na * 8 + (lane & 3) * 2;
            if (mode == 0) {
                uint32_t h0, l0, h1, l1;
                pack2(acc[ma][na][0] + b0v, acc[ma][na][1] + b0v, h0, l0);
                pack2(acc[ma][na][2] + b1v, acc[ma][na][3] + b1v, h1, l1);
                size_t i0v = (size_t)(b * NC + r) * NPIX + c;
                *(uint32_t*)(g_vsh + i0v) = h0;
                *(uint32_t*)(g_vsl + i0v) = l0;
                size_t i1v = i0v + (size_t)8 * NPIX;
                *(uint32_t*)(g_vsh + i1v) = h1;
                *(uint32_t*)(g_vsl + i1v) = l1;
            } else {
                float* O = Oout + (size_t)b * NC * NPIX;
                float2 v0 = make_float2(acc[ma][na][0] + b0v, acc[ma][na][1] + b0v);
                float2 v1 = make_float2(acc[ma][na][2] + b1v, acc[ma][na][3] + b1v);
                *(float2*)&O[(size_t)r * NPIX + c] = v0;
                *(float2*)&O[(size_t)(r + 8) * NPIX + c] = v1;
            }
        }
    }
}

// ------------------------- P matrices: A @ W^T (FFMA) ------------------------
__global__ __launch_bounds__(256) void k_mm256(const float* __restrict__ w1,
                                               const float* __restrict__ w2) {
    int tile = blockIdx.x, b = blockIdx.y, z = blockIdx.z;
    const float* A = (z == 0 ? g_Cf : g_C0) + (size_t)b * NC * NC;
    const float* W = (z == 1 ? w1 : w2);
    float* P = g_P + ((size_t)z * NB + b) * NC * NC;
    int i0 = (tile >> 2) * 64, j0 = (tile & 3) * 64;
    __shared__ float As[64][33], Bs[64][33];
    float acc[4][4] = {};
    int ty = threadIdx.x >> 4, tx = threadIdx.x & 15;
    for (int kb = 0; kb < NC; kb += 32) {
        for (int idx = threadIdx.x; idx < 64 * 32; idx += 256) {
            int r = idx >> 5, c = idx & 31;
            As[r][c] = A[(i0 + r) * NC + kb + c];
            Bs[r][c] = W[(j0 + r) * NC + kb + c];
        }
        __syncthreads();
#pragma unroll
        for (int kk = 0; kk < 32; ++kk) {
            float a[4], bv[4];
#pragma unroll
            for (int ii = 0; ii < 4; ++ii) a[ii] = As[ty + 16 * ii][kk];
#pragma unroll
            for (int jj = 0; jj < 4; ++jj) bv[jj] = Bs[tx + 16 * jj][kk];
#pragma unroll
            for (int ii = 0; ii < 4; ++ii)
#pragma unroll
                for (int jj = 0; jj < 4; ++jj) acc[ii][jj] += a[ii] * bv[jj];
        }
        __syncthreads();
    }
    for (int ii = 0; ii < 4; ++ii)
        for (int jj = 0; jj < 4; ++jj)
            P[(i0 + ty + 16 * ii) * NC + j0 + tx + 16 * jj] = acc[ii][jj];
}

// ------------------------- attn -> softmax -> ifft_c -------------------------
__global__ __launch_bounds__(256) void k_attn(const float* __restrict__ w1,
                                              const float* __restrict__ w2,
                                              const float* __restrict__ b1,
                                              const float* __restrict__ b2,
                                              const float* __restrict__ temp) {
    int b = blockIdx.x >> 3, h = blockIdx.x & 7;
    int tid = threadIdx.x;
    __shared__ float Ps[NC][33];
    __shared__ float numS[CH][33];
    __shared__ float redA[CH][8], redB[CH][8];
    __shared__ float qn[CH], kn[CH], w1s[CH], w2s[CH];
    const float* P1 = g_P + ((size_t)0 * NB + b) * NC * NC;
    const float* P2 = g_P + ((size_t)1 * NB + b) * NC * NC;
    const float* P3 = g_P + ((size_t)2 * NB + b) * NC * NC;
    const float* Sb = g_S + b * NC;

    for (int idx = tid; idx < NC * CH; idx += 256)
        Ps[idx >> 5][idx & 31] = P1[(size_t)(idx >> 5) * NC + h * CH + (idx & 31)];
    __syncthreads();
    {
        int c = tid >> 3, dg = tid & 7;
        float acc[4] = {0.f, 0.f, 0.f, 0.f};
        const float* wrow = w1 + (size_t)(h * CH + c) * NC;
        for (int j = 0; j < NC; ++j) {
            float w = wrow[j];
#pragma unroll
            for (int q = 0; q < 4; ++q) acc[q] += w * Ps[j][dg + 8 * q];
        }
#pragma unroll
        for (int q = 0; q < 4; ++q) numS[c][dg + 8 * q] = acc[q];
    }
    __syncthreads();

    for (int idx = tid; idx < NC * CH; idx += 256)
        Ps[idx >> 5][idx & 31] = P2[(size_t)(idx >> 5) * NC + h * CH + (idx & 31)];
    __syncthreads();
    {
        int c = tid >> 3, g = tid & 7;
        const float* wrow = w1 + (size_t)(h * CH + c) * NC;
        float pa = 0.f, pb = 0.f;
        for (int j = g * 32; j < g * 32 + 32; ++j) {
            float w = wrow[j];
            pa += w * Ps[j][c];
            pb += w * Sb[j];
        }
        redA[c][g] = pa; redB[c][g] = pb;
    }
    __syncthreads();
    if (tid < CH) {
        float a = 0.f, bb = 0.f;
        for (int g = 0; g < 8; ++g) { a += redA[tid][g]; bb += redB[tid][g]; }
        float b1c = b1[h * CH + tid];
        w1s[tid] = bb;
        qn[tid] = fmaxf(sqrtf(fmaxf(a + 2.f * b1c * bb + 16384.f * b1c * b1c, 0.f)), 1e-12f);
    }
    __syncthreads();

    for (int idx = tid; idx < NC * CH; idx += 256)
        Ps[idx >> 5][idx & 31] = P3[(size_t)(idx >> 5) * NC + h * CH + (idx & 31)];
    __syncthreads();
    {
        int c = tid >> 3, g = tid & 7;
        const float* wrow = w2 + (size_t)(h * CH + c) * NC;
        float pa = 0.f, pb = 0.f;
        for (int j = g * 32; j < g * 32 + 32; ++j) {
            float w = wrow[j];
            pa += w * Ps[j][c];
            pb += w * Sb[j];
        }
        redA[c][g] = pa; redB[c][g] = pb;
    }
    __syncthreads();
    if (tid < CH) {
        float a = 0.f, bb = 0.f;
        for (int g = 0; g < 8; ++g) { a += redA[tid][g]; bb += redB[tid][g]; }
        float b2d = b2[h * CH + tid];
        w2s[tid] = bb;
        kn[tid] = fmaxf(sqrtf(fmaxf(a + 2.f * b2d * bb + 16384.f * b2d * b2d, 0.f)), 1e-12f);
    }
    __syncthreads();

    {
        float tH = temp[h];
        for (int idx = tid; idx < CH * CH; idx += 256) {
            int c = idx >> 5, d = idx & 31;
            float b1c = b1[h * CH + c], b2d = b2[h * CH + d];
            float numF = numS[c][d] + b1c * w2s[d] + b2d * w1s[c] + 16384.f * b1c * b2d;
            numS[c][d] = tH * numF / (qn[c] * kn[d]);
        }
    }
    __syncthreads();

    if (tid < CH) {
        float mx = -1e30f;
        for (int d = 0; d < CH; ++d) mx = fmaxf(mx, numS[tid][d]);
        float s = 0.f;
        for (int d = 0; d < CH; ++d) { float e = expf(numS[tid][d] - mx); numS[tid][d] = e; s += e; }
        float inv = 1.f / s;
        for (int d = 0; d < CH; ++d) numS[tid][d] *= inv;
    }
    __syncthreads();

    for (int idx = tid; idx < CH * CH; idx += 256) {
        int cp = idx >> 5, d = idx & 31;
        float re = 0.f, im = 0.f;
        for (int c = 0; c < CH; ++c) {
            int ph = (c * cp) & 31;
            float sv, cv;
            sincosf(0.19634954084936207f * (float)ph, &sv, &cv);
            float a = numS[c][d];
            re += a * cv; im += a * sv;
        }
        re *= 0.03125f; im *= 0.03125f;
        if (cp == 0) im += 0.03125f;
        g_At[((size_t)blockIdx.x * CH + cp) * CH + d] = make_float2(re, im);
    }
}

// ------------------------- Dirichlet table + bf16 expansion ------------------
__global__ __launch_bounds__(256) void k_dtab() {
    int i = blockIdx.x * 256 + threadIdx.x;
    if (i >= 128 * 255) return;
    int s = i / 255, mi = i % 255, m = mi - 127;
    float2 v;
    if (s == 0) {
        v = make_float2(m == 0 ? 1.f : 0.f, 0.f);
    } else {
        double f = (double)s / 128.0;
        double al = (double)m + f;
        double mag = sinpi(f) / (128.0 * sinpi(al / 128.0));
        if (m & 1) mag = -mag;
        double ph = al * (127.0 / 128.0);
        v = make_float2((float)(cospi(ph) * mag), (float)(sinpi(ph) * mag));
    }
    g_Dtab[s * 256 + mi] = v;
}
__global__ __launch_bounds__(256) void k_dexp() {
    int gid = blockIdx.x * 256 + threadIdx.x;
    int x = gid & 127, p = (gid >> 7) & 127, s = gid >> 14;
    float2 v = g_Dtab[s * 256 + (p - x + 127)];
    __nv_bfloat16 hr = __float2bfloat16_rn(v.x);
    __nv_bfloat16 hi = __float2bfloat16_rn(v.y);
    g_DreH[gid] = __bfloat16_as_ushort(hr);
    g_DreL[gid] = __bfloat16_as_ushort(__float2bfloat16_rn(v.x - __bfloat162float(hr)));
    g_DimH[gid] = __bfloat16_as_ushort(hi);
    g_DimL[gid] = __bfloat16_as_ushort(__float2bfloat16_rn(v.y - __bfloat162float(hi)));
}

// ------------------------- fused Dirichlet transform + channel attn ----------
#define FSA 40
#define FGEMM 51200
#define FEPI (66560 + 2 * 2112 * 4)
#define FSMEM (FEPI > FGEMM ? FEPI : FGEMM)
__global__ __launch_bounds__(256, 1) void k_fft_fused() {
    extern __shared__ __align__(16) char smf[];
    __nv_bfloat16* smb = (__nv_bfloat16*)smf;
    int tid = threadIdx.x, wid = tid >> 5, lane = tid & 31;
    int s = blockIdx.x;
    int b = blockIdx.y >> 2, dblk = blockIdx.y & 3;
    int d0 = dblk * 64;
    int wm = wid >> 1, wn = wid & 1;
    float accRe[2][4][4] = {}, accIm[2][4][4] = {};
    const uint32_t sb = smem_u32(smf);
    const uint32_t oReH = 0, oReL = 5120, oImH = 10240, oImL = 15360, oBH = 20480, oBL = 23040;

    for (int kc = 0; kc < 128; kc += 32) {
        __syncthreads();
#pragma unroll
        for (int q = 0; q < 4; ++q) {
            int f = tid + q * 256, r = f >> 3, c = (f & 7) * 4;
            size_t so = (size_t)s * 16384 + r * 128 + kc + c;
            uint32_t dofs = r * FSA + c;
            *(uint2*)(smb + oReH + dofs) = *(const uint2*)(g_DreH + so);
            *(uint2*)(smb + oReL + dofs) = *(const uint2*)(g_DreL + so);
            *(uint2*)(smb + oImH + dofs) = *(const uint2*)(g_DimH + so);
            *(uint2*)(smb + oImL + dofs) = *(const uint2*)(g_DimL + so);
        }
#pragma unroll
        for (int q = 0; q < 2; ++q) {
            int f = tid + q * 256, r = f >> 3, c = (f & 7) * 4;
            size_t so = (size_t)(b * NC + d0 + r) * NPIX + s * 128 + kc + c;
            uint32_t dofs = r * FSA + c;
            *(uint2*)(smb + oBH + dofs) = *(const uint2*)(g_vsh + so);
            *(uint2*)(smb + oBL + dofs) = *(const uint2*)(g_vsl + so);
        }
        __syncthreads();
#pragma unroll
        for (int k16 = 0; k16 < 32; k16 += 16) {
            uint32_t fbh[4][2], fbl[4][2];
            int brow = wn * 32 + (lane & 7), bcol = k16 + (lane & 8);
#pragma unroll
            for (int na = 0; na < 4; ++na) {
                uint32_t off = (uint32_t)((brow + na * 8) * FSA + bcol) * 2;
                ldm_x2(fbh[na], sb + oBH * 2 + off);
                ldm_x2(fbl[na], sb + oBL * 2 + off);
            }
            int arow = wm * 32 + (lane & 15), acol = k16 + ((lane >> 4) << 3);
            {
                uint32_t fh[2][4], fl[2][4];
#pragma unroll
                for (int ma = 0; ma < 2; ++ma) {
                    uint32_t off = (uint32_t)((arow + ma * 16) * FSA + acol) * 2;
                    ldm_x4(fh[ma], sb + oReH * 2 + off);
                    ldm_x4(fl[ma], sb + oReL * 2 + off);
                }
#pragma unroll
                for (int ma = 0; ma < 2; ++ma)
#pragma unroll
                    for (int na = 0; na < 4; ++na) {
                        MMA(accRe[ma][na], fh[ma], fbh[na]);
                        MMA(accRe[ma][na], fh[ma], fbl[na]);
                        MMA(accRe[ma][na], fl[ma], fbh[na]);
                    }
            }
            {
                uint32_t fh[2][4], fl[2][4];
#pragma unroll
                for (int ma = 0; ma < 2; ++ma) {
                    uint32_t off = (uint32_t)((arow + ma * 16) * FSA + acol) * 2;
                    ldm_x4(fh[ma], sb + oImH * 2 + off);
                    ldm_x4(fl[ma], sb + oImL * 2 + off);
                }
#pragma unroll
                for (int ma = 0; ma < 2; ++ma)
#pragma unroll
                    for (int na = 0; na < 4; ++na) {
                        MMA(accIm[ma][na], fh[ma], fbh[na]);
                        MMA(accIm[ma][na], fh[ma], fbl[na]);
                        MMA(accIm[ma][na], fl[ma], fbh[na]);
                    }
            }
        }
    }
    __syncthreads();
    float2* VtS = (float2*)smf;
    float* Are = (float*)(smf + 66560);
    float* Aim = Are + 2112;
#pragma unroll
    for (int ma = 0; ma < 2; ++ma)
#pragma unroll
        for (int na = 0; na < 4; ++na) {
            int p = wm * 32 + ma * 16 + (lane >> 2);
            int d = wn * 32 + na * 8 + (lane & 3) * 2;
            VtS[p * 65 + d]     = make_float2(accRe[ma][na][0], accIm[ma][na][0]);
            VtS[p * 65 + d + 1] = make_float2(accRe[ma][na][1], accIm[ma][na][1]);
            VtS[(p + 8) * 65 + d]     = make_float2(accRe[ma][na][2], accIm[ma][na][2]);
            VtS[(p + 8) * 65 + d + 1] = make_float2(accRe[ma][na][3], accIm[ma][na][3]);
        }
    int h0 = dblk * 2;
    for (int idx = tid; idx < 2048; idx += 256) {
        int hh = idx >> 10, rest = idx & 1023, c = rest >> 5, d = rest & 31;
        float2 a = g_At[(size_t)(b * NHEADS + h0 + hh) * 1024 + c * 32 + d];
        Are[(hh * 32 + c) * 33 + d] = a.x;
        Aim[(hh * 32 + c) * 33 + d] = a.y;
    }
    __syncthreads();
    int pg = tid >> 5, cg = tid & 31;
    int head = cg >> 4, cl0 = (2 * cg) & 31;
    const float* ArH = Are + head * 1056;
    const float* AiH = Aim + head * 1056;
    float accr[2][16] = {}, acci[2][16] = {};
    for (int d = 0; d < 32; ++d) {
        float a0r = ArH[cl0 * 33 + d],       a0i = AiH[cl0 * 33 + d];
        float a1r = ArH[(cl0 + 1) * 33 + d], a1i = AiH[(cl0 + 1) * 33 + d];
        int dv = head * 32 + d;
#pragma unroll
        for (int i = 0; i < 16; ++i) {
            float2 v = VtS[(pg * 16 + i) * 65 + dv];
            accr[0][i] += a0r * v.x - a0i * v.y;
            acci[0][i] += a0r * v.y + a0i * v.x;
            accr[1][i] += a1r * v.x - a1i * v.y;
            acci[1][i] += a1r * v.y + a1i * v.x;
        }
    }
    uint32_t* Y = g_y2 + (size_t)b * NPIX * NC;
#pragma unroll
    for (int i = 0; i < 16; ++i) {
        int p = pg * 16 + i;
        int t = (p << 7) + s;
        float y0 = sqrtf(accr[0][i] * accr[0][i] + acci[0][i] * acci[0][i]);
        float y1 = sqrtf(accr[1][i] * accr[1][i] + acci[1][i] * acci[1][i]);
        uint2 w;
        w.x = pack_hl(y0);
        w.y = pack_hl(y1);
        *(uint2*)&Y[(size_t)t * NC + d0 + 2 * cg] = w;
    }
}

// ------------------------- launch --------------------------------------------
extern "C" void kernel_launch(void* const* d_in, const int* in_sizes, int n_in,
                              void* d_out, int out_size) {
    const float* x  = (const float*)d_in[0];
    const float* w1 = (const float*)d_in[1];
    const float* b1 = (const float*)d_in[2];
    const float* w2 = (const float*)d_in[3];
    const float* b2 = (const float*)d_in[4];
    const float* w3 = (const float*)d_in[5];
    const float* b3 = (const float*)d_in[6];
    const float* wo = (const float*)d_in[7];
    const float* bo = (const float*)d_in[8];
    const float* temp = (const float*)d_in[9];
    float* out = (float*)d_out;

    // One-time resource creation: streams/events persist for the process
    // lifetime so they exist BEFORE the harness's pre-capture memory baseline
    // (created during the correctness call) and nothing is allocated or freed
    // during capture/replay/teardown. Work enqueued per call is identical.
    static cudaStream_t s1 = nullptr, s2 = nullptr;
    static cudaEvent_t evR = nullptr, evS = nullptr, evG = nullptr, evD = nullptr;
    if (s1 == nullptr) {
        cudaStreamCreateWithFlags(&s1, cudaStreamNonBlocking);
        cudaStreamCreateWithFlags(&s2, cudaStreamNonBlocking);
        cudaEventCreateWithFlags(&evR, cudaEventDisableTiming);
        cudaEventCreateWithFlags(&evS, cudaEventDisableTiming);
        cudaEventCreateWithFlags(&evG, cudaEventDisableTiming);
        cudaEventCreateWithFlags(&evD, cudaEventDisableTiming);
        cudaFuncSetAttribute(k_gram_mma, cudaFuncAttributeMaxDynamicSharedMemorySize, GSMEM);
        cudaFuncSetAttribute(k_conv_mma, cudaFuncAttributeMaxDynamicSharedMemorySize, CSMEM);
        cudaFuncSetAttribute(k_fft_fused, cudaFuncAttributeMaxDynamicSharedMemorySize, FSMEM);
    }

    // branch s2: Dirichlet tables (independent until k_fft_fused)
    cudaEventRecord(evR, 0);
    cudaStreamWaitEvent(s2, evR, 0);
    k_dtab<<<128, 256, 0, s2>>>();
    k_dexp<<<8192, 256, 0, s2>>>();
    cudaEventRecord(evD, s2);

    // main: weight split + x split (+flip +sums)
    k_wsplit<<<2 * NC * NC / 4 / 256, 256>>>(w3, wo);
    k_sumsplit<<<NB * NC, 256>>>(x);
    cudaEventRecord(evS, 0);

    // branch s1: gram chain (runs concurrent with conv0 on main)
    cudaStreamWaitEvent(s1, evS, 0);
    k_gram_mma<<<dim3(3, NB, KSPLIT * 2), 256, GSMEM, s1>>>();
    k_gred<<<(NB * 2 * NC * NC) / 256, 256, 0, s1>>>();
    k_mm256<<<dim3(16, NB, 3), 256, 0, s1>>>(w1, w2);
    k_attn<<<NB * NHEADS, 256, 0, s1>>>(w1, w2, b1, b2, temp);
    cudaEventRecord(evG, s1);

    // main: conv0 (needs wsplit + sumsplit only)
    k_conv_mma<<<dim3(128, 2, NB), 256, CSMEM>>>(0, b3, nullptr, 0);

    // join: fft needs conv0 (main), attn (s1), dexp (s2)
    cudaStreamWaitEvent(0, evG, 0);
    cudaStreamWaitEvent(0, evD, 0);
    k_fft_fused<<<dim3(128, 16), 256, FSMEM>>>();
    k_conv_mma<<<dim3(128, 2, NB), 256, CSMEM>>>(1, bo, out, 1);
}

// round 16
// speedup vs baseline: 2.4115x; 1.0262x over previous
#include <cuda_runtime.h>
#include <cuda_bf16.h>
#include <math.h>
#include <stdint.h>

#define NB 4
#define NC 256
#define NPIX 16384
#define NHEADS 8
#define CH 32
#define KSPLIT 8

// ------------------------- scratch ------------------------------------------
__device__ float  g_S[NB * NC];
__device__ float  g_part[KSPLIT * NB * 2 * NC * NC];
__device__ float  g_C0[NB * NC * NC];
__device__ float  g_Cf[NB * NC * NC];
__device__ float  g_P[3 * NB * NC * NC];
__device__ float2 g_At[NB * NHEADS * CH * CH];
__device__ float2 g_Dtab[128 * 256];
// prepacked bf16 hi/lo splits
__device__ unsigned short g_xh[(size_t)NB * NC * NPIX];
__device__ unsigned short g_xl[(size_t)NB * NC * NPIX];
__device__ unsigned short g_xfh[(size_t)NB * NC * NPIX];   // flipped-pixel copy
__device__ unsigned short g_xfl[(size_t)NB * NC * NPIX];
__device__ unsigned short g_vsh[(size_t)NB * NC * NPIX];
__device__ unsigned short g_vsl[(size_t)NB * NC * NPIX];
__device__ unsigned short g_wh[2 * NC * NC];
__device__ unsigned short g_wl[2 * NC * NC];
// y stored [b][t][c], each uint32 = bf16 hi | (bf16 lo << 16)
__device__ uint32_t g_y2[(size_t)NB * NPIX * NC];
// expanded Dirichlet matrices, [s][p][x], bf16 hi/lo, re/im
__device__ unsigned short g_DreH[128 * 128 * 128];
__device__ unsigned short g_DreL[128 * 128 * 128];
__device__ unsigned short g_DimH[128 * 128 * 128];
__device__ unsigned short g_DimL[128 * 128 * 128];

// ------------------------- mma.sync helpers ----------------------------------
__device__ __forceinline__ uint32_t smem_u32(const void* p) {
    uint32_t a;
    asm("{ .reg .u64 t; cvta.to.shared.u64 t, %1; cvt.u32.u64 %0, t; }" : "=r"(a) : "l"(p));
    return a;
}
__device__ __forceinline__ void MMA(float* d, const uint32_t* a, const uint32_t* b) {
    asm volatile("mma.sync.aligned.m16n8k16.row.col.f32.bf16.bf16.f32 "
        "{%0,%1,%2,%3}, {%4,%5,%6,%7}, {%8,%9}, {%0,%1,%2,%3};"
        : "+f"(d[0]), "+f"(d[1]), "+f"(d[2]), "+f"(d[3])
        : "r"(a[0]), "r"(a[1]), "r"(a[2]), "r"(a[3]), "r"(b[0]), "r"(b[1]));
}
__device__ __forceinline__ void ldm_x4(uint32_t* r, uint32_t a) {
    asm volatile("ldmatrix.sync.aligned.m8n8.x4.shared.b16 {%0,%1,%2,%3}, [%4];"
        : "=r"(r[0]), "=r"(r[1]), "=r"(r[2]), "=r"(r[3]) : "r"(a));
}
__device__ __forceinline__ void ldm_x2(uint32_t* r, uint32_t a) {
    asm volatile("ldmatrix.sync.aligned.m8n8.x2.shared.b16 {%0,%1}, [%2];"
        : "=r"(r[0]), "=r"(r[1]) : "r"(a));
}
__device__ __forceinline__ void ldm_x2t(uint32_t* r, uint32_t a) {
    asm volatile("ldmatrix.sync.aligned.m8n8.x2.trans.shared.b16 {%0,%1}, [%2];"
        : "=r"(r[0]), "=r"(r[1]) : "r"(a));
}
__device__ __forceinline__ void split_pack(float4 v, uint2& hi, uint2& lo) {
    __nv_bfloat16 h0 = __float2bfloat16_rn(v.x), h1 = __float2bfloat16_rn(v.y);
    __nv_bfloat16 h2 = __float2bfloat16_rn(v.z), h3 = __float2bfloat16_rn(v.w);
    __nv_bfloat16 l0 = __float2bfloat16_rn(v.x - __bfloat162float(h0));
    __nv_bfloat16 l1 = __float2bfloat16_rn(v.y - __bfloat162float(h1));
    __nv_bfloat16 l2 = __float2bfloat16_rn(v.z - __bfloat162float(h2));
    __nv_bfloat16 l3 = __float2bfloat16_rn(v.w - __bfloat162float(h3));
    hi.x = (uint32_t)__bfloat16_as_ushort(h0) | ((uint32_t)__bfloat16_as_ushort(h1) << 16);
    hi.y = (uint32_t)__bfloat16_as_ushort(h2) | ((uint32_t)__bfloat16_as_ushort(h3) << 16);
    lo.x = (uint32_t)__bfloat16_as_ushort(l0) | ((uint32_t)__bfloat16_as_ushort(l1) << 16);
    lo.y = (uint32_t)__bfloat16_as_ushort(l2) | ((uint32_t)__bfloat16_as_ushort(l3) << 16);
}
__device__ __forceinline__ uint32_t pack_hl(float y) {
    __nv_bfloat16 h = __float2bfloat16_rn(y);
    __nv_bfloat16 l = __float2bfloat16_rn(y - __bfloat162float(h));
    return (uint32_t)__bfloat16_as_ushort(h) | ((uint32_t)__bfloat16_as_ushort(l) << 16);
}
__device__ __forceinline__ void pack2(float a, float b, uint32_t& hi, uint32_t& lo) {
    __nv_bfloat16 ha = __float2bfloat16_rn(a), hb = __float2bfloat16_rn(b);
    __nv_bfloat16 la = __float2bfloat16_rn(a - __bfloat162float(ha));
    __nv_bfloat16 lb = __float2bfloat16_rn(b - __bfloat162float(hb));
    hi = (uint32_t)__bfloat16_as_ushort(ha) | ((uint32_t)__bfloat16_as_ushort(hb) << 16);
    lo = (uint32_t)__bfloat16_as_ushort(la) | ((uint32_t)__bfloat16_as_ushort(lb) << 16);
}

// ------------------------- fused sum + x split (+ warp-shuffle flip) ---------
// Warp w owns rows w*16..w*16+15; each lane holds one 4-elem quad of a row.
// Flipped row out[j] = in[(128-j)&127]:
//   lane L's output quad = [elem0 of lane (32-L)&31, e3,e2,e1 of lane 31-L]
__global__ __launch_bounds__(256) void k_sumsplit(const float* __restrict__ x) {
    int bc = blockIdx.x;
    const float4* p = (const float4*)(x + (size_t)bc * NPIX);
    uint2* Xh = (uint2*)g_xh + (size_t)bc * 4096;
    uint2* Xl = (uint2*)g_xl + (size_t)bc * 4096;
    uint2* Fh = (uint2*)g_xfh + (size_t)bc * 4096;
    uint2* Fl = (uint2*)g_xfl + (size_t)bc * 4096;
    int warp = threadIdx.x >> 5, lane = threadIdx.x & 31;
    int srcR = 31 - lane, src0 = (32 - lane) & 31;
    float s = 0.f;
    for (int rr = 0; rr < 16; ++rr) {
        int row = warp * 16 + rr;
        int idx = row * 32 + lane;
        float4 v = p[idx];
        uint2 hi, lo;
        split_pack(v, hi, lo);
        Xh[idx] = hi; Xl[idx] = lo;
        s += (v.x + v.y) + (v.z + v.w);
        uint32_t rhx = __shfl_sync(0xFFFFFFFFu, hi.x, srcR);
        uint32_t rhy = __shfl_sync(0xFFFFFFFFu, hi.y, srcR);
        uint32_t rlx = __shfl_sync(0xFFFFFFFFu, lo.x, srcR);
        uint32_t rly = __shfl_sync(0xFFFFFFFFu, lo.y, srcR);
        uint32_t e0h = __shfl_sync(0xFFFFFFFFu, hi.x, src0);
        uint32_t e0l = __shfl_sync(0xFFFFFFFFu, lo.x, src0);
        uint2 oh, ol;
        oh.x = (e0h & 0xFFFFu) | (rhy & 0xFFFF0000u);   // [in(128-4L), in(127-4L)]
        oh.y = (rhy & 0xFFFFu) | (rhx & 0xFFFF0000u);   // [in(126-4L), in(125-4L)]
        ol.x = (e0l & 0xFFFFu) | (rly & 0xFFFF0000u);
        ol.y = (rly & 0xFFFFu) | (rlx & 0xFFFF0000u);
        int frow = (128 - row) & 127;
        Fh[frow * 32 + lane] = oh;
        Fl[frow * 32 + lane] = ol;
    }
    __shared__ float sm[256];
    sm[threadIdx.x] = s; __syncthreads();
    for (int w = 128; w > 0; w >>= 1) {
        if (threadIdx.x < w) sm[threadIdx.x] += sm[threadIdx.x + w];
        __syncthreads();
    }
    if (threadIdx.x == 0) g_S[bc] = sm[0];
}
__global__ __launch_bounds__(256) void k_wsplit(const float* __restrict__ w3,
                                                const float* __restrict__ wo) {
    int gid = blockIdx.x * 256 + threadIdx.x;
    int per = NC * NC / 4;
    int m = gid / per, e = gid % per;
    const float* src = (m == 0 ? w3 : wo);
    float4 v = ((const float4*)src)[e];
    uint2 hi, lo;
    split_pack(v, hi, lo);
    ((uint2*)g_wh)[gid] = hi;
    ((uint2*)g_wl)[gid] = lo;
}

// ------------------------- Gram via mma.sync (symmetric: 3 tiles) ------------
#define GSA 40
#define GTILE (128 * GSA)
#define GBUF (4 * GTILE)
#define GSMEM (2 * GBUF * 2)
__global__ __launch_bounds__(256, 1) void k_gram_mma() {
    extern __shared__ __align__(16) __nv_bfloat16 smg[];
    int tid = threadIdx.x, wid = tid >> 5, lane = tid & 31;
    int tile = blockIdx.x;
    int i0 = (tile == 2) ? 128 : 0;
    int j0 = (tile == 0) ? 0 : 128;
    int b = blockIdx.y, ks = blockIdx.z >> 1, mode = blockIdx.z & 1;
    const unsigned short* Xh = g_xh + (size_t)b * NC * NPIX;
    const unsigned short* Xl = g_xl + (size_t)b * NC * NPIX;
    const unsigned short* Bh_g = (mode == 0 ? g_xh : g_xfh) + (size_t)b * NC * NPIX;
    const unsigned short* Bl_g = (mode == 0 ? g_xl : g_xfl) + (size_t)b * NC * NPIX;
    int wm = wid >> 2, wn = wid & 3;
    float acc[4][4][4] = {};
    uint2 pAh[4], pAl[4], pBh[4], pBl[4];

    auto LD = [&](int ch) {
        int Kc = ks * 2048 + ch * 32;
#pragma unroll
        for (int q = 0; q < 4; ++q) {
            int f = tid + q * 256, r = f >> 3, c = (f & 7) * 4;
            size_t off = (size_t)(i0 + r) * NPIX + Kc + c;
            pAh[q] = *(const uint2*)(Xh + off);
            pAl[q] = *(const uint2*)(Xl + off);
        }
#pragma unroll
        for (int q = 0; q < 4; ++q) {
            int f = tid + q * 256, r = f >> 3, c = (f & 7) * 4;
            size_t off = (size_t)(j0 + r) * NPIX + Kc + c;
            pBh[q] = *(const uint2*)(Bh_g + off);
            pBl[q] = *(const uint2*)(Bl_g + off);
        }
    };
    auto ST = [&](int buf) {
        __nv_bfloat16* Ah = smg + buf * GBUF;
        __nv_bfloat16* Al = Ah + GTILE;
        __nv_bfloat16* Bh = Ah + 2 * GTILE;
        __nv_bfloat16* Bl = Ah + 3 * GTILE;
#pragma unroll
        for (int q = 0; q < 4; ++q) {
            int f = tid + q * 256, r = f >> 3, c = (f & 7) * 4;
            *(uint2*)(Ah + r * GSA + c) = pAh[q];
            *(uint2*)(Al + r * GSA + c) = pAl[q];
            *(uint2*)(Bh + r * GSA + c) = pBh[q];
            *(uint2*)(Bl + r * GSA + c) = pBl[q];
        }
    };

    LD(0);
    for (int ch = 0; ch < 64; ++ch) {
        int buf = ch & 1;
        ST(buf);
        __syncthreads();
        if (ch < 63) LD(ch + 1);
        uint32_t sb = smem_u32(smg + buf * GBUF);
        uint32_t aH = sb, aL = sb + GTILE * 2, bH = sb + 4 * GTILE, bL = sb + 6 * GTILE;
#pragma unroll
        for (int k16 = 0; k16 < 32; k16 += 16) {
            uint32_t fah[4][4], fal[4][4], fbh[4][2], fbl[4][2];
            int arow = wm * 64 + (lane & 15), acol = k16 + ((lane >> 4) << 3);
#pragma unroll
            for (int ma = 0; ma < 4; ++ma) {
                uint32_t off = (uint32_t)((arow + ma * 16) * GSA + acol) * 2;
                ldm_x4(fah[ma], aH + off);
                ldm_x4(fal[ma], aL + off);
            }
            int brow = wn * 32 + (lane & 7), bcol = k16 + (lane & 8);
#pragma unroll
            for (int na = 0; na < 4; ++na) {
                uint32_t off = (uint32_t)((brow + na * 8) * GSA + bcol) * 2;
                ldm_x2(fbh[na], bH + off);
                ldm_x2(fbl[na], bL + off);
            }
#pragma unroll
            for (int ma = 0; ma < 4; ++ma)
#pragma unroll
                for (int na = 0; na < 4; ++na) {
                    MMA(acc[ma][na], fah[ma], fbh[na]);
                    MMA(acc[ma][na], fah[ma], fbl[na]);
                    MMA(acc[ma][na], fal[ma], fbh[na]);
                }
        }
        __syncthreads();
    }
    float* P = g_part + (((size_t)ks * NB + b) * 2 + mode) * (NC * NC);
#pragma unroll
    for (int ma = 0; ma < 4; ++ma)
#pragma unroll
        for (int na = 0; na < 4; ++na) {
            int r = i0 + wm * 64 + ma * 16 + (lane >> 2);
            int c = j0 + wn * 32 + na * 8 + (lane & 3) * 2;
            float2 v0 = make_float2(acc[ma][na][0], acc[ma][na][1]);
            float2 v1 = make_float2(acc[ma][na][2], acc[ma][na][3]);
            *(float2*)&P[(size_t)r * NC + c] = v0;
            *(float2*)&P[(size_t)(r + 8) * NC + c] = v1;
        }
}

__global__ __launch_bounds__(256) void k_gred() {
    int gid = blockIdx.x * 256 + threadIdx.x;
    if (gid >= NB * 2 * NC * NC) return;
    int e = gid % (NC * NC);
    int bm = gid / (NC * NC);
    int m = bm & 1, b = bm >> 1;
    int r = e / NC, c = e % NC;
    int esrc = (r >= 128 && c < 128) ? (c * NC + r) : e;
    float s = 0.f;
    for (int ks = 0; ks < KSPLIT; ++ks)
        s += g_part[(((size_t)ks * NB + b) * 2 + m) * (NC * NC) + esrc];
    (m == 0 ? g_C0 : g_Cf)[b * (NC * NC) + e] = s;
}

// ------------------------- 1x1 conv via mma.sync -----------------------------
#define CSA 40
#define CATILE (128 * CSA)
#define CBT 5120
#define CSB0 136
#define CBUFE (2 * CATILE + 2 * CBT)
#define CSMEM (2 * CBUFE * 2)
__global__ __launch_bounds__(256, 1) void k_conv_mma(int widx,
                                                     const float* __restrict__ bias,
                                                     float* __restrict__ Oout,
                                                     int mode) {
    extern __shared__ __align__(16) __nv_bfloat16 smc[];
    int tid = threadIdx.x, wid = tid >> 5, lane = tid & 31;
    int t0 = blockIdx.x * 128, o0 = blockIdx.y * 128, b = blockIdx.z;
    const unsigned short* Wh = g_wh + (size_t)widx * NC * NC;
    const unsigned short* Wl = g_wl + (size_t)widx * NC * NC;
    const unsigned short* Bxh = g_xh + (size_t)b * NC * NPIX;
    const unsigned short* Bxl = g_xl + (size_t)b * NC * NPIX;
    const uint32_t* Ybuf = g_y2 + (size_t)b * NPIX * NC;
    int wm = wid >> 2, wn = wid & 3;
    float acc[4][4][4] = {};
    uint2 pAh[4], pAl[4], pBh[4], pBl[4];
    uint32_t pY[16];

    auto LD = [&](int ch) {
        int k0 = ch * 32;
#pragma unroll
        for (int q = 0; q < 4; ++q) {
            int f = tid + q * 256, r = f >> 3, c = (f & 7) * 4;
            size_t off = (size_t)(o0 + r) * NC + k0 + c;
            pAh[q] = *(const uint2*)(Wh + off);
            pAl[q] = *(const uint2*)(Wl + off);
        }
        if (mode == 0) {
#pragma unroll
            for (int q = 0; q < 4; ++q) {
                int f = tid + q * 256, k = f >> 5, t = (f & 31) * 4;
                size_t off = (size_t)(k0 + k) * NPIX + t0 + t;
                pBh[q] = *(const uint2*)(Bxh + off);
                pBl[q] = *(const uint2*)(Bxl + off);
            }
        } else {
#pragma unroll
            for (int q = 0; q < 16; ++q) {
                int f = tid + q * 256, t = f >> 5, k = f & 31;
                pY[q] = Ybuf[(size_t)(t0 + t) * NC + k0 + k];
            }
        }
    };
    auto ST = [&](int buf) {
        __nv_bfloat16* Ah = smc + buf * CBUFE;
        __nv_bfloat16* Al = Ah + CATILE;
        unsigned short* Bh = (unsigned short*)(Ah + 2 * CATILE);
        unsigned short* Bl = Bh + CBT;
#pragma unroll
        for (int q = 0; q < 4; ++q) {
            int f = tid + q * 256, r = f >> 3, c = (f & 7) * 4;
            *(uint2*)(Ah + r * CSA + c) = pAh[q];
            *(uint2*)(Al + r * CSA + c) = pAl[q];
        }
        if (mode == 0) {
#pragma unroll
            for (int q = 0; q < 4; ++q) {
                int f = tid + q * 256, k = f >> 5, t = (f & 31) * 4;
                *(uint2*)(Bh + k * CSB0 + t) = pBh[q];
                *(uint2*)(Bl + k * CSB0 + t) = pBl[q];
            }
        } else {
#pragma unroll
            for (int q = 0; q < 16; ++q) {
                int f = tid + q * 256, t = f >> 5, k = f & 31;
                uint32_t v = pY[q];
                Bh[t * 40 + k] = (unsigned short)(v & 0xFFFF);
                Bl[t * 40 + k] = (unsigned short)(v >> 16);
            }
        }
    };

    LD(0);
    for (int ch = 0; ch < 8; ++ch) {
        int buf = ch & 1;
        ST(buf);
        __syncthreads();
        if (ch < 7) LD(ch + 1);
        uint32_t sb = smem_u32(smc + buf * CBUFE);
        uint32_t aH = sb, aL = sb + CATILE * 2, bH = sb + 4 * CATILE, bL = bH + CBT * 2;
#pragma unroll
        for (int k16 = 0; k16 < 32; k16 += 16) {
            uint32_t fah[4][4], fal[4][4], fbh[4][2], fbl[4][2];
            int arow = wm * 64 + (lane & 15), acol = k16 + ((lane >> 4) << 3);
#pragma unroll
            for (int ma = 0; ma < 4; ++ma) {
                uint32_t off = (uint32_t)((arow + ma * 16) * CSA + acol) * 2;
                ldm_x4(fah[ma], aH + off);
                ldm_x4(fal[ma], aL + off);
            }
            if (mode == 0) {
                int krow = k16 + (lane & 15);
#pragma unroll
                for (int na = 0; na < 4; ++na) {
                    uint32_t off = (uint32_t)(krow * CSB0 + wn * 32 + na * 8) * 2;
                    ldm_x2t(fbh[na], bH + off);
                    ldm_x2t(fbl[na], bL + off);
                }
            } else {
                int brow = wn * 32 + (lane & 7), bcol = k16 + (lane & 8);
#pragma unroll
                for (int na = 0; na < 4; ++na) {
                    uint32_t off = (uint32_t)((brow + na * 8) * 40 + bcol) * 2;
                    ldm_x2(fbh[na], bH + off);
                    ldm_x2(fbl[na], bL + off);
                }
            }
#pragma unroll
            for (int ma = 0; ma < 4; ++ma)
#pragma unroll
                for (int na = 0; na < 4; ++na) {
                    MMA(acc[ma][na], fah[ma], fbh[na]);
                    MMA(acc[ma][na], fah[ma], fbl[na]);
                    MMA(acc[ma][na], fal[ma], fbh[na]);
                }
        }
        __syncthreads();
    }
#pragma unroll
    for (int ma = 0; ma < 4; ++ma) {
        int r = o0 + wm * 64 + ma * 16 + (lane >> 2);
        float b0v = bias[r], b1v = bias[r + 8];
#pragma unroll
        for (int na = 0; na < 4; ++na) {
            int c = t0 + wn * 32 + na * 8 + (lane & 3) * 2;
            if (mode == 0) {
                uint32_t h0, l0, h1, l1;
                pack2(acc[ma][na][0] + b0v, acc[ma][na][1] + b0v, h0, l0);
                pack2(acc[ma][na][2] + b1v, acc[ma][na][3] + b1v, h1, l1);
                size_t i0v = (size_t)(b * NC + r) * NPIX + c;
                *(uint32_t*)(g_vsh + i0v) = h0;
                *(uint32_t*)(g_vsl + i0v) = l0;
                size_t i1v = i0v + (size_t)8 * NPIX;
                *(uint32_t*)(g_vsh + i1v) = h1;
                *(uint32_t*)(g_vsl + i1v) = l1;
            } else {
                float* O = Oout + (size_t)b * NC * NPIX;
                float2 v0 = make_float2(acc[ma][na][0] + b0v, acc[ma][na][1] + b0v);
                float2 v1 = make_float2(acc[ma][na][2] + b1v, acc[ma][na][3] + b1v);
                *(float2*)&O[(size_t)r * NPIX + c] = v0;
                *(float2*)&O[(size_t)(r + 8) * NPIX + c] = v1;
            }
        }
    }
}

// ------------------------- P matrices: A @ W^T (FFMA) ------------------------
__global__ __launch_bounds__(256) void k_mm256(const float* __restrict__ w1,
                                               const float* __restrict__ w2) {
    int tile = blockIdx.x, b = blockIdx.y, z = blockIdx.z;
    const float* A = (z == 0 ? g_Cf : g_C0) + (size_t)b * NC * NC;
    const float* W = (z == 1 ? w1 : w2);
    float* P = g_P + ((size_t)z * NB + b) * NC * NC;
    int i0 = (tile >> 2) * 64, j0 = (tile & 3) * 64;
    __shared__ float As[64][33], Bs[64][33];
    float acc[4][4] = {};
    int ty = threadIdx.x >> 4, tx = threadIdx.x & 15;
    for (int kb = 0; kb < NC; kb += 32) {
        for (int idx = threadIdx.x; idx < 64 * 32; idx += 256) {
            int r = idx >> 5, c = idx & 31;
            As[r][c] = A[(i0 + r) * NC + kb + c];
            Bs[r][c] = W[(j0 + r) * NC + kb + c];
        }
        __syncthreads();
#pragma unroll
        for (int kk = 0; kk < 32; ++kk) {
            float a[4], bv[4];
#pragma unroll
            for (int ii = 0; ii < 4; ++ii) a[ii] = As[ty + 16 * ii][kk];
#pragma unroll
            for (int jj = 0; jj < 4; ++jj) bv[jj] = Bs[tx + 16 * jj][kk];
#pragma unroll
            for (int ii = 0; ii < 4; ++ii)
#pragma unroll
                for (int jj = 0; jj < 4; ++jj) acc[ii][jj] += a[ii] * bv[jj];
        }
        __syncthreads();
    }
    for (int ii = 0; ii < 4; ++ii)
        for (int jj = 0; jj < 4; ++jj)
            P[(i0 + ty + 16 * ii) * NC + j0 + tx + 16 * jj] = acc[ii][jj];
}

// ------------------------- attn -> softmax -> ifft_c -------------------------
__global__ __launch_bounds__(256) void k_attn(const float* __restrict__ w1,
                                              const float* __restrict__ w2,
                                              const float* __restrict__ b1,
                                              const float* __restrict__ b2,
                                              const float* __restrict__ temp) {
    int b = blockIdx.x >> 3, h = blockIdx.x & 7;
    int tid = threadIdx.x;
    __shared__ float Ps[NC][33];
    __shared__ float numS[CH][33];
    __shared__ float redA[CH][8], redB[CH][8];
    __shared__ float qn[CH], kn[CH], w1s[CH], w2s[CH];
    const float* P1 = g_P + ((size_t)0 * NB + b) * NC * NC;
    const float* P2 = g_P + ((size_t)1 * NB + b) * NC * NC;
    const float* P3 = g_P + ((size_t)2 * NB + b) * NC * NC;
    const float* Sb = g_S + b * NC;

    for (int idx = tid; idx < NC * CH; idx += 256)
        Ps[idx >> 5][idx & 31] = P1[(size_t)(idx >> 5) * NC + h * CH + (idx & 31)];
    __syncthreads();
    {
        int c = tid >> 3, dg = tid & 7;
        float acc[4] = {0.f, 0.f, 0.f, 0.f};
        const float* wrow = w1 + (size_t)(h * CH + c) * NC;
        for (int j = 0; j < NC; ++j) {
            float w = wrow[j];
#pragma unroll
            for (int q = 0; q < 4; ++q) acc[q] += w * Ps[j][dg + 8 * q];
        }
#pragma unroll
        for (int q = 0; q < 4; ++q) numS[c][dg + 8 * q] = acc[q];
    }
    __syncthreads();

    for (int idx = tid; idx < NC * CH; idx += 256)
        Ps[idx >> 5][idx & 31] = P2[(size_t)(idx >> 5) * NC + h * CH + (idx & 31)];
    __syncthreads();
    {
        int c = tid >> 3, g = tid & 7;
        const float* wrow = w1 + (size_t)(h * CH + c) * NC;
        float pa = 0.f, pb = 0.f;
        for (int j = g * 32; j < g * 32 + 32; ++j) {
            float w = wrow[j];
            pa += w * Ps[j][c];
            pb += w * Sb[j];
        }
        redA[c][g] = pa; redB[c][g] = pb;
    }
    __syncthreads();
    if (tid < CH) {
        float a = 0.f, bb = 0.f;
        for (int g = 0; g < 8; ++g) { a += redA[tid][g]; bb += redB[tid][g]; }
        float b1c = b1[h * CH + tid];
        w1s[tid] = bb;
        qn[tid] = fmaxf(sqrtf(fmaxf(a + 2.f * b1c * bb + 16384.f * b1c * b1c, 0.f)), 1e-12f);
    }
    __syncthreads();

    for (int idx = tid; idx < NC * CH; idx += 256)
        Ps[idx >> 5][idx & 31] = P3[(size_t)(idx >> 5) * NC + h * CH + (idx & 31)];
    __syncthreads();
    {
        int c = tid >> 3, g = tid & 7;
        const float* wrow = w2 + (size_t)(h * CH + c) * NC;
        float pa = 0.f, pb = 0.f;
        for (int j = g * 32; j < g * 32 + 32; ++j) {
            float w = wrow[j];
            pa += w * Ps[j][c];
            pb += w * Sb[j];
        }
        redA[c][g] = pa; redB[c][g] = pb;
    }
    __syncthreads();
    if (tid < CH) {
        float a = 0.f, bb = 0.f;
        for (int g = 0; g < 8; ++g) { a += redA[tid][g]; bb += redB[tid][g]; }
        float b2d = b2[h * CH + tid];
        w2s[tid] = bb;
        kn[tid] = fmaxf(sqrtf(fmaxf(a + 2.f * b2d * bb + 16384.f * b2d * b2d, 0.f)), 1e-12f);
    }
    __syncthreads();

    {
        float tH = temp[h];
        for (int idx = tid; idx < CH * CH; idx += 256) {
            int c = idx >> 5, d = idx & 31;
            float b1c = b1[h * CH + c], b2d = b2[h * CH + d];
            float numF = numS[c][d] + b1c * w2s[d] + b2d * w1s[c] + 16384.f * b1c * b2d;
            numS[c][d] = tH * numF / (qn[c] * kn[d]);
        }
    }
    __syncthreads();

    if (tid < CH) {
        float mx = -1e30f;
        for (int d = 0; d < CH; ++d) mx = fmaxf(mx, numS[tid][d]);
        float s = 0.f;
        for (int d = 0; d < CH; ++d) { float e = expf(numS[tid][d] - mx); numS[tid][d] = e; s += e; }
        float inv = 1.f / s;
        for (int d = 0; d < CH; ++d) numS[tid][d] *= inv;
    }
    __syncthreads();

    for (int idx = tid; idx < CH * CH; idx += 256) {
        int cp = idx >> 5, d = idx & 31;
        float re = 0.f, im = 0.f;
        for (int c = 0; c < CH; ++c) {
            int ph = (c * cp) & 31;
            float sv, cv;
            sincosf(0.19634954084936207f * (float)ph, &sv, &cv);
            float a = numS[c][d];
            re += a * cv; im += a * sv;
        }
        re *= 0.03125f; im *= 0.03125f;
        if (cp == 0) im += 0.03125f;
        g_At[((size_t)blockIdx.x * CH + cp) * CH + d] = make_float2(re, im);
    }
}

// ------------------------- Dirichlet table + bf16 expansion ------------------
__global__ __launch_bounds__(256) void k_dtab() {
    int i = blockIdx.x * 256 + threadIdx.x;
    if (i >= 128 * 255) return;
    int s = i / 255, mi = i % 255, m = mi - 127;
    float2 v;
    if (s == 0) {
        v = make_float2(m == 0 ? 1.f : 0.f, 0.f);
    } else {
        double f = (double)s / 128.0;
        double al = (double)m + f;
        double mag = sinpi(f) / (128.0 * sinpi(al / 128.0));
        if (m & 1) mag = -mag;
        double ph = al * (127.0 / 128.0);
        v = make_float2((float)(cospi(ph) * mag), (float)(sinpi(ph) * mag));
    }
    g_Dtab[s * 256 + mi] = v;
}
__global__ __launch_bounds__(256) void k_dexp() {
    int gid = blockIdx.x * 256 + threadIdx.x;
    int x = gid & 127, p = (gid >> 7) & 127, s = gid >> 14;
    float2 v = g_Dtab[s * 256 + (p - x + 127)];
    __nv_bfloat16 hr = __float2bfloat16_rn(v.x);
    __nv_bfloat16 hi = __float2bfloat16_rn(v.y);
    g_DreH[gid] = __bfloat16_as_ushort(hr);
    g_DreL[gid] = __bfloat16_as_ushort(__float2bfloat16_rn(v.x - __bfloat162float(hr)));
    g_DimH[gid] = __bfloat16_as_ushort(hi);
    g_DimL[gid] = __bfloat16_as_ushort(__float2bfloat16_rn(v.y - __bfloat162float(hi)));
}

// ------------------------- fused Dirichlet transform + channel attn ----------
#define FSA 40
#define FGEMM 51200
#define FEPI (66560 + 2 * 2112 * 4)
#define FSMEM (FEPI > FGEMM ? FEPI : FGEMM)
__global__ __launch_bounds__(256, 1) void k_fft_fused() {
    extern __shared__ __align__(16) char smf[];
    __nv_bfloat16* smb = (__nv_bfloat16*)smf;
    int tid = threadIdx.x, wid = tid >> 5, lane = tid & 31;
    int s = blockIdx.x;
    int b = blockIdx.y >> 2, dblk = blockIdx.y & 3;
    int d0 = dblk * 64;
    int wm = wid >> 1, wn = wid & 1;
    float accRe[2][4][4] = {}, accIm[2][4][4] = {};
    const uint32_t sb = smem_u32(smf);
    const uint32_t oReH = 0, oReL = 5120, oImH = 10240, oImL = 15360, oBH = 20480, oBL = 23040;

    for (int kc = 0; kc < 128; kc += 32) {
        __syncthreads();
#pragma unroll
        for (int q = 0; q < 4; ++q) {
            int f = tid + q * 256, r = f >> 3, c = (f & 7) * 4;
            size_t so = (size_t)s * 16384 + r * 128 + kc + c;
            uint32_t dofs = r * FSA + c;
            *(uint2*)(smb + oReH + dofs) = *(const uint2*)(g_DreH + so);
            *(uint2*)(smb + oReL + dofs) = *(const uint2*)(g_DreL + so);
            *(uint2*)(smb + oImH + dofs) = *(const uint2*)(g_DimH + so);
            *(uint2*)(smb + oImL + dofs) = *(const uint2*)(g_DimL + so);
        }
#pragma unroll
        for (int q = 0; q < 2; ++q) {
            int f = tid + q * 256, r = f >> 3, c = (f & 7) * 4;
            size_t so = (size_t)(b * NC + d0 + r) * NPIX + s * 128 + kc + c;
            uint32_t dofs = r * FSA + c;
            *(uint2*)(smb + oBH + dofs) = *(const uint2*)(g_vsh + so);
            *(uint2*)(smb + oBL + dofs) = *(const uint2*)(g_vsl + so);
        }
        __syncthreads();
#pragma unroll
        for (int k16 = 0; k16 < 32; k16 += 16) {
            uint32_t fbh[4][2], fbl[4][2];
            int brow = wn * 32 + (lane & 7), bcol = k16 + (lane & 8);
#pragma unroll
            for (int na = 0; na < 4; ++na) {
                uint32_t off = (uint32_t)((brow + na * 8) * FSA + bcol) * 2;
                ldm_x2(fbh[na], sb + oBH * 2 + off);
                ldm_x2(fbl[na], sb + oBL * 2 + off);
            }
            int arow = wm * 32 + (lane & 15), acol = k16 + ((lane >> 4) << 3);
            {
                uint32_t fh[2][4], fl[2][4];
#pragma unroll
                for (int ma = 0; ma < 2; ++ma) {
                    uint32_t off = (uint32_t)((arow + ma * 16) * FSA + acol) * 2;
                    ldm_x4(fh[ma], sb + oReH * 2 + off);
                    ldm_x4(fl[ma], sb + oReL * 2 + off);
                }
#pragma unroll
                for (int ma = 0; ma < 2; ++ma)
#pragma unroll
                    for (int na = 0; na < 4; ++na) {
                        MMA(accRe[ma][na], fh[ma], fbh[na]);
                        MMA(accRe[ma][na], fh[ma], fbl[na]);
                        MMA(accRe[ma][na], fl[ma], fbh[na]);
                    }
            }
            {
                uint32_t fh[2][4], fl[2][4];
#pragma unroll
                for (int ma = 0; ma < 2; ++ma) {
                    uint32_t off = (uint32_t)((arow + ma * 16) * FSA + acol) * 2;
                    ldm_x4(fh[ma], sb + oImH * 2 + off);
                    ldm_x4(fl[ma], sb + oImL * 2 + off);
                }
#pragma unroll
                for (int ma = 0; ma < 2; ++ma)
#pragma unroll
                    for (int na = 0; na < 4; ++na) {
                        MMA(accIm[ma][na], fh[ma], fbh[na]);
                        MMA(accIm[ma][na], fh[ma], fbl[na]);
                        MMA(accIm[ma][na], fl[ma], fbh[na]);
                    }
            }
        }
    }
    __syncthreads();
    float2* VtS = (float2*)smf;
    float* Are = (float*)(smf + 66560);
    float* Aim = Are + 2112;
#pragma unroll
    for (int ma = 0; ma < 2; ++ma)
#pragma unroll
        for (int na = 0; na < 4; ++na) {
            int p = wm * 32 + ma * 16 + (lane >> 2);
            int d = wn * 32 + na * 8 + (lane & 3) * 2;
            VtS[p * 65 + d]     = make_float2(accRe[ma][na][0], accIm[ma][na][0]);
            VtS[p * 65 + d + 1] = make_float2(accRe[ma][na][1], accIm[ma][na][1]);
            VtS[(p + 8) * 65 + d]     = make_float2(accRe[ma][na][2], accIm[ma][na][2]);
            VtS[(p + 8) * 65 + d + 1] = make_float2(accRe[ma][na][3], accIm[ma][na][3]);
        }
    int h0 = dblk * 2;
    for (int idx = tid; idx < 2048; idx += 256) {
        int hh = idx >> 10, rest = idx & 1023, c = rest >> 5, d = rest & 31;
        float2 a = g_At[(size_t)(b * NHEADS + h0 + hh) * 1024 + c * 32 + d];
        Are[(hh * 32 + c) * 33 + d] = a.x;
        Aim[(hh * 32 + c) * 33 + d] = a.y;
    }
    __syncthreads();
    int pg = tid >> 5, cg = tid & 31;
    int head = cg >> 4, cl0 = (2 * cg) & 31;
    const float* ArH = Are + head * 1056;
    const float* AiH = Aim + head * 1056;
    float accr[2][16] = {}, acci[2][16] = {};
    for (int d = 0; d < 32; ++d) {
        float a0r = ArH[cl0 * 33 + d],       a0i = AiH[cl0 * 33 + d];
        float a1r = ArH[(cl0 + 1) * 33 + d], a1i = AiH[(cl0 + 1) * 33 + d];
        int dv = head * 32 + d;
#pragma unroll
        for (int i = 0; i < 16; ++i) {
            float2 v = VtS[(pg * 16 + i) * 65 + dv];
            accr[0][i] += a0r * v.x - a0i * v.y;
            acci[0][i] += a0r * v.y + a0i * v.x;
            accr[1][i] += a1r * v.x - a1i * v.y;
            acci[1][i] += a1r * v.y + a1i * v.x;
        }
    }
    uint32_t* Y = g_y2 + (size_t)b * NPIX * NC;
#pragma unroll
    for (int i = 0; i < 16; ++i) {
        int p = pg * 16 + i;
        int t = (p << 7) + s;
        float y0 = sqrtf(accr[0][i] * accr[0][i] + acci[0][i] * acci[0][i]);
        float y1 = sqrtf(accr[1][i] * accr[1][i] + acci[1][i] * acci[1][i]);
        uint2 w;
        w.x = pack_hl(y0);
        w.y = pack_hl(y1);
        *(uint2*)&Y[(size_t)t * NC + d0 + 2 * cg] = w;
    }
}

// ------------------------- launch --------------------------------------------
extern "C" void kernel_launch(void* const* d_in, const int* in_sizes, int n_in,
                              void* d_out, int out_size) {
    const float* x  = (const float*)d_in[0];
    const float* w1 = (const float*)d_in[1];
    const float* b1 = (const float*)d_in[2];
    const float* w2 = (const float*)d_in[3];
    const float* b2 = (const float*)d_in[4];
    const float* w3 = (const float*)d_in[5];
    const float* b3 = (const float*)d_in[6];
    const float* wo = (const float*)d_in[7];
    const float* bo = (const float*)d_in[8];
    const float* temp = (const float*)d_in[9];
    float* out = (float*)d_out;

    // One-time resources (exist before harness pre-capture baseline; nothing
    // allocated/freed during capture/replay/teardown).
    static cudaStream_t s1 = nullptr, s2 = nullptr;
    static cudaEvent_t evR = nullptr, evS = nullptr, evG = nullptr, evD = nullptr;
    if (s1 == nullptr) {
        cudaStreamCreateWithFlags(&s1, cudaStreamNonBlocking);
        cudaStreamCreateWithFlags(&s2, cudaStreamNonBlocking);
        cudaEventCreateWithFlags(&evR, cudaEventDisableTiming);
        cudaEventCreateWithFlags(&evS, cudaEventDisableTiming);
        cudaEventCreateWithFlags(&evG, cudaEventDisableTiming);
        cudaEventCreateWithFlags(&evD, cudaEventDisableTiming);
        cudaFuncSetAttribute(k_gram_mma, cudaFuncAttributeMaxDynamicSharedMemorySize, GSMEM);
        cudaFuncSetAttribute(k_conv_mma, cudaFuncAttributeMaxDynamicSharedMemorySize, CSMEM);
        cudaFuncSetAttribute(k_fft_fused, cudaFuncAttributeMaxDynamicSharedMemorySize, FSMEM);
    }

    // branch s2: Dirichlet tables (independent until k_fft_fused)
    cudaEventRecord(evR, 0);
    cudaStreamWaitEvent(s2, evR, 0);
    k_dtab<<<128, 256, 0, s2>>>();
    k_dexp<<<8192, 256, 0, s2>>>();
    cudaEventRecord(evD, s2);

    // main: x split (+flip +sums) — the sole serial prefix
    k_sumsplit<<<NB * NC, 256>>>(x);
    cudaEventRecord(evS, 0);

    // branch s1: gram chain (concurrent with wsplit+conv0 on main)
    cudaStreamWaitEvent(s1, evS, 0);
    k_gram_mma<<<dim3(3, NB, KSPLIT * 2), 256, GSMEM, s1>>>();
    k_gred<<<(NB * 2 * NC * NC) / 256, 256, 0, s1>>>();
    k_mm256<<<dim3(16, NB, 3), 256, 0, s1>>>(w1, w2);
    k_attn<<<NB * NHEADS, 256, 0, s1>>>(w1, w2, b1, b2, temp);
    cudaEventRecord(evG, s1);

    // main: weight split (only conv needs it) then conv0
    k_wsplit<<<2 * NC * NC / 4 / 256, 256>>>(w3, wo);
    k_conv_mma<<<dim3(128, 2, NB), 256, CSMEM>>>(0, b3, nullptr, 0);

    // join: fft needs conv0 (main), attn (s1), dexp (s2)
    cudaStreamWaitEvent(0, evG, 0);
    cudaStreamWaitEvent(0, evD, 0);
    k_fft_fused<<<dim3(128, 16), 256, FSMEM>>>();
    k_conv_mma<<<dim3(128, 2, NB), 256, CSMEM>>>(1, bo, out, 1);
}